// round 1
// baseline (speedup 1.0000x reference)
#include <cuda_runtime.h>
#include <math.h>
#include <stdint.h>

// Problem constants
#define Bn  2
#define Sn  4096
#define En  512
#define Hn  8
#define Dn  64
#define E3  1536
#define Mrows (Bn * Sn)   // 8192

// Scratch (static device globals -- no allocation at runtime)
__device__ float g_qkv[(size_t)Mrows * E3];   // [B*S, 3E]  (q | k | v per row)
__device__ float g_att[(size_t)Mrows * En];   // [B*S, E]   attention output (b,s,h,d)

// ---------------------------------------------------------------------------
// SGEMM: C[M,N] = A[M,K] @ Bw[N,K]^T + bias[N]
// 128x128 block tile, BK=16, 256 threads, 8x8 micro-tile. All dims divide.
// ---------------------------------------------------------------------------
__device__ __forceinline__ void sgemm_body(
    const float* __restrict__ A, const float* __restrict__ Bw,
    const float* __restrict__ bias, float* __restrict__ C,
    int M, int N, int K)
{
    constexpr int BM = 128, BN = 128, BK = 16;
    constexpr int PITCH = BM + 4;   // padded to reduce STS conflicts
    __shared__ float As[BK * PITCH];
    __shared__ float Ws[BK * PITCH];

    const int tid  = threadIdx.x;
    const int tcol = tid & 15;      // 0..15 -> n micro
    const int trow = tid >> 4;      // 0..15 -> m micro
    const int mBase = blockIdx.y * BM;
    const int nBase = blockIdx.x * BN;

    float acc[8][8];
#pragma unroll
    for (int i = 0; i < 8; i++)
#pragma unroll
        for (int j = 0; j < 8; j++) acc[i][j] = 0.0f;

    for (int kt = 0; kt < K; kt += BK) {
        // Load A tile (128 x 16) and B tile (128 x 16), transposed into smem.
#pragma unroll
        for (int it = 0; it < 2; it++) {
            int idx = tid + it * 256;          // 0..511
            int r   = idx >> 2;                // 0..127
            int c4  = (idx & 3) << 2;          // 0,4,8,12
            float4 av = *reinterpret_cast<const float4*>(
                A + (size_t)(mBase + r) * K + kt + c4);
            As[(c4 + 0) * PITCH + r] = av.x;
            As[(c4 + 1) * PITCH + r] = av.y;
            As[(c4 + 2) * PITCH + r] = av.z;
            As[(c4 + 3) * PITCH + r] = av.w;
            float4 bv = *reinterpret_cast<const float4*>(
                Bw + (size_t)(nBase + r) * K + kt + c4);
            Ws[(c4 + 0) * PITCH + r] = bv.x;
            Ws[(c4 + 1) * PITCH + r] = bv.y;
            Ws[(c4 + 2) * PITCH + r] = bv.z;
            Ws[(c4 + 3) * PITCH + r] = bv.w;
        }
        __syncthreads();

#pragma unroll
        for (int kk = 0; kk < BK; kk++) {
            float ar[8], br[8];
            *reinterpret_cast<float4*>(ar)     = *reinterpret_cast<const float4*>(As + kk * PITCH + trow * 8);
            *reinterpret_cast<float4*>(ar + 4) = *reinterpret_cast<const float4*>(As + kk * PITCH + trow * 8 + 4);
            *reinterpret_cast<float4*>(br)     = *reinterpret_cast<const float4*>(Ws + kk * PITCH + tcol * 8);
            *reinterpret_cast<float4*>(br + 4) = *reinterpret_cast<const float4*>(Ws + kk * PITCH + tcol * 8 + 4);
#pragma unroll
            for (int i = 0; i < 8; i++)
#pragma unroll
                for (int j = 0; j < 8; j++)
                    acc[i][j] = fmaf(ar[i], br[j], acc[i][j]);
        }
        __syncthreads();
    }

    // Epilogue: add bias, vectorized store.
#pragma unroll
    for (int i = 0; i < 8; i++) {
        int m = mBase + trow * 8 + i;
#pragma unroll
        for (int j4 = 0; j4 < 8; j4 += 4) {
            int n = nBase + tcol * 8 + j4;
            float4 bv = *reinterpret_cast<const float4*>(bias + n);
            float4 cv;
            cv.x = acc[i][j4 + 0] + bv.x;
            cv.y = acc[i][j4 + 1] + bv.y;
            cv.z = acc[i][j4 + 2] + bv.z;
            cv.w = acc[i][j4 + 3] + bv.w;
            *reinterpret_cast<float4*>(C + (size_t)m * N + n) = cv;
        }
    }
}

__global__ void __launch_bounds__(256)
gemm_qkv_kernel(const float* __restrict__ x,
                const float* __restrict__ w1,
                const float* __restrict__ b1)
{
    sgemm_body(x, w1, b1, g_qkv, Mrows, E3, En);
}

__global__ void __launch_bounds__(256)
gemm_out_kernel(const float* __restrict__ w2,
                const float* __restrict__ b2,
                float* __restrict__ out)
{
    sgemm_body(g_att, w2, b2, out, Mrows, En, En);
}

// ---------------------------------------------------------------------------
// Fused attention with Gaussian relative-position bias (flash-style).
// Grid: (S/64, H, B). Block: 256 threads (16x16, 4x4 micro over 64x64 tiles).
// Smem (dynamic): Qs[d][r], Ks[d][c], Vs[c][d], Ps[c][r], all pitch 68.
// ---------------------------------------------------------------------------
#define AP 68   // smem pitch (floats); 68*4B keeps float4 alignment

__global__ void __launch_bounds__(256)
attn_kernel(const float* __restrict__ t)
{
    extern __shared__ float sm[];
    float* Qs = sm;                 // [64][AP]  layout [d][r], pre-scaled by 1/8
    float* Ks = Qs + 64 * AP;       // [64][AP]  layout [d][c]
    float* Vs = Ks + 64 * AP;       // [64][AP]  layout [c][d]
    float* Ps = Vs + 64 * AP;       // [64][AP]  layout [c][r]

    const int qb = blockIdx.x;      // q tile index (0..63)
    const int h  = blockIdx.y;      // head
    const int b  = blockIdx.z;      // batch
    const int tid  = threadIdx.x;
    const int tcol = tid & 15;      // key/out-col micro index
    const int trow = tid >> 4;      // query-row micro index
    const int q0 = qb * 64;

    const float tt   = t[h];
    const float sig  = tt * tt;               // sigma = t^2
    const float inv2s4 = 1.0f / (2.0f * sig * sig);  // 1 / (2 sigma^2)

    // Load Q tile transposed into Qs[d][r], scaled by 1/sqrt(D)=0.125.
    for (int i = tid; i < 64 * 16; i += 256) {
        int r  = i >> 4;
        int d4 = (i & 15) << 2;
        const float4 v = *reinterpret_cast<const float4*>(
            g_qkv + (size_t)(b * Sn + q0 + r) * E3 + h * Dn + d4);
        Qs[(d4 + 0) * AP + r] = v.x * 0.125f;
        Qs[(d4 + 1) * AP + r] = v.y * 0.125f;
        Qs[(d4 + 2) * AP + r] = v.z * 0.125f;
        Qs[(d4 + 3) * AP + r] = v.w * 0.125f;
    }

    float o[4][4];
    float m_i[4], l_i[4];
#pragma unroll
    for (int i = 0; i < 4; i++) {
        m_i[i] = -INFINITY;
        l_i[i] = 0.0f;
#pragma unroll
        for (int j = 0; j < 4; j++) o[i][j] = 0.0f;
    }

    for (int kb = 0; kb < Sn / 64; kb++) {
        const int k0 = kb * 64;
        // Load K (transposed) and V (natural) tiles.
        for (int i = tid; i < 64 * 16; i += 256) {
            int r  = i >> 4;
            int d4 = (i & 15) << 2;
            size_t base = (size_t)(b * Sn + k0 + r) * E3 + h * Dn + d4;
            float4 kv = *reinterpret_cast<const float4*>(g_qkv + En + base);
            Ks[(d4 + 0) * AP + r] = kv.x;
            Ks[(d4 + 1) * AP + r] = kv.y;
            Ks[(d4 + 2) * AP + r] = kv.z;
            Ks[(d4 + 3) * AP + r] = kv.w;
            float4 vv = *reinterpret_cast<const float4*>(g_qkv + 2 * En + base);
            *reinterpret_cast<float4*>(Vs + r * AP + d4) = vv;
        }
        __syncthreads();

        // S tile = Q @ K^T (scaled) ; per-thread 4x4 fragment.
        float s[4][4];
#pragma unroll
        for (int i = 0; i < 4; i++)
#pragma unroll
            for (int j = 0; j < 4; j++) s[i][j] = 0.0f;

#pragma unroll 8
        for (int d = 0; d < 64; d++) {
            float4 qf = *reinterpret_cast<const float4*>(Qs + d * AP + trow * 4);
            float4 kf = *reinterpret_cast<const float4*>(Ks + d * AP + tcol * 4);
            float qa[4] = {qf.x, qf.y, qf.z, qf.w};
            float ka[4] = {kf.x, kf.y, kf.z, kf.w};
#pragma unroll
            for (int i = 0; i < 4; i++)
#pragma unroll
                for (int j = 0; j < 4; j++)
                    s[i][j] = fmaf(qa[i], ka[j], s[i][j]);
        }

        // Gaussian bias + row max (partial over this thread's 4 cols)
        float rmax[4];
#pragma unroll
        for (int i = 0; i < 4; i++) {
            int q = q0 + trow * 4 + i;
            rmax[i] = -INFINITY;
#pragma unroll
            for (int j = 0; j < 4; j++) {
                float dqk = (float)(q - (k0 + tcol * 4 + j));
                s[i][j] -= dqk * dqk * inv2s4;
                rmax[i] = fmaxf(rmax[i], s[i][j]);
            }
        }
        // Reduce max across the 16 tcol lanes (xor stays within half-warp).
#pragma unroll
        for (int off = 8; off; off >>= 1)
#pragma unroll
            for (int i = 0; i < 4; i++)
                rmax[i] = fmaxf(rmax[i], __shfl_xor_sync(0xffffffffu, rmax[i], off));

        float rsum[4];
#pragma unroll
        for (int i = 0; i < 4; i++) {
            float mnew = fmaxf(m_i[i], rmax[i]);
            float corr = __expf(m_i[i] - mnew);
            m_i[i] = mnew;
            float ls = 0.0f;
#pragma unroll
            for (int j = 0; j < 4; j++) {
                float p = __expf(s[i][j] - mnew);
                s[i][j] = p;
                ls += p;
            }
            rsum[i] = ls;
            l_i[i] *= corr;
#pragma unroll
            for (int j = 0; j < 4; j++) o[i][j] *= corr;
        }
#pragma unroll
        for (int off = 8; off; off >>= 1)
#pragma unroll
            for (int i = 0; i < 4; i++)
                rsum[i] += __shfl_xor_sync(0xffffffffu, rsum[i], off);
#pragma unroll
        for (int i = 0; i < 4; i++) l_i[i] += rsum[i];

        // Write P transposed: Ps[c][r]
#pragma unroll
        for (int i = 0; i < 4; i++)
#pragma unroll
            for (int j = 0; j < 4; j++)
                Ps[(tcol * 4 + j) * AP + (trow * 4 + i)] = s[i][j];
        __syncthreads();

        // O[r][d] += sum_c P[r][c] * V[c][d]
#pragma unroll 8
        for (int c = 0; c < 64; c++) {
            float4 pf = *reinterpret_cast<const float4*>(Ps + c * AP + trow * 4);
            float4 vf = *reinterpret_cast<const float4*>(Vs + c * AP + tcol * 4);
            float pa[4] = {pf.x, pf.y, pf.z, pf.w};
            float va[4] = {vf.x, vf.y, vf.z, vf.w};
#pragma unroll
            for (int i = 0; i < 4; i++)
#pragma unroll
                for (int j = 0; j < 4; j++)
                    o[i][j] = fmaf(pa[i], va[j], o[i][j]);
        }
        __syncthreads();   // protect Ks/Vs/Ps before next iteration's loads
    }

    // Epilogue: normalize and store to g_att in [b, s, h, d] (== [b,s,E]) layout.
#pragma unroll
    for (int i = 0; i < 4; i++) {
        float inv_l = 1.0f / l_i[i];
        int q = q0 + trow * 4 + i;
        float4 res;
        res.x = o[i][0] * inv_l;
        res.y = o[i][1] * inv_l;
        res.z = o[i][2] * inv_l;
        res.w = o[i][3] * inv_l;
        *reinterpret_cast<float4*>(
            g_att + (size_t)(b * Sn + q) * En + h * Dn + tcol * 4) = res;
    }
}

// ---------------------------------------------------------------------------
// Launch
// ---------------------------------------------------------------------------
extern "C" void kernel_launch(void* const* d_in, const int* in_sizes, int n_in,
                              void* d_out, int out_size)
{
    const float* x  = (const float*)d_in[0];   // [B,S,E]
    const float* w1 = (const float*)d_in[1];   // [3E,E]
    const float* b1 = (const float*)d_in[2];   // [3E]
    const float* w2 = (const float*)d_in[3];   // [E,E]
    const float* b2 = (const float*)d_in[4];   // [E]
    const float* t  = (const float*)d_in[5];   // [H]
    float* out = (float*)d_out;                // [B,S,E]

    (void)in_sizes; (void)n_in; (void)out_size;

    // QKV projection: [8192,512] @ [1536,512]^T -> g_qkv
    gemm_qkv_kernel<<<dim3(E3 / 128, Mrows / 128), 256>>>(x, w1, b1);

    // Fused attention
    const int smem = 4 * 64 * AP * (int)sizeof(float);   // 69632 B
    cudaFuncSetAttribute(attn_kernel,
                         cudaFuncAttributeMaxDynamicSharedMemorySize, smem);
    attn_kernel<<<dim3(Sn / 64, Hn, Bn), 256, smem>>>(t);

    // Output projection: [8192,512] @ [512,512]^T -> d_out
    gemm_out_kernel<<<dim3(En / 128, Mrows / 128), 256>>>(w2, b2, out);
}

// round 3
// speedup vs baseline: 1.8504x; 1.8504x over previous
#include <cuda_runtime.h>
#include <math.h>
#include <stdint.h>

// Problem constants
#define Bn  2
#define Sn  4096
#define En  512
#define Hn  8
#define Dn  64
#define E3  1536
#define Mrows (Bn * Sn)   // 8192

// Scratch (static device globals -- no allocation at runtime)
__device__ float g_qkv[(size_t)Mrows * E3];   // [B*S, 3E]  (q | k | v per row)
__device__ float g_att[(size_t)Mrows * En];   // [B*S, E]   attention output

// ===========================================================================
// Helpers
// ===========================================================================
__device__ __forceinline__ uint32_t f2tf32(float x) {
    uint32_t r;
    asm("cvt.rna.tf32.f32 %0, %1;" : "=r"(r) : "f"(x));
    return r;
}

__device__ __forceinline__ void mma_tf32(
    float& c0, float& c1, float& c2, float& c3,
    uint32_t a0, uint32_t a1, uint32_t a2, uint32_t a3,
    uint32_t b0, uint32_t b1)
{
    asm volatile(
        "mma.sync.aligned.m16n8k8.row.col.f32.tf32.tf32.f32 "
        "{%0,%1,%2,%3}, {%4,%5,%6,%7}, {%8,%9}, {%0,%1,%2,%3};"
        : "+f"(c0), "+f"(c1), "+f"(c2), "+f"(c3)
        : "r"(a0), "r"(a1), "r"(a2), "r"(a3), "r"(b0), "r"(b1));
}

// ===========================================================================
// SGEMM (fp32): C[M,N] = A[M,K] @ Bw[N,K]^T + bias[N]   (projections)
// ===========================================================================
__device__ __forceinline__ void sgemm_body(
    const float* __restrict__ A, const float* __restrict__ Bw,
    const float* __restrict__ bias, float* __restrict__ C,
    int M, int N, int K)
{
    constexpr int BM = 128, BN = 128, BK = 16;
    constexpr int PITCH = BM + 4;
    __shared__ float As[BK * PITCH];
    __shared__ float Ws[BK * PITCH];

    const int tid  = threadIdx.x;
    const int tcol = tid & 15;
    const int trow = tid >> 4;
    const int mBase = blockIdx.y * BM;
    const int nBase = blockIdx.x * BN;

    float acc[8][8];
#pragma unroll
    for (int i = 0; i < 8; i++)
#pragma unroll
        for (int j = 0; j < 8; j++) acc[i][j] = 0.0f;

    for (int kt = 0; kt < K; kt += BK) {
#pragma unroll
        for (int it = 0; it < 2; it++) {
            int idx = tid + it * 256;
            int r   = idx >> 2;
            int c4  = (idx & 3) << 2;
            float4 av = *reinterpret_cast<const float4*>(A + (size_t)(mBase + r) * K + kt + c4);
            As[(c4 + 0) * PITCH + r] = av.x;
            As[(c4 + 1) * PITCH + r] = av.y;
            As[(c4 + 2) * PITCH + r] = av.z;
            As[(c4 + 3) * PITCH + r] = av.w;
            float4 bv = *reinterpret_cast<const float4*>(Bw + (size_t)(nBase + r) * K + kt + c4);
            Ws[(c4 + 0) * PITCH + r] = bv.x;
            Ws[(c4 + 1) * PITCH + r] = bv.y;
            Ws[(c4 + 2) * PITCH + r] = bv.z;
            Ws[(c4 + 3) * PITCH + r] = bv.w;
        }
        __syncthreads();
#pragma unroll
        for (int kk = 0; kk < BK; kk++) {
            float ar[8], br[8];
            *reinterpret_cast<float4*>(ar)     = *reinterpret_cast<const float4*>(As + kk * PITCH + trow * 8);
            *reinterpret_cast<float4*>(ar + 4) = *reinterpret_cast<const float4*>(As + kk * PITCH + trow * 8 + 4);
            *reinterpret_cast<float4*>(br)     = *reinterpret_cast<const float4*>(Ws + kk * PITCH + tcol * 8);
            *reinterpret_cast<float4*>(br + 4) = *reinterpret_cast<const float4*>(Ws + kk * PITCH + tcol * 8 + 4);
#pragma unroll
            for (int i = 0; i < 8; i++)
#pragma unroll
                for (int j = 0; j < 8; j++)
                    acc[i][j] = fmaf(ar[i], br[j], acc[i][j]);
        }
        __syncthreads();
    }
#pragma unroll
    for (int i = 0; i < 8; i++) {
        int m = mBase + trow * 8 + i;
#pragma unroll
        for (int j4 = 0; j4 < 8; j4 += 4) {
            int n = nBase + tcol * 8 + j4;
            float4 bv = *reinterpret_cast<const float4*>(bias + n);
            float4 cv;
            cv.x = acc[i][j4 + 0] + bv.x;
            cv.y = acc[i][j4 + 1] + bv.y;
            cv.z = acc[i][j4 + 2] + bv.z;
            cv.w = acc[i][j4 + 3] + bv.w;
            *reinterpret_cast<float4*>(C + (size_t)m * N + n) = cv;
        }
    }
}

__global__ void __launch_bounds__(256)
gemm_qkv_kernel(const float* __restrict__ x, const float* __restrict__ w1,
                const float* __restrict__ b1)
{
    sgemm_body(x, w1, b1, g_qkv, Mrows, E3, En);
}

__global__ void __launch_bounds__(256)
gemm_out_kernel(const float* __restrict__ w2, const float* __restrict__ b2,
                float* __restrict__ out)
{
    sgemm_body(g_att, w2, b2, out, Mrows, En, En);
}

// ===========================================================================
// FlashAttention-2 with Gaussian bias, tf32 mma.sync (HMMA).
// Grid (Sn/128, Hn, Bn), 256 threads (8 warps x 16 q-rows). Bc = 64.
// Smem: K,V tiles [64][68] fp32(tf32), double-buffered = 69632 B.
// ===========================================================================
#define BR   128
#define BC   64
#define KVP  68                    // smem pitch (floats)
#define NKB  (Sn / BC)             // 64 key tiles
#define TILE_F4 (2 * BC * (Dn/4))  // 2048 float4 per (K,V) tile pair

__global__ void __launch_bounds__(256, 1)
attn_fa2_kernel(const float* __restrict__ t)
{
    extern __shared__ float sm[];
    float* Kbuf[2] = { sm,                 sm + 2 * BC * KVP };
    float* Vbuf[2] = { sm + BC * KVP,      sm + 3 * BC * KVP };

    const int tid  = threadIdx.x;
    const int lane = tid & 31;
    const int wid  = tid >> 5;
    const int qt = blockIdx.x, h = blockIdx.y, b = blockIdx.z;
    const int q0 = qt * BR;
    const int qw = q0 + wid * 16;          // this warp's first q row

    const int lr = lane >> 2;              // 0..7 row-in-tile / n-col selector
    const int lc = lane & 3;               // 0..3 k-col / paired-col selector

    const float tt = t[h];
    const float sig = tt * tt;
    const float ninv = -1.0f / (2.0f * sig * sig);   // -1/(2 sigma^2), sigma=t^2

    // ---- Q fragments (tf32, pre-scaled by 1/8), resident in registers ----
    uint32_t qa[8][4];
    {
        const float* qp = g_qkv + (size_t)(b * Sn + qw + lr) * E3 + h * Dn;
        const float* qp8 = qp + 8 * E3;
#pragma unroll
        for (int kt = 0; kt < 8; kt++) {
            qa[kt][0] = f2tf32(qp [kt * 8 + lc]     * 0.125f);
            qa[kt][1] = f2tf32(qp8[kt * 8 + lc]     * 0.125f);
            qa[kt][2] = f2tf32(qp [kt * 8 + lc + 4] * 0.125f);
            qa[kt][3] = f2tf32(qp8[kt * 8 + lc + 4] * 0.125f);
        }
    }

    float o[8][4];
#pragma unroll
    for (int nt = 0; nt < 8; nt++)
#pragma unroll
        for (int i = 0; i < 4; i++) o[nt][i] = 0.0f;
    float m0 = -INFINITY, m1 = -INFINITY;
    float l0 = 0.0f, l1 = 0.0f;

    // ---- preload tile 0 ----
    {
        const float* src0 = g_qkv + En + (size_t)(b * Sn) * E3 + h * Dn;
#pragma unroll
        for (int i = 0; i < 8; i++) {
            int f   = i * 256 + tid;
            int sel = f >> 10;
            int idx = f & 1023;
            int row = idx >> 4;
            int c4  = (idx & 15) << 2;
            float4 v = *reinterpret_cast<const float4*>(
                src0 + (size_t)sel * En + (size_t)row * E3 + c4);
            float* dst = (sel ? Vbuf[0] : Kbuf[0]) + row * KVP + c4;
            float4 w;
            w.x = __uint_as_float(f2tf32(v.x));
            w.y = __uint_as_float(f2tf32(v.y));
            w.z = __uint_as_float(f2tf32(v.z));
            w.w = __uint_as_float(f2tf32(v.w));
            *reinterpret_cast<float4*>(dst) = w;
        }
    }
    __syncthreads();

    const int srcA = (lane & ~3) | (lc >> 1);
    const int srcB = srcA + 2;
    const bool oddl = lane & 1;
    const int colb = 2 * lc;

    int cur = 0;
    for (int kb = 0; kb < NKB; kb++) {
        const int k0 = kb * BC;
        const float* Kc = Kbuf[cur];
        const float* Vc = Vbuf[cur];
        const bool pre = (kb + 1 < NKB);

        // ---- 1. prefetch next tile into registers (hides L2 latency) ----
        float4 stg[8];
        if (pre) {
            const float* srcn = g_qkv + En
                + (size_t)(b * Sn + k0 + BC) * E3 + h * Dn;
#pragma unroll
            for (int i = 0; i < 8; i++) {
                int f   = i * 256 + tid;
                int sel = f >> 10;
                int idx = f & 1023;
                int row = idx >> 4;
                int c4  = (idx & 15) << 2;
                stg[i] = *reinterpret_cast<const float4*>(
                    srcn + (size_t)sel * En + (size_t)row * E3 + c4);
            }
        }

        // ---- 2. S = Q @ K^T ----
        float sc[8][4];
#pragma unroll
        for (int nt = 0; nt < 8; nt++)
#pragma unroll
            for (int i = 0; i < 4; i++) sc[nt][i] = 0.0f;

#pragma unroll
        for (int kt = 0; kt < 8; kt++) {
#pragma unroll
            for (int nt = 0; nt < 8; nt++) {
                const float* kp = Kc + (nt * 8 + lr) * KVP + kt * 8 + lc;
                uint32_t b0 = __float_as_uint(kp[0]);
                uint32_t b1 = __float_as_uint(kp[4]);
                mma_tf32(sc[nt][0], sc[nt][1], sc[nt][2], sc[nt][3],
                         qa[kt][0], qa[kt][1], qa[kt][2], qa[kt][3], b0, b1);
            }
        }

        // ---- 3. Gaussian bias + online softmax (registers only) ----
        const float d0f = (float)(qw + lr - k0);     // q - k0 for row lr
        const float d1f = d0f + 8.0f;                // row lr+8
        float rmax0 = -INFINITY, rmax1 = -INFINITY;
#pragma unroll
        for (int nt = 0; nt < 8; nt++) {
#pragma unroll
            for (int e = 0; e < 2; e++) {
                float cj = (float)(nt * 8 + colb + e);
                float fd0 = d0f - cj;
                float fd1 = d1f - cj;
                sc[nt][e]     = fmaf(fd0 * fd0, ninv, sc[nt][e]);
                sc[nt][e + 2] = fmaf(fd1 * fd1, ninv, sc[nt][e + 2]);
                rmax0 = fmaxf(rmax0, sc[nt][e]);
                rmax1 = fmaxf(rmax1, sc[nt][e + 2]);
            }
        }
        rmax0 = fmaxf(rmax0, __shfl_xor_sync(0xffffffffu, rmax0, 1));
        rmax0 = fmaxf(rmax0, __shfl_xor_sync(0xffffffffu, rmax0, 2));
        rmax1 = fmaxf(rmax1, __shfl_xor_sync(0xffffffffu, rmax1, 1));
        rmax1 = fmaxf(rmax1, __shfl_xor_sync(0xffffffffu, rmax1, 2));

        const float mn0 = fmaxf(m0, rmax0);
        const float mn1 = fmaxf(m1, rmax1);
        const float corr0 = __expf(m0 - mn0);
        const float corr1 = __expf(m1 - mn1);
        m0 = mn0; m1 = mn1;

        float ls0 = 0.0f, ls1 = 0.0f;
#pragma unroll
        for (int nt = 0; nt < 8; nt++) {
#pragma unroll
            for (int e = 0; e < 2; e++) {
                float p0 = __expf(sc[nt][e]     - mn0);
                float p1 = __expf(sc[nt][e + 2] - mn1);
                // round P to tf32; sum the ROUNDED value so O/l cancels exactly
                float p0t = __uint_as_float(f2tf32(p0));
                float p1t = __uint_as_float(f2tf32(p1));
                sc[nt][e]     = p0t;
                sc[nt][e + 2] = p1t;
                ls0 += p0t;
                ls1 += p1t;
            }
        }
        l0 = l0 * corr0 + ls0;
        l1 = l1 * corr1 + ls1;

        // rescale O (skip when no row max moved anywhere in the warp)
        if (__ballot_sync(0xffffffffu, (corr0 != 1.0f) | (corr1 != 1.0f))) {
#pragma unroll
            for (int nt = 0; nt < 8; nt++) {
                o[nt][0] *= corr0; o[nt][1] *= corr0;
                o[nt][2] *= corr1; o[nt][3] *= corr1;
            }
        }

        // ---- 4. drain prefetch into the other smem buffer ----
        if (pre) {
            float* Kn = Kbuf[cur ^ 1];
            float* Vn = Vbuf[cur ^ 1];
#pragma unroll
            for (int i = 0; i < 8; i++) {
                int f   = i * 256 + tid;
                int sel = f >> 10;
                int idx = f & 1023;
                int row = idx >> 4;
                int c4  = (idx & 15) << 2;
                float* dst = (sel ? Vn : Kn) + row * KVP + c4;
                float4 w;
                w.x = __uint_as_float(f2tf32(stg[i].x));
                w.y = __uint_as_float(f2tf32(stg[i].y));
                w.z = __uint_as_float(f2tf32(stg[i].z));
                w.w = __uint_as_float(f2tf32(stg[i].w));
                *reinterpret_cast<float4*>(dst) = w;
            }
        }

        // ---- 5. O += P @ V  (A-fragments of P built via quad shuffles) ----
#pragma unroll
        for (int kt = 0; kt < 8; kt++) {
            float p0 = sc[kt][0], p1 = sc[kt][1];
            float p2 = sc[kt][2], p3 = sc[kt][3];
            float x0 = __shfl_sync(0xffffffffu, p0, srcA);
            float x1 = __shfl_sync(0xffffffffu, p1, srcA);
            float y0 = __shfl_sync(0xffffffffu, p0, srcB);
            float y1 = __shfl_sync(0xffffffffu, p1, srcB);
            float x2 = __shfl_sync(0xffffffffu, p2, srcA);
            float x3 = __shfl_sync(0xffffffffu, p3, srcA);
            float y2 = __shfl_sync(0xffffffffu, p2, srcB);
            float y3 = __shfl_sync(0xffffffffu, p3, srcB);
            uint32_t a0 = __float_as_uint(oddl ? x1 : x0);
            uint32_t a2 = __float_as_uint(oddl ? y1 : y0);
            uint32_t a1 = __float_as_uint(oddl ? x3 : x2);
            uint32_t a3 = __float_as_uint(oddl ? y3 : y2);

            const float* vp = Vc + (kt * 8 + lc) * KVP + lr;
#pragma unroll
            for (int nt = 0; nt < 8; nt++) {
                uint32_t b0 = __float_as_uint(vp[nt * 8]);
                uint32_t b1 = __float_as_uint(vp[nt * 8 + 4 * KVP]);
                mma_tf32(o[nt][0], o[nt][1], o[nt][2], o[nt][3],
                         a0, a1, a2, a3, b0, b1);
            }
        }

        __syncthreads();
        cur ^= 1;
    }

    // ---- epilogue: reduce l across quad, normalize, store ----
    l0 += __shfl_xor_sync(0xffffffffu, l0, 1);
    l0 += __shfl_xor_sync(0xffffffffu, l0, 2);
    l1 += __shfl_xor_sync(0xffffffffu, l1, 1);
    l1 += __shfl_xor_sync(0xffffffffu, l1, 2);
    const float il0 = 1.0f / l0;
    const float il1 = 1.0f / l1;

    float* op0 = g_att + (size_t)(b * Sn + qw + lr) * En + h * Dn + colb;
    float* op1 = op0 + 8 * En;
#pragma unroll
    for (int nt = 0; nt < 8; nt++) {
        float2 r0 = make_float2(o[nt][0] * il0, o[nt][1] * il0);
        float2 r1 = make_float2(o[nt][2] * il1, o[nt][3] * il1);
        *reinterpret_cast<float2*>(op0 + nt * 8) = r0;
        *reinterpret_cast<float2*>(op1 + nt * 8) = r1;
    }
}

// ===========================================================================
// Launch
// ===========================================================================
extern "C" void kernel_launch(void* const* d_in, const int* in_sizes, int n_in,
                              void* d_out, int out_size)
{
    const float* x  = (const float*)d_in[0];
    const float* w1 = (const float*)d_in[1];
    const float* b1 = (const float*)d_in[2];
    const float* w2 = (const float*)d_in[3];
    const float* b2 = (const float*)d_in[4];
    const float* t  = (const float*)d_in[5];
    float* out = (float*)d_out;
    (void)in_sizes; (void)n_in; (void)out_size;

    gemm_qkv_kernel<<<dim3(E3 / 128, Mrows / 128), 256>>>(x, w1, b1);

    const int smem = 4 * BC * KVP * (int)sizeof(float);   // 69632 B
    cudaFuncSetAttribute(attn_fa2_kernel,
                         cudaFuncAttributeMaxDynamicSharedMemorySize, smem);
    attn_fa2_kernel<<<dim3(Sn / BR, Hn, Bn), 256, smem>>>(t);

    gemm_out_kernel<<<dim3(En / 128, Mrows / 128), 256>>>(w2, b2, out);
}

// round 4
// speedup vs baseline: 4.6790x; 2.5287x over previous
#include <cuda_runtime.h>
#include <math.h>
#include <stdint.h>

// Problem constants
#define Bn  2
#define Sn  4096
#define En  512
#define Hn  8
#define Dn  64
#define E3  1536
#define Mrows (Bn * Sn)   // 8192

// Scratch (static device globals -- no allocation at runtime)
__device__ float g_qkv[(size_t)Mrows * E3];   // [B*S, 3E]  (q | k | v per row)
__device__ float g_att[(size_t)Mrows * En];   // [B*S, E]   attention output

// ===========================================================================
// Helpers
// ===========================================================================
__device__ __forceinline__ uint32_t f2tf32(float x) {
    uint32_t r;
    asm("cvt.rna.tf32.f32 %0, %1;" : "=r"(r) : "f"(x));
    return r;
}

__device__ __forceinline__ void mma_tf32(
    float& c0, float& c1, float& c2, float& c3,
    uint32_t a0, uint32_t a1, uint32_t a2, uint32_t a3,
    uint32_t b0, uint32_t b1)
{
    asm volatile(
        "mma.sync.aligned.m16n8k8.row.col.f32.tf32.tf32.f32 "
        "{%0,%1,%2,%3}, {%4,%5,%6,%7}, {%8,%9}, {%0,%1,%2,%3};"
        : "+f"(c0), "+f"(c1), "+f"(c2), "+f"(c3)
        : "r"(a0), "r"(a1), "r"(a2), "r"(a3), "r"(b0), "r"(b1));
}

// ===========================================================================
// SGEMM (fp32): C[M,N] = A[M,K] @ Bw[N,K]^T + bias[N]   (projections)
// ===========================================================================
__device__ __forceinline__ void sgemm_body(
    const float* __restrict__ A, const float* __restrict__ Bw,
    const float* __restrict__ bias, float* __restrict__ C,
    int M, int N, int K)
{
    constexpr int BM = 128, BN = 128, BK = 16;
    constexpr int PITCH = BM + 4;
    __shared__ float As[BK * PITCH];
    __shared__ float Ws[BK * PITCH];

    const int tid  = threadIdx.x;
    const int tcol = tid & 15;
    const int trow = tid >> 4;
    const int mBase = blockIdx.y * BM;
    const int nBase = blockIdx.x * BN;

    float acc[8][8];
#pragma unroll
    for (int i = 0; i < 8; i++)
#pragma unroll
        for (int j = 0; j < 8; j++) acc[i][j] = 0.0f;

    for (int kt = 0; kt < K; kt += BK) {
#pragma unroll
        for (int it = 0; it < 2; it++) {
            int idx = tid + it * 256;
            int r   = idx >> 2;
            int c4  = (idx & 3) << 2;
            float4 av = *reinterpret_cast<const float4*>(A + (size_t)(mBase + r) * K + kt + c4);
            As[(c4 + 0) * PITCH + r] = av.x;
            As[(c4 + 1) * PITCH + r] = av.y;
            As[(c4 + 2) * PITCH + r] = av.z;
            As[(c4 + 3) * PITCH + r] = av.w;
            float4 bv = *reinterpret_cast<const float4*>(Bw + (size_t)(nBase + r) * K + kt + c4);
            Ws[(c4 + 0) * PITCH + r] = bv.x;
            Ws[(c4 + 1) * PITCH + r] = bv.y;
            Ws[(c4 + 2) * PITCH + r] = bv.z;
            Ws[(c4 + 3) * PITCH + r] = bv.w;
        }
        __syncthreads();
#pragma unroll
        for (int kk = 0; kk < BK; kk++) {
            float ar[8], br[8];
            *reinterpret_cast<float4*>(ar)     = *reinterpret_cast<const float4*>(As + kk * PITCH + trow * 8);
            *reinterpret_cast<float4*>(ar + 4) = *reinterpret_cast<const float4*>(As + kk * PITCH + trow * 8 + 4);
            *reinterpret_cast<float4*>(br)     = *reinterpret_cast<const float4*>(Ws + kk * PITCH + tcol * 8);
            *reinterpret_cast<float4*>(br + 4) = *reinterpret_cast<const float4*>(Ws + kk * PITCH + tcol * 8 + 4);
#pragma unroll
            for (int i = 0; i < 8; i++)
#pragma unroll
                for (int j = 0; j < 8; j++)
                    acc[i][j] = fmaf(ar[i], br[j], acc[i][j]);
        }
        __syncthreads();
    }
#pragma unroll
    for (int i = 0; i < 8; i++) {
        int m = mBase + trow * 8 + i;
#pragma unroll
        for (int j4 = 0; j4 < 8; j4 += 4) {
            int n = nBase + tcol * 8 + j4;
            float4 bv = *reinterpret_cast<const float4*>(bias + n);
            float4 cv;
            cv.x = acc[i][j4 + 0] + bv.x;
            cv.y = acc[i][j4 + 1] + bv.y;
            cv.z = acc[i][j4 + 2] + bv.z;
            cv.w = acc[i][j4 + 3] + bv.w;
            *reinterpret_cast<float4*>(C + (size_t)m * N + n) = cv;
        }
    }
}

__global__ void __launch_bounds__(256)
gemm_qkv_kernel(const float* __restrict__ x, const float* __restrict__ w1,
                const float* __restrict__ b1)
{
    sgemm_body(x, w1, b1, g_qkv, Mrows, E3, En);
}

__global__ void __launch_bounds__(256)
gemm_out_kernel(const float* __restrict__ w2, const float* __restrict__ b2,
                float* __restrict__ out)
{
    sgemm_body(g_att, w2, b2, out, Mrows, En, En);
}

// ===========================================================================
// FlashAttention-2 with Gaussian bias, tf32 mma.sync (HMMA).
// Gaussian bias => attention is LOCAL: weight of key at distance D is
// exp(-D^2/(2 t^4)); beyond D = sqrt(120)*t^2 (~11*sigma) the suppression
// factor is < e^-60, and with score spread generously bounded by 30 the
// dropped relative mass is < 4096 * e^-30 ~ 4e-10  (far below fp32 eps).
// So each q-tile only visits k-tiles within window W = 11*t^2 + 64.
// Grid (Sn/128, Hn, Bn), 256 threads (8 warps x 16 q-rows). Bc = 64.
// ===========================================================================
#define BR   128
#define BC   64
#define KVP  68                    // smem pitch (floats)
#define NKB  (Sn / BC)             // 64 key tiles

__global__ void __launch_bounds__(256, 1)
attn_fa2_kernel(const float* __restrict__ t)
{
    extern __shared__ float sm[];
    float* Kbuf[2] = { sm,                 sm + 2 * BC * KVP };
    float* Vbuf[2] = { sm + BC * KVP,      sm + 3 * BC * KVP };

    const int tid  = threadIdx.x;
    const int lane = tid & 31;
    const int wid  = tid >> 5;
    const int qt = blockIdx.x, h = blockIdx.y, b = blockIdx.z;
    const int q0 = qt * BR;
    const int qw = q0 + wid * 16;          // this warp's first q row

    const int lr = lane >> 2;              // 0..7 row-in-tile / n-col selector
    const int lc = lane & 3;               // 0..3 k-col / paired-col selector

    const float tt = t[h];
    const float sig = tt * tt;                       // sigma = t^2
    const float ninv = -1.0f / (2.0f * sig * sig);   // -1/(2 sigma^2)

    // ---- locality window: only k-tiles with |q - k| <= W matter ----
    const float Wf = fminf(11.0f * sig + 64.0f, (float)Sn);
    const int   W  = (int)Wf;
    const int kb_lo = max(0, (q0 - W) >> 6);
    const int kb_hi = min(NKB - 1, (q0 + BR - 1 + W) >> 6);

    // ---- Q fragments (tf32, pre-scaled by 1/8), resident in registers ----
    uint32_t qa[8][4];
    {
        const float* qp = g_qkv + (size_t)(b * Sn + qw + lr) * E3 + h * Dn;
        const float* qp8 = qp + 8 * E3;
#pragma unroll
        for (int kt = 0; kt < 8; kt++) {
            qa[kt][0] = f2tf32(qp [kt * 8 + lc]     * 0.125f);
            qa[kt][1] = f2tf32(qp8[kt * 8 + lc]     * 0.125f);
            qa[kt][2] = f2tf32(qp [kt * 8 + lc + 4] * 0.125f);
            qa[kt][3] = f2tf32(qp8[kt * 8 + lc + 4] * 0.125f);
        }
    }

    float o[8][4];
#pragma unroll
    for (int nt = 0; nt < 8; nt++)
#pragma unroll
        for (int i = 0; i < 4; i++) o[nt][i] = 0.0f;
    float m0 = -INFINITY, m1 = -INFINITY;
    float l0 = 0.0f, l1 = 0.0f;

    // ---- preload first in-window tile ----
    {
        const float* src0 = g_qkv + En
            + (size_t)(b * Sn + kb_lo * BC) * E3 + h * Dn;
#pragma unroll
        for (int i = 0; i < 8; i++) {
            int f   = i * 256 + tid;
            int sel = f >> 10;
            int idx = f & 1023;
            int row = idx >> 4;
            int c4  = (idx & 15) << 2;
            float4 v = *reinterpret_cast<const float4*>(
                src0 + (size_t)sel * En + (size_t)row * E3 + c4);
            float* dst = (sel ? Vbuf[0] : Kbuf[0]) + row * KVP + c4;
            float4 w;
            w.x = __uint_as_float(f2tf32(v.x));
            w.y = __uint_as_float(f2tf32(v.y));
            w.z = __uint_as_float(f2tf32(v.z));
            w.w = __uint_as_float(f2tf32(v.w));
            *reinterpret_cast<float4*>(dst) = w;
        }
    }
    __syncthreads();

    const int srcA = (lane & ~3) | (lc >> 1);
    const int srcB = srcA + 2;
    const bool oddl = lane & 1;
    const int colb = 2 * lc;

    int cur = 0;
    for (int kb = kb_lo; kb <= kb_hi; kb++) {
        const int k0 = kb * BC;
        const float* Kc = Kbuf[cur];
        const float* Vc = Vbuf[cur];
        const bool pre = (kb + 1 <= kb_hi);

        // ---- 1. prefetch next tile into registers (hides L2 latency) ----
        float4 stg[8];
        if (pre) {
            const float* srcn = g_qkv + En
                + (size_t)(b * Sn + k0 + BC) * E3 + h * Dn;
#pragma unroll
            for (int i = 0; i < 8; i++) {
                int f   = i * 256 + tid;
                int sel = f >> 10;
                int idx = f & 1023;
                int row = idx >> 4;
                int c4  = (idx & 15) << 2;
                stg[i] = *reinterpret_cast<const float4*>(
                    srcn + (size_t)sel * En + (size_t)row * E3 + c4);
            }
        }

        // ---- 2. S = Q @ K^T ----
        float sc[8][4];
#pragma unroll
        for (int nt = 0; nt < 8; nt++)
#pragma unroll
            for (int i = 0; i < 4; i++) sc[nt][i] = 0.0f;

#pragma unroll
        for (int kt = 0; kt < 8; kt++) {
#pragma unroll
            for (int nt = 0; nt < 8; nt++) {
                const float* kp = Kc + (nt * 8 + lr) * KVP + kt * 8 + lc;
                uint32_t b0 = __float_as_uint(kp[0]);
                uint32_t b1 = __float_as_uint(kp[4]);
                mma_tf32(sc[nt][0], sc[nt][1], sc[nt][2], sc[nt][3],
                         qa[kt][0], qa[kt][1], qa[kt][2], qa[kt][3], b0, b1);
            }
        }

        // ---- 3. Gaussian bias + online softmax (registers only) ----
        const float d0f = (float)(qw + lr - k0);     // q - k0 for row lr
        const float d1f = d0f + 8.0f;                // row lr+8
        float rmax0 = -INFINITY, rmax1 = -INFINITY;
#pragma unroll
        for (int nt = 0; nt < 8; nt++) {
#pragma unroll
            for (int e = 0; e < 2; e++) {
                float cj = (float)(nt * 8 + colb + e);
                float fd0 = d0f - cj;
                float fd1 = d1f - cj;
                sc[nt][e]     = fmaf(fd0 * fd0, ninv, sc[nt][e]);
                sc[nt][e + 2] = fmaf(fd1 * fd1, ninv, sc[nt][e + 2]);
                rmax0 = fmaxf(rmax0, sc[nt][e]);
                rmax1 = fmaxf(rmax1, sc[nt][e + 2]);
            }
        }
        rmax0 = fmaxf(rmax0, __shfl_xor_sync(0xffffffffu, rmax0, 1));
        rmax0 = fmaxf(rmax0, __shfl_xor_sync(0xffffffffu, rmax0, 2));
        rmax1 = fmaxf(rmax1, __shfl_xor_sync(0xffffffffu, rmax1, 1));
        rmax1 = fmaxf(rmax1, __shfl_xor_sync(0xffffffffu, rmax1, 2));

        const float mn0 = fmaxf(m0, rmax0);
        const float mn1 = fmaxf(m1, rmax1);
        const float corr0 = __expf(m0 - mn0);
        const float corr1 = __expf(m1 - mn1);
        m0 = mn0; m1 = mn1;

        float ls0 = 0.0f, ls1 = 0.0f;
#pragma unroll
        for (int nt = 0; nt < 8; nt++) {
#pragma unroll
            for (int e = 0; e < 2; e++) {
                float p0 = __expf(sc[nt][e]     - mn0);
                float p1 = __expf(sc[nt][e + 2] - mn1);
                // round P to tf32; sum the ROUNDED value so O/l cancels exactly
                float p0t = __uint_as_float(f2tf32(p0));
                float p1t = __uint_as_float(f2tf32(p1));
                sc[nt][e]     = p0t;
                sc[nt][e + 2] = p1t;
                ls0 += p0t;
                ls1 += p1t;
            }
        }
        l0 = l0 * corr0 + ls0;
        l1 = l1 * corr1 + ls1;

        // rescale O (skip when no row max moved anywhere in the warp)
        if (__ballot_sync(0xffffffffu, (corr0 != 1.0f) | (corr1 != 1.0f))) {
#pragma unroll
            for (int nt = 0; nt < 8; nt++) {
                o[nt][0] *= corr0; o[nt][1] *= corr0;
                o[nt][2] *= corr1; o[nt][3] *= corr1;
            }
        }

        // ---- 4. drain prefetch into the other smem buffer ----
        if (pre) {
            float* Kn = Kbuf[cur ^ 1];
            float* Vn = Vbuf[cur ^ 1];
#pragma unroll
            for (int i = 0; i < 8; i++) {
                int f   = i * 256 + tid;
                int sel = f >> 10;
                int idx = f & 1023;
                int row = idx >> 4;
                int c4  = (idx & 15) << 2;
                float* dst = (sel ? Vn : Kn) + row * KVP + c4;
                float4 w;
                w.x = __uint_as_float(f2tf32(stg[i].x));
                w.y = __uint_as_float(f2tf32(stg[i].y));
                w.z = __uint_as_float(f2tf32(stg[i].z));
                w.w = __uint_as_float(f2tf32(stg[i].w));
                *reinterpret_cast<float4*>(dst) = w;
            }
        }

        // ---- 5. O += P @ V  (A-fragments of P built via quad shuffles) ----
#pragma unroll
        for (int kt = 0; kt < 8; kt++) {
            float p0 = sc[kt][0], p1 = sc[kt][1];
            float p2 = sc[kt][2], p3 = sc[kt][3];
            float x0 = __shfl_sync(0xffffffffu, p0, srcA);
            float x1 = __shfl_sync(0xffffffffu, p1, srcA);
            float y0 = __shfl_sync(0xffffffffu, p0, srcB);
            float y1 = __shfl_sync(0xffffffffu, p1, srcB);
            float x2 = __shfl_sync(0xffffffffu, p2, srcA);
            float x3 = __shfl_sync(0xffffffffu, p3, srcA);
            float y2 = __shfl_sync(0xffffffffu, p2, srcB);
            float y3 = __shfl_sync(0xffffffffu, p3, srcB);
            uint32_t a0 = __float_as_uint(oddl ? x1 : x0);
            uint32_t a2 = __float_as_uint(oddl ? y1 : y0);
            uint32_t a1 = __float_as_uint(oddl ? x3 : x2);
            uint32_t a3 = __float_as_uint(oddl ? y3 : y2);

            const float* vp = Vc + (kt * 8 + lc) * KVP + lr;
#pragma unroll
            for (int nt = 0; nt < 8; nt++) {
                uint32_t b0 = __float_as_uint(vp[nt * 8]);
                uint32_t b1 = __float_as_uint(vp[nt * 8 + 4 * KVP]);
                mma_tf32(o[nt][0], o[nt][1], o[nt][2], o[nt][3],
                         a0, a1, a2, a3, b0, b1);
            }
        }

        __syncthreads();
        cur ^= 1;
    }

    // ---- epilogue: reduce l across quad, normalize, store ----
    l0 += __shfl_xor_sync(0xffffffffu, l0, 1);
    l0 += __shfl_xor_sync(0xffffffffu, l0, 2);
    l1 += __shfl_xor_sync(0xffffffffu, l1, 1);
    l1 += __shfl_xor_sync(0xffffffffu, l1, 2);
    const float il0 = 1.0f / l0;
    const float il1 = 1.0f / l1;

    float* op0 = g_att + (size_t)(b * Sn + qw + lr) * En + h * Dn + colb;
    float* op1 = op0 + 8 * En;
#pragma unroll
    for (int nt = 0; nt < 8; nt++) {
        float2 r0 = make_float2(o[nt][0] * il0, o[nt][1] * il0);
        float2 r1 = make_float2(o[nt][2] * il1, o[nt][3] * il1);
        *reinterpret_cast<float2*>(op0 + nt * 8) = r0;
        *reinterpret_cast<float2*>(op1 + nt * 8) = r1;
    }
}

// ===========================================================================
// Launch
// ===========================================================================
extern "C" void kernel_launch(void* const* d_in, const int* in_sizes, int n_in,
                              void* d_out, int out_size)
{
    const float* x  = (const float*)d_in[0];
    const float* w1 = (const float*)d_in[1];
    const float* b1 = (const float*)d_in[2];
    const float* w2 = (const float*)d_in[3];
    const float* b2 = (const float*)d_in[4];
    const float* t  = (const float*)d_in[5];
    float* out = (float*)d_out;
    (void)in_sizes; (void)n_in; (void)out_size;

    gemm_qkv_kernel<<<dim3(E3 / 128, Mrows / 128), 256>>>(x, w1, b1);

    const int smem = 4 * BC * KVP * (int)sizeof(float);   // 69632 B
    cudaFuncSetAttribute(attn_fa2_kernel,
                         cudaFuncAttributeMaxDynamicSharedMemorySize, smem);
    attn_fa2_kernel<<<dim3(Sn / BR, Hn, Bn), 256, smem>>>(t);

    gemm_out_kernel<<<dim3(En / 128, Mrows / 128), 256>>>(w2, b2, out);
}

// round 5
// speedup vs baseline: 8.6476x; 1.8482x over previous
#include <cuda_runtime.h>
#include <math.h>
#include <stdint.h>

// Problem constants
#define Bn  2
#define Sn  4096
#define En  512
#define Hn  8
#define Dn  64
#define E3  1536
#define Mrows (Bn * Sn)   // 8192

// Scratch (static device globals -- no allocation at runtime)
__device__ float g_qkv[(size_t)Mrows * E3];   // [B*S, 3E]  (q | k | v per row)
__device__ float g_att[(size_t)Mrows * En];   // [B*S, E]   attention output

// ===========================================================================
// Helpers
// ===========================================================================
__device__ __forceinline__ uint32_t f2tf32(float x) {
    uint32_t r;
    asm("cvt.rna.tf32.f32 %0, %1;" : "=r"(r) : "f"(x));
    return r;
}

__device__ __forceinline__ void mma_tf32(
    float& c0, float& c1, float& c2, float& c3,
    uint32_t a0, uint32_t a1, uint32_t a2, uint32_t a3,
    uint32_t b0, uint32_t b1)
{
    asm volatile(
        "mma.sync.aligned.m16n8k8.row.col.f32.tf32.tf32.f32 "
        "{%0,%1,%2,%3}, {%4,%5,%6,%7}, {%8,%9}, {%0,%1,%2,%3};"
        : "+f"(c0), "+f"(c1), "+f"(c2), "+f"(c3)
        : "r"(a0), "r"(a1), "r"(a2), "r"(a3), "r"(b0), "r"(b1));
}

// ===========================================================================
// tf32 tensor-core GEMM: C[M,N] = A[M,K] @ Bw[N,K]^T + bias[N]
// 128x128 block tile, BK=16, 256 threads (8 warps, 2x4), warp tile 64x32.
// Both operands K-contiguous; B-fragment layout identical to the attention
// kernel's (validated). Smem pitch 20 floats => conflict-free frag loads.
// ===========================================================================
#define GP 20   // smem pitch in floats

__device__ __forceinline__ void tf32_gemm_body(
    const float* __restrict__ A, const float* __restrict__ Bw,
    const float* __restrict__ bias, float* __restrict__ C,
    int M, int N, int K)
{
    __shared__ float As[2][128 * GP];
    __shared__ float Ws[2][128 * GP];

    const int tid  = threadIdx.x;
    const int lane = tid & 31;
    const int wid  = tid >> 5;
    const int wm   = wid >> 2;          // 0..1
    const int wn   = wid & 3;           // 0..3
    const int lr   = lane >> 2;         // 0..7
    const int lc   = lane & 3;          // 0..3
    const int mBase = blockIdx.y * 128;
    const int nBase = blockIdx.x * 128;

    float acc[4][4][4];
#pragma unroll
    for (int mt = 0; mt < 4; mt++)
#pragma unroll
        for (int nt = 0; nt < 4; nt++)
#pragma unroll
            for (int i = 0; i < 4; i++) acc[mt][nt][i] = 0.0f;

    // Per-thread slab-load geometry: 4 float4 (A half f<512, W half f>=512)
    int lrow[4], lc4[4];
    const float* lsrc[4];
#pragma unroll
    for (int i = 0; i < 4; i++) {
        int f   = tid + i * 256;
        int sel = f >> 9;
        int idx = f & 511;
        lrow[i] = idx >> 2;
        lc4[i]  = (idx & 3) << 2;
        lsrc[i] = sel ? (Bw + (size_t)(nBase + lrow[i]) * K)
                      : (A  + (size_t)(mBase + lrow[i]) * K);
    }
    float* ldst[2][4];
#pragma unroll
    for (int bufi = 0; bufi < 2; bufi++)
#pragma unroll
        for (int i = 0; i < 4; i++) {
            int f   = tid + i * 256;
            int sel = f >> 9;
            ldst[bufi][i] = (sel ? Ws[bufi] : As[bufi]) + lrow[i] * GP + lc4[i];
        }

    // Preload slab 0
#pragma unroll
    for (int i = 0; i < 4; i++) {
        float4 v = *reinterpret_cast<const float4*>(lsrc[i] + lc4[i]);
        float4 w;
        w.x = __uint_as_float(f2tf32(v.x));
        w.y = __uint_as_float(f2tf32(v.y));
        w.z = __uint_as_float(f2tf32(v.z));
        w.w = __uint_as_float(f2tf32(v.w));
        *reinterpret_cast<float4*>(ldst[0][i]) = w;
    }
    __syncthreads();

    const int nIter = K >> 4;
    int cur = 0;
    for (int it = 0; it < nIter; it++) {
        const bool pre = (it + 1 < nIter);
        float4 stg[4];
        if (pre) {
            const int kt = (it + 1) << 4;
#pragma unroll
            for (int i = 0; i < 4; i++)
                stg[i] = *reinterpret_cast<const float4*>(lsrc[i] + kt + lc4[i]);
        }

        const float* Ab = As[cur];
        const float* Wb = Ws[cur];
#pragma unroll
        for (int k8 = 0; k8 < 16; k8 += 8) {
            uint32_t af[4][4], bf[4][2];
#pragma unroll
            for (int mt = 0; mt < 4; mt++) {
                const float* ap = Ab + (wm * 64 + mt * 16 + lr) * GP + k8 + lc;
                af[mt][0] = __float_as_uint(ap[0]);
                af[mt][1] = __float_as_uint(ap[8 * GP]);
                af[mt][2] = __float_as_uint(ap[4]);
                af[mt][3] = __float_as_uint(ap[8 * GP + 4]);
            }
#pragma unroll
            for (int nt = 0; nt < 4; nt++) {
                const float* bp = Wb + (wn * 32 + nt * 8 + lr) * GP + k8 + lc;
                bf[nt][0] = __float_as_uint(bp[0]);
                bf[nt][1] = __float_as_uint(bp[4]);
            }
#pragma unroll
            for (int mt = 0; mt < 4; mt++)
#pragma unroll
                for (int nt = 0; nt < 4; nt++)
                    mma_tf32(acc[mt][nt][0], acc[mt][nt][1],
                             acc[mt][nt][2], acc[mt][nt][3],
                             af[mt][0], af[mt][1], af[mt][2], af[mt][3],
                             bf[nt][0], bf[nt][1]);
        }

        if (pre) {
#pragma unroll
            for (int i = 0; i < 4; i++) {
                float4 w;
                w.x = __uint_as_float(f2tf32(stg[i].x));
                w.y = __uint_as_float(f2tf32(stg[i].y));
                w.z = __uint_as_float(f2tf32(stg[i].z));
                w.w = __uint_as_float(f2tf32(stg[i].w));
                *reinterpret_cast<float4*>(ldst[cur ^ 1][i]) = w;
            }
        }
        __syncthreads();
        cur ^= 1;
    }

    // Epilogue: add bias, store float2 pairs
#pragma unroll
    for (int mt = 0; mt < 4; mt++) {
        const int row0 = mBase + wm * 64 + mt * 16 + lr;
#pragma unroll
        for (int nt = 0; nt < 4; nt++) {
            const int col = nBase + wn * 32 + nt * 8 + 2 * lc;
            const float bx = bias[col];
            const float by = bias[col + 1];
            float2 r0 = make_float2(acc[mt][nt][0] + bx, acc[mt][nt][1] + by);
            float2 r1 = make_float2(acc[mt][nt][2] + bx, acc[mt][nt][3] + by);
            *reinterpret_cast<float2*>(C + (size_t)row0 * N + col) = r0;
            *reinterpret_cast<float2*>(C + (size_t)(row0 + 8) * N + col) = r1;
        }
    }
}

__global__ void __launch_bounds__(256)
gemm_qkv_kernel(const float* __restrict__ x, const float* __restrict__ w1,
                const float* __restrict__ b1)
{
    tf32_gemm_body(x, w1, b1, g_qkv, Mrows, E3, En);
}

__global__ void __launch_bounds__(256)
gemm_out_kernel(const float* __restrict__ w2, const float* __restrict__ b2,
                float* __restrict__ out)
{
    tf32_gemm_body(g_att, w2, b2, out, Mrows, En, En);
}

// ===========================================================================
// FlashAttention-2 with Gaussian bias, tf32 mma.sync (HMMA), windowed.
// Weight of key at distance D is exp(-D^2/(2 t^4)); beyond W = 11 t^2 + 64
// the dropped relative mass is < 4e-10 (sub-fp32-eps). Unchanged from R4.
// ===========================================================================
#define BR   128
#define BC   64
#define KVP  68                    // smem pitch (floats)
#define NKB  (Sn / BC)             // 64 key tiles

__global__ void __launch_bounds__(256, 1)
attn_fa2_kernel(const float* __restrict__ t)
{
    extern __shared__ float sm[];
    float* Kbuf[2] = { sm,                 sm + 2 * BC * KVP };
    float* Vbuf[2] = { sm + BC * KVP,      sm + 3 * BC * KVP };

    const int tid  = threadIdx.x;
    const int lane = tid & 31;
    const int wid  = tid >> 5;
    const int qt = blockIdx.x, h = blockIdx.y, b = blockIdx.z;
    const int q0 = qt * BR;
    const int qw = q0 + wid * 16;

    const int lr = lane >> 2;
    const int lc = lane & 3;

    const float tt = t[h];
    const float sig = tt * tt;
    const float ninv = -1.0f / (2.0f * sig * sig);

    const float Wf = fminf(11.0f * sig + 64.0f, (float)Sn);
    const int   W  = (int)Wf;
    const int kb_lo = max(0, (q0 - W) >> 6);
    const int kb_hi = min(NKB - 1, (q0 + BR - 1 + W) >> 6);

    uint32_t qa[8][4];
    {
        const float* qp = g_qkv + (size_t)(b * Sn + qw + lr) * E3 + h * Dn;
        const float* qp8 = qp + 8 * E3;
#pragma unroll
        for (int kt = 0; kt < 8; kt++) {
            qa[kt][0] = f2tf32(qp [kt * 8 + lc]     * 0.125f);
            qa[kt][1] = f2tf32(qp8[kt * 8 + lc]     * 0.125f);
            qa[kt][2] = f2tf32(qp [kt * 8 + lc + 4] * 0.125f);
            qa[kt][3] = f2tf32(qp8[kt * 8 + lc + 4] * 0.125f);
        }
    }

    float o[8][4];
#pragma unroll
    for (int nt = 0; nt < 8; nt++)
#pragma unroll
        for (int i = 0; i < 4; i++) o[nt][i] = 0.0f;
    float m0 = -INFINITY, m1 = -INFINITY;
    float l0 = 0.0f, l1 = 0.0f;

    {
        const float* src0 = g_qkv + En
            + (size_t)(b * Sn + kb_lo * BC) * E3 + h * Dn;
#pragma unroll
        for (int i = 0; i < 8; i++) {
            int f   = i * 256 + tid;
            int sel = f >> 10;
            int idx = f & 1023;
            int row = idx >> 4;
            int c4  = (idx & 15) << 2;
            float4 v = *reinterpret_cast<const float4*>(
                src0 + (size_t)sel * En + (size_t)row * E3 + c4);
            float* dst = (sel ? Vbuf[0] : Kbuf[0]) + row * KVP + c4;
            float4 w;
            w.x = __uint_as_float(f2tf32(v.x));
            w.y = __uint_as_float(f2tf32(v.y));
            w.z = __uint_as_float(f2tf32(v.z));
            w.w = __uint_as_float(f2tf32(v.w));
            *reinterpret_cast<float4*>(dst) = w;
        }
    }
    __syncthreads();

    const int srcA = (lane & ~3) | (lc >> 1);
    const int srcB = srcA + 2;
    const bool oddl = lane & 1;
    const int colb = 2 * lc;

    int cur = 0;
    for (int kb = kb_lo; kb <= kb_hi; kb++) {
        const int k0 = kb * BC;
        const float* Kc = Kbuf[cur];
        const float* Vc = Vbuf[cur];
        const bool pre = (kb + 1 <= kb_hi);

        float4 stg[8];
        if (pre) {
            const float* srcn = g_qkv + En
                + (size_t)(b * Sn + k0 + BC) * E3 + h * Dn;
#pragma unroll
            for (int i = 0; i < 8; i++) {
                int f   = i * 256 + tid;
                int sel = f >> 10;
                int idx = f & 1023;
                int row = idx >> 4;
                int c4  = (idx & 15) << 2;
                stg[i] = *reinterpret_cast<const float4*>(
                    srcn + (size_t)sel * En + (size_t)row * E3 + c4);
            }
        }

        float sc[8][4];
#pragma unroll
        for (int nt = 0; nt < 8; nt++)
#pragma unroll
            for (int i = 0; i < 4; i++) sc[nt][i] = 0.0f;

#pragma unroll
        for (int kt = 0; kt < 8; kt++) {
#pragma unroll
            for (int nt = 0; nt < 8; nt++) {
                const float* kp = Kc + (nt * 8 + lr) * KVP + kt * 8 + lc;
                uint32_t b0 = __float_as_uint(kp[0]);
                uint32_t b1 = __float_as_uint(kp[4]);
                mma_tf32(sc[nt][0], sc[nt][1], sc[nt][2], sc[nt][3],
                         qa[kt][0], qa[kt][1], qa[kt][2], qa[kt][3], b0, b1);
            }
        }

        const float d0f = (float)(qw + lr - k0);
        const float d1f = d0f + 8.0f;
        float rmax0 = -INFINITY, rmax1 = -INFINITY;
#pragma unroll
        for (int nt = 0; nt < 8; nt++) {
#pragma unroll
            for (int e = 0; e < 2; e++) {
                float cj = (float)(nt * 8 + colb + e);
                float fd0 = d0f - cj;
                float fd1 = d1f - cj;
                sc[nt][e]     = fmaf(fd0 * fd0, ninv, sc[nt][e]);
                sc[nt][e + 2] = fmaf(fd1 * fd1, ninv, sc[nt][e + 2]);
                rmax0 = fmaxf(rmax0, sc[nt][e]);
                rmax1 = fmaxf(rmax1, sc[nt][e + 2]);
            }
        }
        rmax0 = fmaxf(rmax0, __shfl_xor_sync(0xffffffffu, rmax0, 1));
        rmax0 = fmaxf(rmax0, __shfl_xor_sync(0xffffffffu, rmax0, 2));
        rmax1 = fmaxf(rmax1, __shfl_xor_sync(0xffffffffu, rmax1, 1));
        rmax1 = fmaxf(rmax1, __shfl_xor_sync(0xffffffffu, rmax1, 2));

        const float mn0 = fmaxf(m0, rmax0);
        const float mn1 = fmaxf(m1, rmax1);
        const float corr0 = __expf(m0 - mn0);
        const float corr1 = __expf(m1 - mn1);
        m0 = mn0; m1 = mn1;

        float ls0 = 0.0f, ls1 = 0.0f;
#pragma unroll
        for (int nt = 0; nt < 8; nt++) {
#pragma unroll
            for (int e = 0; e < 2; e++) {
                float p0 = __expf(sc[nt][e]     - mn0);
                float p1 = __expf(sc[nt][e + 2] - mn1);
                float p0t = __uint_as_float(f2tf32(p0));
                float p1t = __uint_as_float(f2tf32(p1));
                sc[nt][e]     = p0t;
                sc[nt][e + 2] = p1t;
                ls0 += p0t;
                ls1 += p1t;
            }
        }
        l0 = l0 * corr0 + ls0;
        l1 = l1 * corr1 + ls1;

        if (__ballot_sync(0xffffffffu, (corr0 != 1.0f) | (corr1 != 1.0f))) {
#pragma unroll
            for (int nt = 0; nt < 8; nt++) {
                o[nt][0] *= corr0; o[nt][1] *= corr0;
                o[nt][2] *= corr1; o[nt][3] *= corr1;
            }
        }

        if (pre) {
            float* Kn = Kbuf[cur ^ 1];
            float* Vn = Vbuf[cur ^ 1];
#pragma unroll
            for (int i = 0; i < 8; i++) {
                int f   = i * 256 + tid;
                int sel = f >> 10;
                int idx = f & 1023;
                int row = idx >> 4;
                int c4  = (idx & 15) << 2;
                float* dst = (sel ? Vn : Kn) + row * KVP + c4;
                float4 w;
                w.x = __uint_as_float(f2tf32(stg[i].x));
                w.y = __uint_as_float(f2tf32(stg[i].y));
                w.z = __uint_as_float(f2tf32(stg[i].z));
                w.w = __uint_as_float(f2tf32(stg[i].w));
                *reinterpret_cast<float4*>(dst) = w;
            }
        }

#pragma unroll
        for (int kt = 0; kt < 8; kt++) {
            float p0 = sc[kt][0], p1 = sc[kt][1];
            float p2 = sc[kt][2], p3 = sc[kt][3];
            float x0 = __shfl_sync(0xffffffffu, p0, srcA);
            float x1 = __shfl_sync(0xffffffffu, p1, srcA);
            float y0 = __shfl_sync(0xffffffffu, p0, srcB);
            float y1 = __shfl_sync(0xffffffffu, p1, srcB);
            float x2 = __shfl_sync(0xffffffffu, p2, srcA);
            float x3 = __shfl_sync(0xffffffffu, p3, srcA);
            float y2 = __shfl_sync(0xffffffffu, p2, srcB);
            float y3 = __shfl_sync(0xffffffffu, p3, srcB);
            uint32_t a0 = __float_as_uint(oddl ? x1 : x0);
            uint32_t a2 = __float_as_uint(oddl ? y1 : y0);
            uint32_t a1 = __float_as_uint(oddl ? x3 : x2);
            uint32_t a3 = __float_as_uint(oddl ? y3 : y2);

            const float* vp = Vc + (kt * 8 + lc) * KVP + lr;
#pragma unroll
            for (int nt = 0; nt < 8; nt++) {
                uint32_t b0 = __float_as_uint(vp[nt * 8]);
                uint32_t b1 = __float_as_uint(vp[nt * 8 + 4 * KVP]);
                mma_tf32(o[nt][0], o[nt][1], o[nt][2], o[nt][3],
                         a0, a1, a2, a3, b0, b1);
            }
        }

        __syncthreads();
        cur ^= 1;
    }

    l0 += __shfl_xor_sync(0xffffffffu, l0, 1);
    l0 += __shfl_xor_sync(0xffffffffu, l0, 2);
    l1 += __shfl_xor_sync(0xffffffffu, l1, 1);
    l1 += __shfl_xor_sync(0xffffffffu, l1, 2);
    const float il0 = 1.0f / l0;
    const float il1 = 1.0f / l1;

    float* op0 = g_att + (size_t)(b * Sn + qw + lr) * En + h * Dn + colb;
    float* op1 = op0 + 8 * En;
#pragma unroll
    for (int nt = 0; nt < 8; nt++) {
        float2 r0 = make_float2(o[nt][0] * il0, o[nt][1] * il0);
        float2 r1 = make_float2(o[nt][2] * il1, o[nt][3] * il1);
        *reinterpret_cast<float2*>(op0 + nt * 8) = r0;
        *reinterpret_cast<float2*>(op1 + nt * 8) = r1;
    }
}

// ===========================================================================
// Launch
// ===========================================================================
extern "C" void kernel_launch(void* const* d_in, const int* in_sizes, int n_in,
                              void* d_out, int out_size)
{
    const float* x  = (const float*)d_in[0];
    const float* w1 = (const float*)d_in[1];
    const float* b1 = (const float*)d_in[2];
    const float* w2 = (const float*)d_in[3];
    const float* b2 = (const float*)d_in[4];
    const float* t  = (const float*)d_in[5];
    float* out = (float*)d_out;
    (void)in_sizes; (void)n_in; (void)out_size;

    gemm_qkv_kernel<<<dim3(E3 / 128, Mrows / 128), 256>>>(x, w1, b1);

    const int smem = 4 * BC * KVP * (int)sizeof(float);   // 69632 B
    cudaFuncSetAttribute(attn_fa2_kernel,
                         cudaFuncAttributeMaxDynamicSharedMemorySize, smem);
    attn_fa2_kernel<<<dim3(Sn / BR, Hn, Bn), 256, smem>>>(t);

    gemm_out_kernel<<<dim3(En / 128, Mrows / 128), 256>>>(w2, b2, out);
}

// round 6
// speedup vs baseline: 10.1108x; 1.1692x over previous
#include <cuda_runtime.h>
#include <math.h>
#include <stdint.h>

// Problem constants
#define Bn  2
#define Sn  4096
#define En  512
#define Hn  8
#define Dn  64
#define E3  1536
#define Mrows (Bn * Sn)   // 8192

// Scratch (static device globals -- no allocation at runtime)
__device__ float g_qkv[(size_t)Mrows * E3];   // [B*S, 3E] (tf32-rounded)
__device__ float g_att[(size_t)Mrows * En];   // [B*S, E]  (tf32-rounded)
__device__ float g_xc [(size_t)Mrows * En];   // x  pre-rounded to tf32
__device__ float g_w1c[(size_t)E3 * En];      // w1 pre-rounded
__device__ float g_w2c[(size_t)En * En];      // w2 pre-rounded

// ===========================================================================
// Helpers
// ===========================================================================
__device__ __forceinline__ uint32_t f2tf32(float x) {
    uint32_t r;
    asm("cvt.rna.tf32.f32 %0, %1;" : "=r"(r) : "f"(x));
    return r;
}
__device__ __forceinline__ uint32_t smem_u32(const void* p) {
    uint32_t a;
    asm("{ .reg .u64 t; cvta.to.shared.u64 t, %1; cvt.u32.u64 %0, t; }"
        : "=r"(a) : "l"(p));
    return a;
}
__device__ __forceinline__ void cp16(uint32_t d, const void* s) {
    asm volatile("cp.async.cg.shared.global [%0], [%1], 16;"
                 :: "r"(d), "l"(s));
}
#define CP_COMMIT() asm volatile("cp.async.commit_group;" ::: "memory")
#define CP_WAIT1()  asm volatile("cp.async.wait_group 1;" ::: "memory")
#define CP_WAIT0()  asm volatile("cp.async.wait_group 0;" ::: "memory")

__device__ __forceinline__ void mma_tf32(
    float& c0, float& c1, float& c2, float& c3,
    uint32_t a0, uint32_t a1, uint32_t a2, uint32_t a3,
    uint32_t b0, uint32_t b1)
{
    asm volatile(
        "mma.sync.aligned.m16n8k8.row.col.f32.tf32.tf32.f32 "
        "{%0,%1,%2,%3}, {%4,%5,%6,%7}, {%8,%9}, {%0,%1,%2,%3};"
        : "+f"(c0), "+f"(c1), "+f"(c2), "+f"(c3)
        : "r"(a0), "r"(a1), "r"(a2), "r"(a3), "r"(b0), "r"(b1));
}

// ===========================================================================
// Pre-round x, w1, w2 to tf32 (one flat grid: 5120 blocks x 256)
// ===========================================================================
#define NX4  (Mrows * En / 4)      // 1048576
#define NW14 (E3 * En / 4)         // 196608
#define NW24 (En * En / 4)         // 65536

__global__ void __launch_bounds__(256)
cvt_tf32_kernel(const float4* __restrict__ x, const float4* __restrict__ w1,
                const float4* __restrict__ w2)
{
    int i = blockIdx.x * 256 + threadIdx.x;
    const float4* s;
    float4* d;
    if (i < NX4) {
        s = x + i;                       d = (float4*)g_xc + i;
    } else if (i < NX4 + NW14) {
        s = w1 + (i - NX4);              d = (float4*)g_w1c + (i - NX4);
    } else {
        s = w2 + (i - NX4 - NW14);       d = (float4*)g_w2c + (i - NX4 - NW14);
    }
    float4 v = *s;
    float4 w;
    w.x = __uint_as_float(f2tf32(v.x));
    w.y = __uint_as_float(f2tf32(v.y));
    w.z = __uint_as_float(f2tf32(v.z));
    w.w = __uint_as_float(f2tf32(v.w));
    *d = w;
}

// ===========================================================================
// tf32 GEMM, cp.async 3-stage: C[M,N] = A[M,K] @ Bw[N,K]^T + bias[N]
// Inputs already tf32-rounded. 128x128 tile, BK=16, 256 thr, warp 64x32.
// ===========================================================================
#define GP 20   // smem pitch in floats
#define GEMM_SMEM (3 * 2 * 128 * GP * 4)   // 61440 B

template<bool ROUND>
__device__ __forceinline__ void tf32_gemm_ca(
    const float* __restrict__ A, const float* __restrict__ Bw,
    const float* __restrict__ bias, float* __restrict__ C,
    int M, int N, int K)
{
    extern __shared__ float gsm[];
    const int tid  = threadIdx.x;
    const int lane = tid & 31;
    const int wid  = tid >> 5;
    const int wm   = wid >> 2;
    const int wn   = wid & 3;
    const int lr   = lane >> 2;
    const int lc   = lane & 3;
    const int mBase = blockIdx.y * 128;
    const int nBase = blockIdx.x * 128;
    const uint32_t smb = smem_u32(gsm);
    constexpr uint32_t STAGE_B = 2u * 128 * GP * 4;

    float acc[4][4][4];
#pragma unroll
    for (int mt = 0; mt < 4; mt++)
#pragma unroll
        for (int nt = 0; nt < 4; nt++)
#pragma unroll
            for (int i = 0; i < 4; i++) acc[mt][nt][i] = 0.0f;

    // Loader geometry: 2 float4 per thread per (A, W) tile
    const float* srcA[2];
    const float* srcW[2];
    uint32_t dA[2], dW[2];
#pragma unroll
    for (int i = 0; i < 2; i++) {
        int f   = tid + i * 256;
        int row = f >> 2;
        int c4  = (f & 3) << 2;
        srcA[i] = A  + (size_t)(mBase + row) * K + c4;
        srcW[i] = Bw + (size_t)(nBase + row) * K + c4;
        dA[i] = (uint32_t)(row * GP + c4) * 4u;
        dW[i] = dA[i] + 128u * GP * 4u;
    }

    const int nIter = K >> 4;
    auto issue = [&](int it, int s) {
        if (it < nIter) {
            uint32_t sb = smb + (uint32_t)s * STAGE_B;
            int kt = it << 4;
#pragma unroll
            for (int i = 0; i < 2; i++) {
                cp16(sb + dA[i], srcA[i] + kt);
                cp16(sb + dW[i], srcW[i] + kt);
            }
        }
        CP_COMMIT();
    };
    issue(0, 0);
    issue(1, 1);

    int s = 0;
    for (int it = 0; it < nIter; it++) {
        CP_WAIT1();
        __syncthreads();
        int s2 = s + 2; if (s2 >= 3) s2 -= 3;
        issue(it + 2, s2);   // safe: barrier above ordered prior compute on s2

        const float* Ab = gsm + (size_t)s * (2 * 128 * GP);
        const float* Wb = Ab + 128 * GP;
#pragma unroll
        for (int k8 = 0; k8 < 16; k8 += 8) {
            uint32_t af[4][4], bf[4][2];
#pragma unroll
            for (int mt = 0; mt < 4; mt++) {
                const float* ap = Ab + (wm * 64 + mt * 16 + lr) * GP + k8 + lc;
                af[mt][0] = __float_as_uint(ap[0]);
                af[mt][1] = __float_as_uint(ap[8 * GP]);
                af[mt][2] = __float_as_uint(ap[4]);
                af[mt][3] = __float_as_uint(ap[8 * GP + 4]);
            }
#pragma unroll
            for (int nt = 0; nt < 4; nt++) {
                const float* bp = Wb + (wn * 32 + nt * 8 + lr) * GP + k8 + lc;
                bf[nt][0] = __float_as_uint(bp[0]);
                bf[nt][1] = __float_as_uint(bp[4]);
            }
#pragma unroll
            for (int mt = 0; mt < 4; mt++)
#pragma unroll
                for (int nt = 0; nt < 4; nt++)
                    mma_tf32(acc[mt][nt][0], acc[mt][nt][1],
                             acc[mt][nt][2], acc[mt][nt][3],
                             af[mt][0], af[mt][1], af[mt][2], af[mt][3],
                             bf[nt][0], bf[nt][1]);
        }
        if (++s == 3) s = 0;
    }

    // Epilogue: bias add; optional tf32 rounding of the output
#pragma unroll
    for (int mt = 0; mt < 4; mt++) {
        const int row0 = mBase + wm * 64 + mt * 16 + lr;
#pragma unroll
        for (int nt = 0; nt < 4; nt++) {
            const int col = nBase + wn * 32 + nt * 8 + 2 * lc;
            const float bx = bias[col];
            const float by = bias[col + 1];
            float v0 = acc[mt][nt][0] + bx, v1 = acc[mt][nt][1] + by;
            float v2 = acc[mt][nt][2] + bx, v3 = acc[mt][nt][3] + by;
            if (ROUND) {
                v0 = __uint_as_float(f2tf32(v0));
                v1 = __uint_as_float(f2tf32(v1));
                v2 = __uint_as_float(f2tf32(v2));
                v3 = __uint_as_float(f2tf32(v3));
            }
            *reinterpret_cast<float2*>(C + (size_t)row0 * N + col) =
                make_float2(v0, v1);
            *reinterpret_cast<float2*>(C + (size_t)(row0 + 8) * N + col) =
                make_float2(v2, v3);
        }
    }
}

__global__ void __launch_bounds__(256)
gemm_qkv_kernel(const float* __restrict__ b1)
{
    tf32_gemm_ca<true>(g_xc, g_w1c, b1, g_qkv, Mrows, E3, En);
}

__global__ void __launch_bounds__(256)
gemm_out_kernel(const float* __restrict__ b2, float* __restrict__ out)
{
    tf32_gemm_ca<false>(g_att, g_w2c, b2, out, Mrows, En, En);
}

// ===========================================================================
// FlashAttention-2, Gaussian-bias windowed, tf32 HMMA, cp.async K/V staging.
// g_qkv is pre-rounded tf32 => no conversions in the loop.
// Grid (Sn/128, Hn, Bn), 256 threads. Window W = 11 t^2 + 64 (mass < 4e-10).
// ===========================================================================
#define BR   128
#define BC   64
#define KVP  68
#define NKB  (Sn / BC)
#define ATTN_SMEM (4 * BC * KVP * 4)   // 69632 B

__global__ void __launch_bounds__(256, 1)
attn_fa2_kernel(const float* __restrict__ t)
{
    extern __shared__ float sm[];
    const uint32_t smb = smem_u32(sm);

    const int tid  = threadIdx.x;
    const int lane = tid & 31;
    const int wid  = tid >> 5;
    const int qt = blockIdx.x, h = blockIdx.y, b = blockIdx.z;
    const int q0 = qt * BR;
    const int qw = q0 + wid * 16;

    const int lr = lane >> 2;
    const int lc = lane & 3;

    const float tt = t[h];
    const float sig = tt * tt;
    const float ninv = -1.0f / (2.0f * sig * sig);

    const float Wf = fminf(11.0f * sig + 64.0f, (float)Sn);
    const int   W  = (int)Wf;
    const int kb_lo = max(0, (q0 - W) >> 6);
    const int kb_hi = min(NKB - 1, (q0 + BR - 1 + W) >> 6);

    // K/V tile issue via cp.async: buf s at smb + s*2*BC*KVP*4 (K then V)
    auto issue_kv = [&](int k0, int buf) {
        const float* srcb = g_qkv + En + (size_t)(b * Sn + k0) * E3 + h * Dn;
        uint32_t sb = smb + (uint32_t)buf * (2u * BC * KVP * 4u);
#pragma unroll
        for (int i = 0; i < 8; i++) {
            int f   = i * 256 + tid;
            int sel = f >> 10;
            int idx = f & 1023;
            int row = idx >> 4;
            int c4  = (idx & 15) << 2;
            const float* src = srcb + (size_t)sel * En + (size_t)row * E3 + c4;
            uint32_t dst = sb + (uint32_t)(sel * BC * KVP + row * KVP + c4) * 4u;
            cp16(dst, src);
        }
    };

    // Q fragments (pre-rounded tf32; *0.125 is an exact pow2 scale)
    uint32_t qa[8][4];
    {
        const float* qp  = g_qkv + (size_t)(b * Sn + qw + lr) * E3 + h * Dn;
        const float* qp8 = qp + 8 * E3;
#pragma unroll
        for (int kt = 0; kt < 8; kt++) {
            qa[kt][0] = __float_as_uint(qp [kt * 8 + lc]     * 0.125f);
            qa[kt][1] = __float_as_uint(qp8[kt * 8 + lc]     * 0.125f);
            qa[kt][2] = __float_as_uint(qp [kt * 8 + lc + 4] * 0.125f);
            qa[kt][3] = __float_as_uint(qp8[kt * 8 + lc + 4] * 0.125f);
        }
    }

    float o[8][4];
#pragma unroll
    for (int nt = 0; nt < 8; nt++)
#pragma unroll
        for (int i = 0; i < 4; i++) o[nt][i] = 0.0f;
    float m0 = -INFINITY, m1 = -INFINITY;
    float l0 = 0.0f, l1 = 0.0f;

    issue_kv(kb_lo * BC, 0);
    CP_COMMIT();

    const int srcA = (lane & ~3) | (lc >> 1);
    const int srcB = srcA + 2;
    const bool oddl = lane & 1;
    const int colb = 2 * lc;

    int cur = 0;
    for (int kb = kb_lo; kb <= kb_hi; kb++) {
        const int k0 = kb * BC;

        CP_WAIT0();
        __syncthreads();
        if (kb + 1 <= kb_hi) issue_kv(k0 + BC, cur ^ 1);
        CP_COMMIT();

        const float* Kc = sm + 2 * cur * BC * KVP;
        const float* Vc = Kc + BC * KVP;

        // ---- S = Q @ K^T ----
        float sc[8][4];
#pragma unroll
        for (int nt = 0; nt < 8; nt++)
#pragma unroll
            for (int i = 0; i < 4; i++) sc[nt][i] = 0.0f;

#pragma unroll
        for (int kt = 0; kt < 8; kt++) {
#pragma unroll
            for (int nt = 0; nt < 8; nt++) {
                const float* kp = Kc + (nt * 8 + lr) * KVP + kt * 8 + lc;
                uint32_t b0 = __float_as_uint(kp[0]);
                uint32_t b1 = __float_as_uint(kp[4]);
                mma_tf32(sc[nt][0], sc[nt][1], sc[nt][2], sc[nt][3],
                         qa[kt][0], qa[kt][1], qa[kt][2], qa[kt][3], b0, b1);
            }
        }

        // ---- Gaussian bias + online softmax ----
        const float d0f = (float)(qw + lr - k0);
        const float d1f = d0f + 8.0f;
        float rmax0 = -INFINITY, rmax1 = -INFINITY;
#pragma unroll
        for (int nt = 0; nt < 8; nt++) {
#pragma unroll
            for (int e = 0; e < 2; e++) {
                float cj = (float)(nt * 8 + colb + e);
                float fd0 = d0f - cj;
                float fd1 = d1f - cj;
                sc[nt][e]     = fmaf(fd0 * fd0, ninv, sc[nt][e]);
                sc[nt][e + 2] = fmaf(fd1 * fd1, ninv, sc[nt][e + 2]);
                rmax0 = fmaxf(rmax0, sc[nt][e]);
                rmax1 = fmaxf(rmax1, sc[nt][e + 2]);
            }
        }
        rmax0 = fmaxf(rmax0, __shfl_xor_sync(0xffffffffu, rmax0, 1));
        rmax0 = fmaxf(rmax0, __shfl_xor_sync(0xffffffffu, rmax0, 2));
        rmax1 = fmaxf(rmax1, __shfl_xor_sync(0xffffffffu, rmax1, 1));
        rmax1 = fmaxf(rmax1, __shfl_xor_sync(0xffffffffu, rmax1, 2));

        const float mn0 = fmaxf(m0, rmax0);
        const float mn1 = fmaxf(m1, rmax1);
        const float corr0 = __expf(m0 - mn0);
        const float corr1 = __expf(m1 - mn1);
        m0 = mn0; m1 = mn1;

        float ls0 = 0.0f, ls1 = 0.0f;
#pragma unroll
        for (int nt = 0; nt < 8; nt++) {
#pragma unroll
            for (int e = 0; e < 2; e++) {
                float p0 = __expf(sc[nt][e]     - mn0);
                float p1 = __expf(sc[nt][e + 2] - mn1);
                float p0t = __uint_as_float(f2tf32(p0));
                float p1t = __uint_as_float(f2tf32(p1));
                sc[nt][e]     = p0t;
                sc[nt][e + 2] = p1t;
                ls0 += p0t;
                ls1 += p1t;
            }
        }
        l0 = l0 * corr0 + ls0;
        l1 = l1 * corr1 + ls1;

        if (__ballot_sync(0xffffffffu, (corr0 != 1.0f) | (corr1 != 1.0f))) {
#pragma unroll
            for (int nt = 0; nt < 8; nt++) {
                o[nt][0] *= corr0; o[nt][1] *= corr0;
                o[nt][2] *= corr1; o[nt][3] *= corr1;
            }
        }

        // ---- O += P @ V ----
#pragma unroll
        for (int kt = 0; kt < 8; kt++) {
            float p0 = sc[kt][0], p1 = sc[kt][1];
            float p2 = sc[kt][2], p3 = sc[kt][3];
            float x0 = __shfl_sync(0xffffffffu, p0, srcA);
            float x1 = __shfl_sync(0xffffffffu, p1, srcA);
            float y0 = __shfl_sync(0xffffffffu, p0, srcB);
            float y1 = __shfl_sync(0xffffffffu, p1, srcB);
            float x2 = __shfl_sync(0xffffffffu, p2, srcA);
            float x3 = __shfl_sync(0xffffffffu, p3, srcA);
            float y2 = __shfl_sync(0xffffffffu, p2, srcB);
            float y3 = __shfl_sync(0xffffffffu, p3, srcB);
            uint32_t a0 = __float_as_uint(oddl ? x1 : x0);
            uint32_t a2 = __float_as_uint(oddl ? y1 : y0);
            uint32_t a1 = __float_as_uint(oddl ? x3 : x2);
            uint32_t a3 = __float_as_uint(oddl ? y3 : y2);

            const float* vp = Vc + (kt * 8 + lc) * KVP + lr;
#pragma unroll
            for (int nt = 0; nt < 8; nt++) {
                uint32_t b0 = __float_as_uint(vp[nt * 8]);
                uint32_t b1 = __float_as_uint(vp[nt * 8 + 4 * KVP]);
                mma_tf32(o[nt][0], o[nt][1], o[nt][2], o[nt][3],
                         a0, a1, a2, a3, b0, b1);
            }
        }

        cur ^= 1;
    }

    // ---- epilogue: normalize, round to tf32 (consumed by out GEMM) ----
    l0 += __shfl_xor_sync(0xffffffffu, l0, 1);
    l0 += __shfl_xor_sync(0xffffffffu, l0, 2);
    l1 += __shfl_xor_sync(0xffffffffu, l1, 1);
    l1 += __shfl_xor_sync(0xffffffffu, l1, 2);
    const float il0 = 1.0f / l0;
    const float il1 = 1.0f / l1;

    float* op0 = g_att + (size_t)(b * Sn + qw + lr) * En + h * Dn + colb;
    float* op1 = op0 + 8 * En;
#pragma unroll
    for (int nt = 0; nt < 8; nt++) {
        float2 r0 = make_float2(
            __uint_as_float(f2tf32(o[nt][0] * il0)),
            __uint_as_float(f2tf32(o[nt][1] * il0)));
        float2 r1 = make_float2(
            __uint_as_float(f2tf32(o[nt][2] * il1)),
            __uint_as_float(f2tf32(o[nt][3] * il1)));
        *reinterpret_cast<float2*>(op0 + nt * 8) = r0;
        *reinterpret_cast<float2*>(op1 + nt * 8) = r1;
    }
}

// ===========================================================================
// Launch
// ===========================================================================
extern "C" void kernel_launch(void* const* d_in, const int* in_sizes, int n_in,
                              void* d_out, int out_size)
{
    const float* x  = (const float*)d_in[0];
    const float* b1 = (const float*)d_in[2];
    const float* w1 = (const float*)d_in[1];
    const float* w2 = (const float*)d_in[3];
    const float* b2 = (const float*)d_in[4];
    const float* t  = (const float*)d_in[5];
    float* out = (float*)d_out;
    (void)in_sizes; (void)n_in; (void)out_size;

    // Pre-round x/w1/w2 to tf32 (5120 blocks covers all three exactly)
    cvt_tf32_kernel<<<(NX4 + NW14 + NW24) / 256, 256>>>(
        (const float4*)x, (const float4*)w1, (const float4*)w2);

    cudaFuncSetAttribute(gemm_qkv_kernel,
                         cudaFuncAttributeMaxDynamicSharedMemorySize, GEMM_SMEM);
    cudaFuncSetAttribute(gemm_out_kernel,
                         cudaFuncAttributeMaxDynamicSharedMemorySize, GEMM_SMEM);
    cudaFuncSetAttribute(attn_fa2_kernel,
                         cudaFuncAttributeMaxDynamicSharedMemorySize, ATTN_SMEM);

    gemm_qkv_kernel<<<dim3(E3 / 128, Mrows / 128), 256, GEMM_SMEM>>>(b1);

    attn_fa2_kernel<<<dim3(Sn / BR, Hn, Bn), 256, ATTN_SMEM>>>(t);

    gemm_out_kernel<<<dim3(En / 128, Mrows / 128), 256, GEMM_SMEM>>>(b2, out);
}

// round 7
// speedup vs baseline: 10.8146x; 1.0696x over previous
#include <cuda_runtime.h>
#include <math.h>
#include <stdint.h>

// Problem constants
#define Bn  2
#define Sn  4096
#define En  512
#define Hn  8
#define Dn  64
#define E3  1536
#define Mrows (Bn * Sn)   // 8192

// Scratch (static device globals -- no allocation at runtime)
__device__ float g_qkv[(size_t)Mrows * E3];   // [B*S, 3E] (tf32-rounded)
__device__ float g_att[(size_t)Mrows * En];   // [B*S, E]  (tf32-rounded)
__device__ float g_xc [(size_t)Mrows * En];   // x  pre-rounded to tf32
__device__ float g_w1c[(size_t)E3 * En];      // w1 pre-rounded
__device__ float g_w2c[(size_t)En * En];      // w2 pre-rounded

// ===========================================================================
// Helpers
// ===========================================================================
__device__ __forceinline__ uint32_t f2tf32(float x) {
    uint32_t r;
    asm("cvt.rna.tf32.f32 %0, %1;" : "=r"(r) : "f"(x));
    return r;
}
__device__ __forceinline__ uint32_t smem_u32(const void* p) {
    uint32_t a;
    asm("{ .reg .u64 t; cvta.to.shared.u64 t, %1; cvt.u32.u64 %0, t; }"
        : "=r"(a) : "l"(p));
    return a;
}
__device__ __forceinline__ void cp16(uint32_t d, const void* s) {
    asm volatile("cp.async.cg.shared.global [%0], [%1], 16;"
                 :: "r"(d), "l"(s));
}
#define CP_COMMIT() asm volatile("cp.async.commit_group;" ::: "memory")
#define CP_WAIT1()  asm volatile("cp.async.wait_group 1;" ::: "memory")
#define CP_WAIT0()  asm volatile("cp.async.wait_group 0;" ::: "memory")

__device__ __forceinline__ void mma_tf32(
    float& c0, float& c1, float& c2, float& c3,
    uint32_t a0, uint32_t a1, uint32_t a2, uint32_t a3,
    uint32_t b0, uint32_t b1)
{
    asm volatile(
        "mma.sync.aligned.m16n8k8.row.col.f32.tf32.tf32.f32 "
        "{%0,%1,%2,%3}, {%4,%5,%6,%7}, {%8,%9}, {%0,%1,%2,%3};"
        : "+f"(c0), "+f"(c1), "+f"(c2), "+f"(c3)
        : "r"(a0), "r"(a1), "r"(a2), "r"(a3), "r"(b0), "r"(b1));
}

// ldmatrix x4: four 8x8 b16 matrices (= four 8x4 tf32 matrices)
__device__ __forceinline__ void ldsm_x4(uint32_t& r0, uint32_t& r1,
                                        uint32_t& r2, uint32_t& r3,
                                        uint32_t addr)
{
    asm volatile("ldmatrix.sync.aligned.m8n8.x4.shared.b16 {%0,%1,%2,%3}, [%4];"
                 : "=r"(r0), "=r"(r1), "=r"(r2), "=r"(r3) : "r"(addr));
}

// ===========================================================================
// Pre-round x, w1, w2 to tf32 (one flat grid: 5120 blocks x 256)
// ===========================================================================
#define NX4  (Mrows * En / 4)      // 1048576
#define NW14 (E3 * En / 4)         // 196608
#define NW24 (En * En / 4)         // 65536

__global__ void __launch_bounds__(256)
cvt_tf32_kernel(const float4* __restrict__ x, const float4* __restrict__ w1,
                const float4* __restrict__ w2)
{
    int i = blockIdx.x * 256 + threadIdx.x;
    const float4* s;
    float4* d;
    if (i < NX4) {
        s = x + i;                       d = (float4*)g_xc + i;
    } else if (i < NX4 + NW14) {
        s = w1 + (i - NX4);              d = (float4*)g_w1c + (i - NX4);
    } else {
        s = w2 + (i - NX4 - NW14);       d = (float4*)g_w2c + (i - NX4 - NW14);
    }
    float4 v = *s;
    float4 w;
    w.x = __uint_as_float(f2tf32(v.x));
    w.y = __uint_as_float(f2tf32(v.y));
    w.z = __uint_as_float(f2tf32(v.z));
    w.w = __uint_as_float(f2tf32(v.w));
    *d = w;
}

// ===========================================================================
// tf32 GEMM, cp.async 3-stage + ldmatrix fragments.
// C[M,N] = A[M,K] @ Bw[N,K]^T + bias[N]; inputs already tf32-rounded.
// 128x128 tile, BK=16, 256 thr, warp 64x32.
// ===========================================================================
#define GP 20   // smem pitch in floats
#define GEMM_SMEM (3 * 2 * 128 * GP * 4)   // 61440 B

template<bool ROUND>
__device__ __forceinline__ void tf32_gemm_ca(
    const float* __restrict__ A, const float* __restrict__ Bw,
    const float* __restrict__ bias, float* __restrict__ C,
    int M, int N, int K)
{
    extern __shared__ float gsm[];
    const int tid  = threadIdx.x;
    const int lane = tid & 31;
    const int wid  = tid >> 5;
    const int wm   = wid >> 2;
    const int wn   = wid & 3;
    const int lr   = lane >> 2;
    const int lc   = lane & 3;
    const int mBase = blockIdx.y * 128;
    const int nBase = blockIdx.x * 128;
    const uint32_t smb = smem_u32(gsm);
    constexpr uint32_t STAGE_B = 2u * 128 * GP * 4;

    float acc[4][4][4];
#pragma unroll
    for (int mt = 0; mt < 4; mt++)
#pragma unroll
        for (int nt = 0; nt < 4; nt++)
#pragma unroll
            for (int i = 0; i < 4; i++) acc[mt][nt][i] = 0.0f;

    // Loader geometry: 2 float4 per thread per (A, W) tile
    const float* srcA[2];
    const float* srcW[2];
    uint32_t dA[2], dW[2];
#pragma unroll
    for (int i = 0; i < 2; i++) {
        int f   = tid + i * 256;
        int row = f >> 2;
        int c4  = (f & 3) << 2;
        srcA[i] = A  + (size_t)(mBase + row) * K + c4;
        srcW[i] = Bw + (size_t)(nBase + row) * K + c4;
        dA[i] = (uint32_t)(row * GP + c4) * 4u;
        dW[i] = dA[i] + 128u * GP * 4u;
    }

    // ldmatrix per-lane addressing (offsets within a stage, bytes)
    // A-frag (m16k8): matrices {m0-7,k0-3},{m8-15,k0-3},{m0-7,k4-7},{m8-15,k4-7}
    const int rowA = (lane & 7) + ((lane >> 3) & 1) * 8;
    const int kofA = (lane >> 4) * 4;
    // B-frag pairs (two n8k8 frags per x4)
    const int rowB = (lane & 7) + ((lane >> 4) & 1) * 8;
    const int kofB = ((lane >> 3) & 1) * 4;
    uint32_t offA[4], offB[2];
#pragma unroll
    for (int mt = 0; mt < 4; mt++)
        offA[mt] = (uint32_t)(((wm * 64 + mt * 16 + rowA) * GP + kofA) * 4);
#pragma unroll
    for (int p = 0; p < 2; p++)
        offB[p] = (uint32_t)((128 * GP + (wn * 32 + p * 16 + rowB) * GP + kofB) * 4);

    const int nIter = K >> 4;
    auto issue = [&](int it, int s) {
        if (it < nIter) {
            uint32_t sb = smb + (uint32_t)s * STAGE_B;
            int kt = it << 4;
#pragma unroll
            for (int i = 0; i < 2; i++) {
                cp16(sb + dA[i], srcA[i] + kt);
                cp16(sb + dW[i], srcW[i] + kt);
            }
        }
        CP_COMMIT();
    };
    issue(0, 0);
    issue(1, 1);

    int s = 0;
    for (int it = 0; it < nIter; it++) {
        CP_WAIT1();
        __syncthreads();
        int s2 = s + 2; if (s2 >= 3) s2 -= 3;
        issue(it + 2, s2);

        const uint32_t stb = smb + (uint32_t)s * STAGE_B;
#pragma unroll
        for (int k8 = 0; k8 < 16; k8 += 8) {
            uint32_t af[4][4], bf[4][2];
#pragma unroll
            for (int mt = 0; mt < 4; mt++)
                ldsm_x4(af[mt][0], af[mt][1], af[mt][2], af[mt][3],
                        stb + offA[mt] + (uint32_t)(k8 * 4));
#pragma unroll
            for (int p = 0; p < 2; p++)
                ldsm_x4(bf[2 * p][0], bf[2 * p][1],
                        bf[2 * p + 1][0], bf[2 * p + 1][1],
                        stb + offB[p] + (uint32_t)(k8 * 4));
#pragma unroll
            for (int mt = 0; mt < 4; mt++)
#pragma unroll
                for (int nt = 0; nt < 4; nt++)
                    mma_tf32(acc[mt][nt][0], acc[mt][nt][1],
                             acc[mt][nt][2], acc[mt][nt][3],
                             af[mt][0], af[mt][1], af[mt][2], af[mt][3],
                             bf[nt][0], bf[nt][1]);
        }
        if (++s == 3) s = 0;
    }

    // Epilogue: bias add; optional tf32 rounding of the output
#pragma unroll
    for (int mt = 0; mt < 4; mt++) {
        const int row0 = mBase + wm * 64 + mt * 16 + lr;
#pragma unroll
        for (int nt = 0; nt < 4; nt++) {
            const int col = nBase + wn * 32 + nt * 8 + 2 * lc;
            const float bx = bias[col];
            const float by = bias[col + 1];
            float v0 = acc[mt][nt][0] + bx, v1 = acc[mt][nt][1] + by;
            float v2 = acc[mt][nt][2] + bx, v3 = acc[mt][nt][3] + by;
            if (ROUND) {
                v0 = __uint_as_float(f2tf32(v0));
                v1 = __uint_as_float(f2tf32(v1));
                v2 = __uint_as_float(f2tf32(v2));
                v3 = __uint_as_float(f2tf32(v3));
            }
            *reinterpret_cast<float2*>(C + (size_t)row0 * N + col) =
                make_float2(v0, v1);
            *reinterpret_cast<float2*>(C + (size_t)(row0 + 8) * N + col) =
                make_float2(v2, v3);
        }
    }
}

__global__ void __launch_bounds__(256)
gemm_qkv_kernel(const float* __restrict__ b1)
{
    tf32_gemm_ca<true>(g_xc, g_w1c, b1, g_qkv, Mrows, E3, En);
}

__global__ void __launch_bounds__(256)
gemm_out_kernel(const float* __restrict__ b2, float* __restrict__ out)
{
    tf32_gemm_ca<false>(g_att, g_w2c, b2, out, Mrows, En, En);
}

// ===========================================================================
// FlashAttention-2, Gaussian-bias windowed, tf32 HMMA, cp.async staging,
// ldmatrix K-fragments. Window W = 11 t^2 + 64 (dropped mass < 4e-10).
// Grid (Sn/128, Hn, Bn), 256 threads.
// ===========================================================================
#define BR   128
#define BC   64
#define KVP  68
#define NKB  (Sn / BC)
#define ATTN_SMEM (4 * BC * KVP * 4)   // 69632 B

__global__ void __launch_bounds__(256, 1)
attn_fa2_kernel(const float* __restrict__ t)
{
    extern __shared__ float sm[];
    const uint32_t smb = smem_u32(sm);

    const int tid  = threadIdx.x;
    const int lane = tid & 31;
    const int wid  = tid >> 5;
    const int qt = blockIdx.x, h = blockIdx.y, b = blockIdx.z;
    const int q0 = qt * BR;
    const int qw = q0 + wid * 16;

    const int lr = lane >> 2;
    const int lc = lane & 3;

    const float tt = t[h];
    const float sig = tt * tt;
    const float ninv = -1.0f / (2.0f * sig * sig);

    const float Wf = fminf(11.0f * sig + 64.0f, (float)Sn);
    const int   W  = (int)Wf;
    const int kb_lo = max(0, (q0 - W) >> 6);
    const int kb_hi = min(NKB - 1, (q0 + BR - 1 + W) >> 6);

    // K/V tile issue via cp.async: buf s at smb + s*2*BC*KVP*4 (K then V)
    auto issue_kv = [&](int k0, int buf) {
        const float* srcb = g_qkv + En + (size_t)(b * Sn + k0) * E3 + h * Dn;
        uint32_t sb = smb + (uint32_t)buf * (2u * BC * KVP * 4u);
#pragma unroll
        for (int i = 0; i < 8; i++) {
            int f   = i * 256 + tid;
            int sel = f >> 10;
            int idx = f & 1023;
            int row = idx >> 4;
            int c4  = (idx & 15) << 2;
            const float* src = srcb + (size_t)sel * En + (size_t)row * E3 + c4;
            uint32_t dst = sb + (uint32_t)(sel * BC * KVP + row * KVP + c4) * 4u;
            cp16(dst, src);
        }
    };

    // ldmatrix per-lane offsets for K B-fragments (pairs of n8k8)
    const int rowB = (lane & 7) + ((lane >> 4) & 1) * 8;
    const int kofB = ((lane >> 3) & 1) * 4;
    uint32_t offK[4];
#pragma unroll
    for (int p = 0; p < 4; p++)
        offK[p] = (uint32_t)(((p * 16 + rowB) * KVP + kofB) * 4);

    // Q fragments (pre-rounded tf32; *0.125 is an exact pow2 scale)
    uint32_t qa[8][4];
    {
        const float* qp  = g_qkv + (size_t)(b * Sn + qw + lr) * E3 + h * Dn;
        const float* qp8 = qp + 8 * E3;
#pragma unroll
        for (int kt = 0; kt < 8; kt++) {
            qa[kt][0] = __float_as_uint(qp [kt * 8 + lc]     * 0.125f);
            qa[kt][1] = __float_as_uint(qp8[kt * 8 + lc]     * 0.125f);
            qa[kt][2] = __float_as_uint(qp [kt * 8 + lc + 4] * 0.125f);
            qa[kt][3] = __float_as_uint(qp8[kt * 8 + lc + 4] * 0.125f);
        }
    }

    float o[8][4];
#pragma unroll
    for (int nt = 0; nt < 8; nt++)
#pragma unroll
        for (int i = 0; i < 4; i++) o[nt][i] = 0.0f;
    float m0 = -INFINITY, m1 = -INFINITY;
    float l0 = 0.0f, l1 = 0.0f;

    issue_kv(kb_lo * BC, 0);
    CP_COMMIT();

    const int srcA = (lane & ~3) | (lc >> 1);
    const int srcB = srcA + 2;
    const bool oddl = lane & 1;
    const int colb = 2 * lc;

    int cur = 0;
    for (int kb = kb_lo; kb <= kb_hi; kb++) {
        const int k0 = kb * BC;

        CP_WAIT0();
        __syncthreads();
        if (kb + 1 <= kb_hi) issue_kv(k0 + BC, cur ^ 1);
        CP_COMMIT();

        const uint32_t Kb = smb + (uint32_t)cur * (2u * BC * KVP * 4u);
        const float* Vc = sm + (2 * cur + 1) * BC * KVP;

        // ---- S = Q @ K^T (ldmatrix B-fragments) ----
        float sc[8][4];
#pragma unroll
        for (int nt = 0; nt < 8; nt++)
#pragma unroll
            for (int i = 0; i < 4; i++) sc[nt][i] = 0.0f;

#pragma unroll
        for (int kt = 0; kt < 8; kt++) {
            uint32_t kf[8][2];
#pragma unroll
            for (int p = 0; p < 4; p++)
                ldsm_x4(kf[2 * p][0], kf[2 * p][1],
                        kf[2 * p + 1][0], kf[2 * p + 1][1],
                        Kb + offK[p] + (uint32_t)(kt * 32));
#pragma unroll
            for (int nt = 0; nt < 8; nt++)
                mma_tf32(sc[nt][0], sc[nt][1], sc[nt][2], sc[nt][3],
                         qa[kt][0], qa[kt][1], qa[kt][2], qa[kt][3],
                         kf[nt][0], kf[nt][1]);
        }

        // ---- Gaussian bias + online softmax ----
        const float d0f = (float)(qw + lr - k0);
        const float d1f = d0f + 8.0f;
        float rmax0 = -INFINITY, rmax1 = -INFINITY;
#pragma unroll
        for (int nt = 0; nt < 8; nt++) {
#pragma unroll
            for (int e = 0; e < 2; e++) {
                float cj = (float)(nt * 8 + colb + e);
                float fd0 = d0f - cj;
                float fd1 = d1f - cj;
                sc[nt][e]     = fmaf(fd0 * fd0, ninv, sc[nt][e]);
                sc[nt][e + 2] = fmaf(fd1 * fd1, ninv, sc[nt][e + 2]);
                rmax0 = fmaxf(rmax0, sc[nt][e]);
                rmax1 = fmaxf(rmax1, sc[nt][e + 2]);
            }
        }
        rmax0 = fmaxf(rmax0, __shfl_xor_sync(0xffffffffu, rmax0, 1));
        rmax0 = fmaxf(rmax0, __shfl_xor_sync(0xffffffffu, rmax0, 2));
        rmax1 = fmaxf(rmax1, __shfl_xor_sync(0xffffffffu, rmax1, 1));
        rmax1 = fmaxf(rmax1, __shfl_xor_sync(0xffffffffu, rmax1, 2));

        const float mn0 = fmaxf(m0, rmax0);
        const float mn1 = fmaxf(m1, rmax1);
        const float corr0 = __expf(m0 - mn0);
        const float corr1 = __expf(m1 - mn1);
        m0 = mn0; m1 = mn1;

        float ls0 = 0.0f, ls1 = 0.0f;
#pragma unroll
        for (int nt = 0; nt < 8; nt++) {
#pragma unroll
            for (int e = 0; e < 2; e++) {
                float p0 = __expf(sc[nt][e]     - mn0);
                float p1 = __expf(sc[nt][e + 2] - mn1);
                float p0t = __uint_as_float(f2tf32(p0));
                float p1t = __uint_as_float(f2tf32(p1));
                sc[nt][e]     = p0t;
                sc[nt][e + 2] = p1t;
                ls0 += p0t;
                ls1 += p1t;
            }
        }
        l0 = l0 * corr0 + ls0;
        l1 = l1 * corr1 + ls1;

        if (__ballot_sync(0xffffffffu, (corr0 != 1.0f) | (corr1 != 1.0f))) {
#pragma unroll
            for (int nt = 0; nt < 8; nt++) {
                o[nt][0] *= corr0; o[nt][1] *= corr0;
                o[nt][2] *= corr1; o[nt][3] *= corr1;
            }
        }

        // ---- O += P @ V ----
#pragma unroll
        for (int kt = 0; kt < 8; kt++) {
            float p0 = sc[kt][0], p1 = sc[kt][1];
            float p2 = sc[kt][2], p3 = sc[kt][3];
            float x0 = __shfl_sync(0xffffffffu, p0, srcA);
            float x1 = __shfl_sync(0xffffffffu, p1, srcA);
            float y0 = __shfl_sync(0xffffffffu, p0, srcB);
            float y1 = __shfl_sync(0xffffffffu, p1, srcB);
            float x2 = __shfl_sync(0xffffffffu, p2, srcA);
            float x3 = __shfl_sync(0xffffffffu, p3, srcA);
            float y2 = __shfl_sync(0xffffffffu, p2, srcB);
            float y3 = __shfl_sync(0xffffffffu, p3, srcB);
            uint32_t a0 = __float_as_uint(oddl ? x1 : x0);
            uint32_t a2 = __float_as_uint(oddl ? y1 : y0);
            uint32_t a1 = __float_as_uint(oddl ? x3 : x2);
            uint32_t a3 = __float_as_uint(oddl ? y3 : y2);

            const float* vp = Vc + (kt * 8 + lc) * KVP + lr;
#pragma unroll
            for (int nt = 0; nt < 8; nt++) {
                uint32_t b0 = __float_as_uint(vp[nt * 8]);
                uint32_t b1 = __float_as_uint(vp[nt * 8 + 4 * KVP]);
                mma_tf32(o[nt][0], o[nt][1], o[nt][2], o[nt][3],
                         a0, a1, a2, a3, b0, b1);
            }
        }

        cur ^= 1;
    }

    // ---- epilogue: normalize, round to tf32 (consumed by out GEMM) ----
    l0 += __shfl_xor_sync(0xffffffffu, l0, 1);
    l0 += __shfl_xor_sync(0xffffffffu, l0, 2);
    l1 += __shfl_xor_sync(0xffffffffu, l1, 1);
    l1 += __shfl_xor_sync(0xffffffffu, l1, 2);
    const float il0 = 1.0f / l0;
    const float il1 = 1.0f / l1;

    float* op0 = g_att + (size_t)(b * Sn + qw + lr) * En + h * Dn + colb;
    float* op1 = op0 + 8 * En;
#pragma unroll
    for (int nt = 0; nt < 8; nt++) {
        float2 r0 = make_float2(
            __uint_as_float(f2tf32(o[nt][0] * il0)),
            __uint_as_float(f2tf32(o[nt][1] * il0)));
        float2 r1 = make_float2(
            __uint_as_float(f2tf32(o[nt][2] * il1)),
            __uint_as_float(f2tf32(o[nt][3] * il1)));
        *reinterpret_cast<float2*>(op0 + nt * 8) = r0;
        *reinterpret_cast<float2*>(op1 + nt * 8) = r1;
    }
}

// ===========================================================================
// Launch
// ===========================================================================
extern "C" void kernel_launch(void* const* d_in, const int* in_sizes, int n_in,
                              void* d_out, int out_size)
{
    const float* x  = (const float*)d_in[0];
    const float* w1 = (const float*)d_in[1];
    const float* b1 = (const float*)d_in[2];
    const float* w2 = (const float*)d_in[3];
    const float* b2 = (const float*)d_in[4];
    const float* t  = (const float*)d_in[5];
    float* out = (float*)d_out;
    (void)in_sizes; (void)n_in; (void)out_size;

    cvt_tf32_kernel<<<(NX4 + NW14 + NW24) / 256, 256>>>(
        (const float4*)x, (const float4*)w1, (const float4*)w2);

    cudaFuncSetAttribute(gemm_qkv_kernel,
                         cudaFuncAttributeMaxDynamicSharedMemorySize, GEMM_SMEM);
    cudaFuncSetAttribute(gemm_out_kernel,
                         cudaFuncAttributeMaxDynamicSharedMemorySize, GEMM_SMEM);
    cudaFuncSetAttribute(attn_fa2_kernel,
                         cudaFuncAttributeMaxDynamicSharedMemorySize, ATTN_SMEM);

    gemm_qkv_kernel<<<dim3(E3 / 128, Mrows / 128), 256, GEMM_SMEM>>>(b1);

    attn_fa2_kernel<<<dim3(Sn / BR, Hn, Bn), 256, ATTN_SMEM>>>(t);

    gemm_out_kernel<<<dim3(En / 128, Mrows / 128), 256, GEMM_SMEM>>>(b2, out);
}

// round 8
// speedup vs baseline: 11.8960x; 1.1000x over previous
#include <cuda_runtime.h>
#include <math.h>
#include <stdint.h>

// Problem constants
#define Bn  2
#define Sn  4096
#define En  512
#define Hn  8
#define Dn  64
#define E3  1536
#define Mrows (Bn * Sn)   // 8192

// Scratch (static device globals -- no allocation at runtime)
__device__ float g_qkv[(size_t)Mrows * E3];   // [B*S, 3E] (tf32-rounded)
__device__ float g_att[(size_t)Mrows * En];   // [B*S, E]  (tf32-rounded)
__device__ float g_xc [(size_t)Mrows * En];   // x  pre-rounded to tf32
__device__ float g_w1c[(size_t)E3 * En];      // w1 pre-rounded
__device__ float g_w2c[(size_t)En * En];      // w2 pre-rounded

// ===========================================================================
// Helpers
// ===========================================================================
__device__ __forceinline__ uint32_t f2tf32(float x) {
    uint32_t r;
    asm("cvt.rna.tf32.f32 %0, %1;" : "=r"(r) : "f"(x));
    return r;
}
__device__ __forceinline__ uint32_t smem_u32(const void* p) {
    uint32_t a;
    asm("{ .reg .u64 t; cvta.to.shared.u64 t, %1; cvt.u32.u64 %0, t; }"
        : "=r"(a) : "l"(p));
    return a;
}
__device__ __forceinline__ void cp16(uint32_t d, const void* s) {
    asm volatile("cp.async.cg.shared.global [%0], [%1], 16;"
                 :: "r"(d), "l"(s));
}
#define CP_COMMIT() asm volatile("cp.async.commit_group;" ::: "memory")
#define CP_WAIT1()  asm volatile("cp.async.wait_group 1;" ::: "memory")
#define CP_WAIT0()  asm volatile("cp.async.wait_group 0;" ::: "memory")

__device__ __forceinline__ void mma_tf32(
    float& c0, float& c1, float& c2, float& c3,
    uint32_t a0, uint32_t a1, uint32_t a2, uint32_t a3,
    uint32_t b0, uint32_t b1)
{
    asm volatile(
        "mma.sync.aligned.m16n8k8.row.col.f32.tf32.tf32.f32 "
        "{%0,%1,%2,%3}, {%4,%5,%6,%7}, {%8,%9}, {%0,%1,%2,%3};"
        : "+f"(c0), "+f"(c1), "+f"(c2), "+f"(c3)
        : "r"(a0), "r"(a1), "r"(a2), "r"(a3), "r"(b0), "r"(b1));
}

// ldmatrix x4: four 8x8 b16 matrices (= four 8x4 tf32 matrices)
__device__ __forceinline__ void ldsm_x4(uint32_t& r0, uint32_t& r1,
                                        uint32_t& r2, uint32_t& r3,
                                        uint32_t addr)
{
    asm volatile("ldmatrix.sync.aligned.m8n8.x4.shared.b16 {%0,%1,%2,%3}, [%4];"
                 : "=r"(r0), "=r"(r1), "=r"(r2), "=r"(r3) : "r"(addr));
}

// ===========================================================================
// Pre-round x, w1, w2 to tf32 (one flat grid: 5120 blocks x 256)
// ===========================================================================
#define NX4  (Mrows * En / 4)      // 1048576
#define NW14 (E3 * En / 4)         // 196608
#define NW24 (En * En / 4)         // 65536

__global__ void __launch_bounds__(256)
cvt_tf32_kernel(const float4* __restrict__ x, const float4* __restrict__ w1,
                const float4* __restrict__ w2)
{
    int i = blockIdx.x * 256 + threadIdx.x;
    const float4* s;
    float4* d;
    if (i < NX4) {
        s = x + i;                       d = (float4*)g_xc + i;
    } else if (i < NX4 + NW14) {
        s = w1 + (i - NX4);              d = (float4*)g_w1c + (i - NX4);
    } else {
        s = w2 + (i - NX4 - NW14);       d = (float4*)g_w2c + (i - NX4 - NW14);
    }
    float4 v = *s;
    float4 w;
    w.x = __uint_as_float(f2tf32(v.x));
    w.y = __uint_as_float(f2tf32(v.y));
    w.z = __uint_as_float(f2tf32(v.z));
    w.w = __uint_as_float(f2tf32(v.w));
    *d = w;
}

// ===========================================================================
// tf32 GEMM, cp.async 3-stage, BK=32, ldmatrix fragments.
// C[M,N] = A[M,K] @ Bw[N,K]^T + bias[N]; inputs already tf32-rounded.
// 128x128 tile, 256 thr (8 warps 2x4), warp 64x32. 16 barriers per K=512.
// ===========================================================================
#define GP 36   // smem pitch in floats (32 + 4)
#define GEMM_SMEM (3 * 2 * 128 * GP * 4)   // 110592 B

template<bool ROUND>
__device__ __forceinline__ void tf32_gemm_ca(
    const float* __restrict__ A, const float* __restrict__ Bw,
    const float* __restrict__ bias, float* __restrict__ C,
    int M, int N, int K)
{
    extern __shared__ float gsm[];
    const int tid  = threadIdx.x;
    const int lane = tid & 31;
    const int wid  = tid >> 5;
    const int wm   = wid >> 2;
    const int wn   = wid & 3;
    const int lr   = lane >> 2;
    const int lc   = lane & 3;
    const int mBase = blockIdx.y * 128;
    const int nBase = blockIdx.x * 128;
    const uint32_t smb = smem_u32(gsm);
    constexpr uint32_t STAGE_B = 2u * 128 * GP * 4;   // 36864

    float acc[4][4][4];
#pragma unroll
    for (int mt = 0; mt < 4; mt++)
#pragma unroll
        for (int nt = 0; nt < 4; nt++)
#pragma unroll
            for (int i = 0; i < 4; i++) acc[mt][nt][i] = 0.0f;

    // Loader geometry: 4 float4 per thread per (A, W) tile (128 rows x 32)
    const float* srcA[4];
    const float* srcW[4];
    uint32_t dA[4], dW[4];
#pragma unroll
    for (int i = 0; i < 4; i++) {
        int f   = tid + i * 256;           // 0..1023
        int row = f >> 3;                  // 0..127
        int c4  = (f & 7) << 2;            // 0..28
        srcA[i] = A  + (size_t)(mBase + row) * K + c4;
        srcW[i] = Bw + (size_t)(nBase + row) * K + c4;
        dA[i] = (uint32_t)(row * GP + c4) * 4u;
        dW[i] = dA[i] + 128u * GP * 4u;
    }

    // ldmatrix per-lane addressing (offsets within a stage, bytes)
    const int rowA = (lane & 7) + ((lane >> 3) & 1) * 8;
    const int kofA = (lane >> 4) * 4;
    const int rowB = (lane & 7) + ((lane >> 4) & 1) * 8;
    const int kofB = ((lane >> 3) & 1) * 4;
    uint32_t offA[4], offB[2];
#pragma unroll
    for (int mt = 0; mt < 4; mt++)
        offA[mt] = (uint32_t)(((wm * 64 + mt * 16 + rowA) * GP + kofA) * 4);
#pragma unroll
    for (int p = 0; p < 2; p++)
        offB[p] = (uint32_t)((128 * GP + (wn * 32 + p * 16 + rowB) * GP + kofB) * 4);

    const int nIter = K >> 5;
    auto issue = [&](int it, int s) {
        if (it < nIter) {
            uint32_t sb = smb + (uint32_t)s * STAGE_B;
            int kt = it << 5;
#pragma unroll
            for (int i = 0; i < 4; i++) {
                cp16(sb + dA[i], srcA[i] + kt);
                cp16(sb + dW[i], srcW[i] + kt);
            }
        }
        CP_COMMIT();
    };
    issue(0, 0);
    issue(1, 1);

    int s = 0;
    for (int it = 0; it < nIter; it++) {
        CP_WAIT1();
        __syncthreads();
        int s2 = s + 2; if (s2 >= 3) s2 -= 3;
        issue(it + 2, s2);

        const uint32_t stb = smb + (uint32_t)s * STAGE_B;
#pragma unroll
        for (int k8 = 0; k8 < 32; k8 += 8) {
            uint32_t af[4][4], bf[4][2];
#pragma unroll
            for (int mt = 0; mt < 4; mt++)
                ldsm_x4(af[mt][0], af[mt][1], af[mt][2], af[mt][3],
                        stb + offA[mt] + (uint32_t)(k8 * 4));
#pragma unroll
            for (int p = 0; p < 2; p++)
                ldsm_x4(bf[2 * p][0], bf[2 * p][1],
                        bf[2 * p + 1][0], bf[2 * p + 1][1],
                        stb + offB[p] + (uint32_t)(k8 * 4));
#pragma unroll
            for (int mt = 0; mt < 4; mt++)
#pragma unroll
                for (int nt = 0; nt < 4; nt++)
                    mma_tf32(acc[mt][nt][0], acc[mt][nt][1],
                             acc[mt][nt][2], acc[mt][nt][3],
                             af[mt][0], af[mt][1], af[mt][2], af[mt][3],
                             bf[nt][0], bf[nt][1]);
        }
        if (++s == 3) s = 0;
    }

    // Epilogue: bias add; optional tf32 rounding of the output
#pragma unroll
    for (int mt = 0; mt < 4; mt++) {
        const int row0 = mBase + wm * 64 + mt * 16 + lr;
#pragma unroll
        for (int nt = 0; nt < 4; nt++) {
            const int col = nBase + wn * 32 + nt * 8 + 2 * lc;
            const float bx = bias[col];
            const float by = bias[col + 1];
            float v0 = acc[mt][nt][0] + bx, v1 = acc[mt][nt][1] + by;
            float v2 = acc[mt][nt][2] + bx, v3 = acc[mt][nt][3] + by;
            if (ROUND) {
                v0 = __uint_as_float(f2tf32(v0));
                v1 = __uint_as_float(f2tf32(v1));
                v2 = __uint_as_float(f2tf32(v2));
                v3 = __uint_as_float(f2tf32(v3));
            }
            *reinterpret_cast<float2*>(C + (size_t)row0 * N + col) =
                make_float2(v0, v1);
            *reinterpret_cast<float2*>(C + (size_t)(row0 + 8) * N + col) =
                make_float2(v2, v3);
        }
    }
}

__global__ void __launch_bounds__(256, 2)
gemm_qkv_kernel(const float* __restrict__ b1)
{
    tf32_gemm_ca<true>(g_xc, g_w1c, b1, g_qkv, Mrows, E3, En);
}

__global__ void __launch_bounds__(256, 2)
gemm_out_kernel(const float* __restrict__ b2, float* __restrict__ out)
{
    tf32_gemm_ca<false>(g_att, g_w2c, b2, out, Mrows, En, En);
}

// ===========================================================================
// FlashAttention-2, Gaussian-bias windowed, tf32 HMMA, cp.async staging,
// ldmatrix K-fragments. Window W = 11 t^2 + 64 (dropped mass < 4e-10).
// Grid (Sn/128, Hn, Bn), 256 threads.  (unchanged from R7)
// ===========================================================================
#define BR   128
#define BC   64
#define KVP  68
#define NKB  (Sn / BC)
#define ATTN_SMEM (4 * BC * KVP * 4)   // 69632 B

__global__ void __launch_bounds__(256, 1)
attn_fa2_kernel(const float* __restrict__ t)
{
    extern __shared__ float sm[];
    const uint32_t smb = smem_u32(sm);

    const int tid  = threadIdx.x;
    const int lane = tid & 31;
    const int wid  = tid >> 5;
    const int qt = blockIdx.x, h = blockIdx.y, b = blockIdx.z;
    const int q0 = qt * BR;
    const int qw = q0 + wid * 16;

    const int lr = lane >> 2;
    const int lc = lane & 3;

    const float tt = t[h];
    const float sig = tt * tt;
    const float ninv = -1.0f / (2.0f * sig * sig);

    const float Wf = fminf(11.0f * sig + 64.0f, (float)Sn);
    const int   W  = (int)Wf;
    const int kb_lo = max(0, (q0 - W) >> 6);
    const int kb_hi = min(NKB - 1, (q0 + BR - 1 + W) >> 6);

    auto issue_kv = [&](int k0, int buf) {
        const float* srcb = g_qkv + En + (size_t)(b * Sn + k0) * E3 + h * Dn;
        uint32_t sb = smb + (uint32_t)buf * (2u * BC * KVP * 4u);
#pragma unroll
        for (int i = 0; i < 8; i++) {
            int f   = i * 256 + tid;
            int sel = f >> 10;
            int idx = f & 1023;
            int row = idx >> 4;
            int c4  = (idx & 15) << 2;
            const float* src = srcb + (size_t)sel * En + (size_t)row * E3 + c4;
            uint32_t dst = sb + (uint32_t)(sel * BC * KVP + row * KVP + c4) * 4u;
            cp16(dst, src);
        }
    };

    const int rowB = (lane & 7) + ((lane >> 4) & 1) * 8;
    const int kofB = ((lane >> 3) & 1) * 4;
    uint32_t offK[4];
#pragma unroll
    for (int p = 0; p < 4; p++)
        offK[p] = (uint32_t)(((p * 16 + rowB) * KVP + kofB) * 4);

    uint32_t qa[8][4];
    {
        const float* qp  = g_qkv + (size_t)(b * Sn + qw + lr) * E3 + h * Dn;
        const float* qp8 = qp + 8 * E3;
#pragma unroll
        for (int kt = 0; kt < 8; kt++) {
            qa[kt][0] = __float_as_uint(qp [kt * 8 + lc]     * 0.125f);
            qa[kt][1] = __float_as_uint(qp8[kt * 8 + lc]     * 0.125f);
            qa[kt][2] = __float_as_uint(qp [kt * 8 + lc + 4] * 0.125f);
            qa[kt][3] = __float_as_uint(qp8[kt * 8 + lc + 4] * 0.125f);
        }
    }

    float o[8][4];
#pragma unroll
    for (int nt = 0; nt < 8; nt++)
#pragma unroll
        for (int i = 0; i < 4; i++) o[nt][i] = 0.0f;
    float m0 = -INFINITY, m1 = -INFINITY;
    float l0 = 0.0f, l1 = 0.0f;

    issue_kv(kb_lo * BC, 0);
    CP_COMMIT();

    const int srcA = (lane & ~3) | (lc >> 1);
    const int srcB = srcA + 2;
    const bool oddl = lane & 1;
    const int colb = 2 * lc;

    int cur = 0;
    for (int kb = kb_lo; kb <= kb_hi; kb++) {
        const int k0 = kb * BC;

        CP_WAIT0();
        __syncthreads();
        if (kb + 1 <= kb_hi) issue_kv(k0 + BC, cur ^ 1);
        CP_COMMIT();

        const uint32_t Kb = smb + (uint32_t)cur * (2u * BC * KVP * 4u);
        const float* Vc = sm + (2 * cur + 1) * BC * KVP;

        float sc[8][4];
#pragma unroll
        for (int nt = 0; nt < 8; nt++)
#pragma unroll
            for (int i = 0; i < 4; i++) sc[nt][i] = 0.0f;

#pragma unroll
        for (int kt = 0; kt < 8; kt++) {
            uint32_t kf[8][2];
#pragma unroll
            for (int p = 0; p < 4; p++)
                ldsm_x4(kf[2 * p][0], kf[2 * p][1],
                        kf[2 * p + 1][0], kf[2 * p + 1][1],
                        Kb + offK[p] + (uint32_t)(kt * 32));
#pragma unroll
            for (int nt = 0; nt < 8; nt++)
                mma_tf32(sc[nt][0], sc[nt][1], sc[nt][2], sc[nt][3],
                         qa[kt][0], qa[kt][1], qa[kt][2], qa[kt][3],
                         kf[nt][0], kf[nt][1]);
        }

        const float d0f = (float)(qw + lr - k0);
        const float d1f = d0f + 8.0f;
        float rmax0 = -INFINITY, rmax1 = -INFINITY;
#pragma unroll
        for (int nt = 0; nt < 8; nt++) {
#pragma unroll
            for (int e = 0; e < 2; e++) {
                float cj = (float)(nt * 8 + colb + e);
                float fd0 = d0f - cj;
                float fd1 = d1f - cj;
                sc[nt][e]     = fmaf(fd0 * fd0, ninv, sc[nt][e]);
                sc[nt][e + 2] = fmaf(fd1 * fd1, ninv, sc[nt][e + 2]);
                rmax0 = fmaxf(rmax0, sc[nt][e]);
                rmax1 = fmaxf(rmax1, sc[nt][e + 2]);
            }
        }
        rmax0 = fmaxf(rmax0, __shfl_xor_sync(0xffffffffu, rmax0, 1));
        rmax0 = fmaxf(rmax0, __shfl_xor_sync(0xffffffffu, rmax0, 2));
        rmax1 = fmaxf(rmax1, __shfl_xor_sync(0xffffffffu, rmax1, 1));
        rmax1 = fmaxf(rmax1, __shfl_xor_sync(0xffffffffu, rmax1, 2));

        const float mn0 = fmaxf(m0, rmax0);
        const float mn1 = fmaxf(m1, rmax1);
        const float corr0 = __expf(m0 - mn0);
        const float corr1 = __expf(m1 - mn1);
        m0 = mn0; m1 = mn1;

        float ls0 = 0.0f, ls1 = 0.0f;
#pragma unroll
        for (int nt = 0; nt < 8; nt++) {
#pragma unroll
            for (int e = 0; e < 2; e++) {
                float p0 = __expf(sc[nt][e]     - mn0);
                float p1 = __expf(sc[nt][e + 2] - mn1);
                float p0t = __uint_as_float(f2tf32(p0));
                float p1t = __uint_as_float(f2tf32(p1));
                sc[nt][e]     = p0t;
                sc[nt][e + 2] = p1t;
                ls0 += p0t;
                ls1 += p1t;
            }
        }
        l0 = l0 * corr0 + ls0;
        l1 = l1 * corr1 + ls1;

        if (__ballot_sync(0xffffffffu, (corr0 != 1.0f) | (corr1 != 1.0f))) {
#pragma unroll
            for (int nt = 0; nt < 8; nt++) {
                o[nt][0] *= corr0; o[nt][1] *= corr0;
                o[nt][2] *= corr1; o[nt][3] *= corr1;
            }
        }

#pragma unroll
        for (int kt = 0; kt < 8; kt++) {
            float p0 = sc[kt][0], p1 = sc[kt][1];
            float p2 = sc[kt][2], p3 = sc[kt][3];
            float x0 = __shfl_sync(0xffffffffu, p0, srcA);
            float x1 = __shfl_sync(0xffffffffu, p1, srcA);
            float y0 = __shfl_sync(0xffffffffu, p0, srcB);
            float y1 = __shfl_sync(0xffffffffu, p1, srcB);
            float x2 = __shfl_sync(0xffffffffu, p2, srcA);
            float x3 = __shfl_sync(0xffffffffu, p3, srcA);
            float y2 = __shfl_sync(0xffffffffu, p2, srcB);
            float y3 = __shfl_sync(0xffffffffu, p3, srcB);
            uint32_t a0 = __float_as_uint(oddl ? x1 : x0);
            uint32_t a2 = __float_as_uint(oddl ? y1 : y0);
            uint32_t a1 = __float_as_uint(oddl ? x3 : x2);
            uint32_t a3 = __float_as_uint(oddl ? y3 : y2);

            const float* vp = Vc + (kt * 8 + lc) * KVP + lr;
#pragma unroll
            for (int nt = 0; nt < 8; nt++) {
                uint32_t b0 = __float_as_uint(vp[nt * 8]);
                uint32_t b1 = __float_as_uint(vp[nt * 8 + 4 * KVP]);
                mma_tf32(o[nt][0], o[nt][1], o[nt][2], o[nt][3],
                         a0, a1, a2, a3, b0, b1);
            }
        }

        cur ^= 1;
    }

    l0 += __shfl_xor_sync(0xffffffffu, l0, 1);
    l0 += __shfl_xor_sync(0xffffffffu, l0, 2);
    l1 += __shfl_xor_sync(0xffffffffu, l1, 1);
    l1 += __shfl_xor_sync(0xffffffffu, l1, 2);
    const float il0 = 1.0f / l0;
    const float il1 = 1.0f / l1;

    float* op0 = g_att + (size_t)(b * Sn + qw + lr) * En + h * Dn + colb;
    float* op1 = op0 + 8 * En;
#pragma unroll
    for (int nt = 0; nt < 8; nt++) {
        float2 r0 = make_float2(
            __uint_as_float(f2tf32(o[nt][0] * il0)),
            __uint_as_float(f2tf32(o[nt][1] * il0)));
        float2 r1 = make_float2(
            __uint_as_float(f2tf32(o[nt][2] * il1)),
            __uint_as_float(f2tf32(o[nt][3] * il1)));
        *reinterpret_cast<float2*>(op0 + nt * 8) = r0;
        *reinterpret_cast<float2*>(op1 + nt * 8) = r1;
    }
}

// ===========================================================================
// Launch
// ===========================================================================
extern "C" void kernel_launch(void* const* d_in, const int* in_sizes, int n_in,
                              void* d_out, int out_size)
{
    const float* x  = (const float*)d_in[0];
    const float* w1 = (const float*)d_in[1];
    const float* b1 = (const float*)d_in[2];
    const float* w2 = (const float*)d_in[3];
    const float* b2 = (const float*)d_in[4];
    const float* t  = (const float*)d_in[5];
    float* out = (float*)d_out;
    (void)in_sizes; (void)n_in; (void)out_size;

    cvt_tf32_kernel<<<(NX4 + NW14 + NW24) / 256, 256>>>(
        (const float4*)x, (const float4*)w1, (const float4*)w2);

    cudaFuncSetAttribute(gemm_qkv_kernel,
                         cudaFuncAttributeMaxDynamicSharedMemorySize, GEMM_SMEM);
    cudaFuncSetAttribute(gemm_out_kernel,
                         cudaFuncAttributeMaxDynamicSharedMemorySize, GEMM_SMEM);
    cudaFuncSetAttribute(attn_fa2_kernel,
                         cudaFuncAttributeMaxDynamicSharedMemorySize, ATTN_SMEM);

    gemm_qkv_kernel<<<dim3(E3 / 128, Mrows / 128), 256, GEMM_SMEM>>>(b1);

    attn_fa2_kernel<<<dim3(Sn / BR, Hn, Bn), 256, ATTN_SMEM>>>(t);

    gemm_out_kernel<<<dim3(En / 128, Mrows / 128), 256, GEMM_SMEM>>>(b2, out);
}

// round 9
// speedup vs baseline: 13.5239x; 1.1368x over previous
#include <cuda_runtime.h>
#include <math.h>
#include <stdint.h>

// Problem constants
#define Bn  2
#define Sn  4096
#define En  512
#define Hn  8
#define Dn  64
#define E3  1536
#define Mrows (Bn * Sn)   // 8192

// Scratch (static device globals -- no allocation at runtime)
__device__ float g_qkv[(size_t)Mrows * E3];   // [B*S, 3E] (tf32-rounded)
__device__ float g_att[(size_t)Mrows * En];   // [B*S, E]  (tf32-rounded)
__device__ float g_xc [(size_t)Mrows * En];   // x  pre-rounded to tf32
__device__ float g_w1c[(size_t)E3 * En];      // w1 pre-rounded
__device__ float g_w2c[(size_t)En * En];      // w2 pre-rounded

// ===========================================================================
// Helpers
// ===========================================================================
__device__ __forceinline__ uint32_t f2tf32(float x) {
    uint32_t r;
    asm("cvt.rna.tf32.f32 %0, %1;" : "=r"(r) : "f"(x));
    return r;
}
__device__ __forceinline__ uint32_t smem_u32(const void* p) {
    uint32_t a;
    asm("{ .reg .u64 t; cvta.to.shared.u64 t, %1; cvt.u32.u64 %0, t; }"
        : "=r"(a) : "l"(p));
    return a;
}
__device__ __forceinline__ void cp16(uint32_t d, const void* s) {
    asm volatile("cp.async.cg.shared.global [%0], [%1], 16;"
                 :: "r"(d), "l"(s));
}
#define CP_COMMIT() asm volatile("cp.async.commit_group;" ::: "memory")
#define CP_WAIT1()  asm volatile("cp.async.wait_group 1;" ::: "memory")
#define CP_WAIT0()  asm volatile("cp.async.wait_group 0;" ::: "memory")

__device__ __forceinline__ void mma_tf32(
    float& c0, float& c1, float& c2, float& c3,
    uint32_t a0, uint32_t a1, uint32_t a2, uint32_t a3,
    uint32_t b0, uint32_t b1)
{
    asm volatile(
        "mma.sync.aligned.m16n8k8.row.col.f32.tf32.tf32.f32 "
        "{%0,%1,%2,%3}, {%4,%5,%6,%7}, {%8,%9}, {%0,%1,%2,%3};"
        : "+f"(c0), "+f"(c1), "+f"(c2), "+f"(c3)
        : "r"(a0), "r"(a1), "r"(a2), "r"(a3), "r"(b0), "r"(b1));
}

// ldmatrix x4: four 8x8 b16 matrices (= four 8x4 tf32 matrices)
__device__ __forceinline__ void ldsm_x4(uint32_t& r0, uint32_t& r1,
                                        uint32_t& r2, uint32_t& r3,
                                        uint32_t addr)
{
    asm volatile("ldmatrix.sync.aligned.m8n8.x4.shared.b16 {%0,%1,%2,%3}, [%4];"
                 : "=r"(r0), "=r"(r1), "=r"(r2), "=r"(r3) : "r"(addr));
}

// ===========================================================================
// Pre-round x, w1, w2 to tf32 (one flat grid: 5120 blocks x 256)
// ===========================================================================
#define NX4  (Mrows * En / 4)      // 1048576
#define NW14 (E3 * En / 4)         // 196608
#define NW24 (En * En / 4)         // 65536

__global__ void __launch_bounds__(256)
cvt_tf32_kernel(const float4* __restrict__ x, const float4* __restrict__ w1,
                const float4* __restrict__ w2)
{
    int i = blockIdx.x * 256 + threadIdx.x;
    const float4* s;
    float4* d;
    if (i < NX4) {
        s = x + i;                       d = (float4*)g_xc + i;
    } else if (i < NX4 + NW14) {
        s = w1 + (i - NX4);              d = (float4*)g_w1c + (i - NX4);
    } else {
        s = w2 + (i - NX4 - NW14);       d = (float4*)g_w2c + (i - NX4 - NW14);
    }
    float4 v = *s;
    float4 w;
    w.x = __uint_as_float(f2tf32(v.x));
    w.y = __uint_as_float(f2tf32(v.y));
    w.z = __uint_as_float(f2tf32(v.z));
    w.w = __uint_as_float(f2tf32(v.w));
    *d = w;
}

// ===========================================================================
// tf32 GEMM, cp.async 3-stage, BK=32, ldmatrix fragments. (unchanged R8)
// C[M,N] = A[M,K] @ Bw[N,K]^T + bias[N]; inputs already tf32-rounded.
// 128x128 tile, 256 thr (8 warps 2x4), warp 64x32.
// ===========================================================================
#define GP 36   // smem pitch in floats (32 + 4)
#define GEMM_SMEM (3 * 2 * 128 * GP * 4)   // 110592 B

template<bool ROUND>
__device__ __forceinline__ void tf32_gemm_ca(
    const float* __restrict__ A, const float* __restrict__ Bw,
    const float* __restrict__ bias, float* __restrict__ C,
    int M, int N, int K)
{
    extern __shared__ float gsm[];
    const int tid  = threadIdx.x;
    const int lane = tid & 31;
    const int wid  = tid >> 5;
    const int wm   = wid >> 2;
    const int wn   = wid & 3;
    const int lr   = lane >> 2;
    const int lc   = lane & 3;
    const int mBase = blockIdx.y * 128;
    const int nBase = blockIdx.x * 128;
    const uint32_t smb = smem_u32(gsm);
    constexpr uint32_t STAGE_B = 2u * 128 * GP * 4;   // 36864

    float acc[4][4][4];
#pragma unroll
    for (int mt = 0; mt < 4; mt++)
#pragma unroll
        for (int nt = 0; nt < 4; nt++)
#pragma unroll
            for (int i = 0; i < 4; i++) acc[mt][nt][i] = 0.0f;

    const float* srcA[4];
    const float* srcW[4];
    uint32_t dA[4], dW[4];
#pragma unroll
    for (int i = 0; i < 4; i++) {
        int f   = tid + i * 256;
        int row = f >> 3;
        int c4  = (f & 7) << 2;
        srcA[i] = A  + (size_t)(mBase + row) * K + c4;
        srcW[i] = Bw + (size_t)(nBase + row) * K + c4;
        dA[i] = (uint32_t)(row * GP + c4) * 4u;
        dW[i] = dA[i] + 128u * GP * 4u;
    }

    const int rowA = (lane & 7) + ((lane >> 3) & 1) * 8;
    const int kofA = (lane >> 4) * 4;
    const int rowB = (lane & 7) + ((lane >> 4) & 1) * 8;
    const int kofB = ((lane >> 3) & 1) * 4;
    uint32_t offA[4], offB[2];
#pragma unroll
    for (int mt = 0; mt < 4; mt++)
        offA[mt] = (uint32_t)(((wm * 64 + mt * 16 + rowA) * GP + kofA) * 4);
#pragma unroll
    for (int p = 0; p < 2; p++)
        offB[p] = (uint32_t)((128 * GP + (wn * 32 + p * 16 + rowB) * GP + kofB) * 4);

    const int nIter = K >> 5;
    auto issue = [&](int it, int s) {
        if (it < nIter) {
            uint32_t sb = smb + (uint32_t)s * STAGE_B;
            int kt = it << 5;
#pragma unroll
            for (int i = 0; i < 4; i++) {
                cp16(sb + dA[i], srcA[i] + kt);
                cp16(sb + dW[i], srcW[i] + kt);
            }
        }
        CP_COMMIT();
    };
    issue(0, 0);
    issue(1, 1);

    int s = 0;
    for (int it = 0; it < nIter; it++) {
        CP_WAIT1();
        __syncthreads();
        int s2 = s + 2; if (s2 >= 3) s2 -= 3;
        issue(it + 2, s2);

        const uint32_t stb = smb + (uint32_t)s * STAGE_B;
#pragma unroll
        for (int k8 = 0; k8 < 32; k8 += 8) {
            uint32_t af[4][4], bf[4][2];
#pragma unroll
            for (int mt = 0; mt < 4; mt++)
                ldsm_x4(af[mt][0], af[mt][1], af[mt][2], af[mt][3],
                        stb + offA[mt] + (uint32_t)(k8 * 4));
#pragma unroll
            for (int p = 0; p < 2; p++)
                ldsm_x4(bf[2 * p][0], bf[2 * p][1],
                        bf[2 * p + 1][0], bf[2 * p + 1][1],
                        stb + offB[p] + (uint32_t)(k8 * 4));
#pragma unroll
            for (int mt = 0; mt < 4; mt++)
#pragma unroll
                for (int nt = 0; nt < 4; nt++)
                    mma_tf32(acc[mt][nt][0], acc[mt][nt][1],
                             acc[mt][nt][2], acc[mt][nt][3],
                             af[mt][0], af[mt][1], af[mt][2], af[mt][3],
                             bf[nt][0], bf[nt][1]);
        }
        if (++s == 3) s = 0;
    }

#pragma unroll
    for (int mt = 0; mt < 4; mt++) {
        const int row0 = mBase + wm * 64 + mt * 16 + lr;
#pragma unroll
        for (int nt = 0; nt < 4; nt++) {
            const int col = nBase + wn * 32 + nt * 8 + 2 * lc;
            const float bx = bias[col];
            const float by = bias[col + 1];
            float v0 = acc[mt][nt][0] + bx, v1 = acc[mt][nt][1] + by;
            float v2 = acc[mt][nt][2] + bx, v3 = acc[mt][nt][3] + by;
            if (ROUND) {
                v0 = __uint_as_float(f2tf32(v0));
                v1 = __uint_as_float(f2tf32(v1));
                v2 = __uint_as_float(f2tf32(v2));
                v3 = __uint_as_float(f2tf32(v3));
            }
            *reinterpret_cast<float2*>(C + (size_t)row0 * N + col) =
                make_float2(v0, v1);
            *reinterpret_cast<float2*>(C + (size_t)(row0 + 8) * N + col) =
                make_float2(v2, v3);
        }
    }
}

__global__ void __launch_bounds__(256, 2)
gemm_qkv_kernel(const float* __restrict__ b1)
{
    tf32_gemm_ca<true>(g_xc, g_w1c, b1, g_qkv, Mrows, E3, En);
}

__global__ void __launch_bounds__(256, 2)
gemm_out_kernel(const float* __restrict__ b2, float* __restrict__ out)
{
    tf32_gemm_ca<false>(g_att, g_w2c, b2, out, Mrows, En, En);
}

// ===========================================================================
// FlashAttention-2, Gaussian-bias windowed, tf32 HMMA, cp.async staging,
// ldmatrix K-fragments.
// R9: BR 128 -> 64, CTA 256 -> 128 threads (4 warps), 3 CTAs/SM.
// Total work scales as S*(BR + 2W): BR=64 cuts ~22% of tile work vs BR=128.
// Window W = 11 t^2 + 64 (dropped mass < 4e-10).
// Grid (Sn/64, Hn, Bn), 128 threads.
// ===========================================================================
#define BR   64
#define BC   64
#define KVP  68
#define NKB  (Sn / BC)
#define ATTN_THREADS 128
#define ATTN_SMEM (4 * BC * KVP * 4)   // 69632 B

__global__ void __launch_bounds__(ATTN_THREADS, 3)
attn_fa2_kernel(const float* __restrict__ t)
{
    extern __shared__ float sm[];
    const uint32_t smb = smem_u32(sm);

    const int tid  = threadIdx.x;
    const int lane = tid & 31;
    const int wid  = tid >> 5;             // 0..3
    const int qt = blockIdx.x, h = blockIdx.y, b = blockIdx.z;
    const int q0 = qt * BR;
    const int qw = q0 + wid * 16;          // this warp's first q row

    const int lr = lane >> 2;
    const int lc = lane & 3;

    const float tt = t[h];
    const float sig = tt * tt;
    const float ninv = -1.0f / (2.0f * sig * sig);

    const float Wf = fminf(11.0f * sig + 64.0f, (float)Sn);
    const int   W  = (int)Wf;
    const int kb_lo = max(0, (q0 - W) >> 6);
    const int kb_hi = min(NKB - 1, (q0 + BR - 1 + W) >> 6);

    auto issue_kv = [&](int k0, int buf) {
        const float* srcb = g_qkv + En + (size_t)(b * Sn + k0) * E3 + h * Dn;
        uint32_t sb = smb + (uint32_t)buf * (2u * BC * KVP * 4u);
#pragma unroll
        for (int i = 0; i < 16; i++) {
            int f   = i * ATTN_THREADS + tid;   // 0..2047
            int sel = f >> 10;
            int idx = f & 1023;
            int row = idx >> 4;
            int c4  = (idx & 15) << 2;
            const float* src = srcb + (size_t)sel * En + (size_t)row * E3 + c4;
            uint32_t dst = sb + (uint32_t)(sel * BC * KVP + row * KVP + c4) * 4u;
            cp16(dst, src);
        }
    };

    const int rowB = (lane & 7) + ((lane >> 4) & 1) * 8;
    const int kofB = ((lane >> 3) & 1) * 4;
    uint32_t offK[4];
#pragma unroll
    for (int p = 0; p < 4; p++)
        offK[p] = (uint32_t)(((p * 16 + rowB) * KVP + kofB) * 4);

    uint32_t qa[8][4];
    {
        const float* qp  = g_qkv + (size_t)(b * Sn + qw + lr) * E3 + h * Dn;
        const float* qp8 = qp + 8 * E3;
#pragma unroll
        for (int kt = 0; kt < 8; kt++) {
            qa[kt][0] = __float_as_uint(qp [kt * 8 + lc]     * 0.125f);
            qa[kt][1] = __float_as_uint(qp8[kt * 8 + lc]     * 0.125f);
            qa[kt][2] = __float_as_uint(qp [kt * 8 + lc + 4] * 0.125f);
            qa[kt][3] = __float_as_uint(qp8[kt * 8 + lc + 4] * 0.125f);
        }
    }

    float o[8][4];
#pragma unroll
    for (int nt = 0; nt < 8; nt++)
#pragma unroll
        for (int i = 0; i < 4; i++) o[nt][i] = 0.0f;
    float m0 = -INFINITY, m1 = -INFINITY;
    float l0 = 0.0f, l1 = 0.0f;

    issue_kv(kb_lo * BC, 0);
    CP_COMMIT();

    const int srcA = (lane & ~3) | (lc >> 1);
    const int srcB = srcA + 2;
    const bool oddl = lane & 1;
    const int colb = 2 * lc;

    int cur = 0;
    for (int kb = kb_lo; kb <= kb_hi; kb++) {
        const int k0 = kb * BC;

        CP_WAIT0();
        __syncthreads();
        if (kb + 1 <= kb_hi) issue_kv(k0 + BC, cur ^ 1);
        CP_COMMIT();

        const uint32_t Kb = smb + (uint32_t)cur * (2u * BC * KVP * 4u);
        const float* Vc = sm + (2 * cur + 1) * BC * KVP;

        float sc[8][4];
#pragma unroll
        for (int nt = 0; nt < 8; nt++)
#pragma unroll
            for (int i = 0; i < 4; i++) sc[nt][i] = 0.0f;

#pragma unroll
        for (int kt = 0; kt < 8; kt++) {
            uint32_t kf[8][2];
#pragma unroll
            for (int p = 0; p < 4; p++)
                ldsm_x4(kf[2 * p][0], kf[2 * p][1],
                        kf[2 * p + 1][0], kf[2 * p + 1][1],
                        Kb + offK[p] + (uint32_t)(kt * 32));
#pragma unroll
            for (int nt = 0; nt < 8; nt++)
                mma_tf32(sc[nt][0], sc[nt][1], sc[nt][2], sc[nt][3],
                         qa[kt][0], qa[kt][1], qa[kt][2], qa[kt][3],
                         kf[nt][0], kf[nt][1]);
        }

        const float d0f = (float)(qw + lr - k0);
        const float d1f = d0f + 8.0f;
        float rmax0 = -INFINITY, rmax1 = -INFINITY;
#pragma unroll
        for (int nt = 0; nt < 8; nt++) {
#pragma unroll
            for (int e = 0; e < 2; e++) {
                float cj = (float)(nt * 8 + colb + e);
                float fd0 = d0f - cj;
                float fd1 = d1f - cj;
                sc[nt][e]     = fmaf(fd0 * fd0, ninv, sc[nt][e]);
                sc[nt][e + 2] = fmaf(fd1 * fd1, ninv, sc[nt][e + 2]);
                rmax0 = fmaxf(rmax0, sc[nt][e]);
                rmax1 = fmaxf(rmax1, sc[nt][e + 2]);
            }
        }
        rmax0 = fmaxf(rmax0, __shfl_xor_sync(0xffffffffu, rmax0, 1));
        rmax0 = fmaxf(rmax0, __shfl_xor_sync(0xffffffffu, rmax0, 2));
        rmax1 = fmaxf(rmax1, __shfl_xor_sync(0xffffffffu, rmax1, 1));
        rmax1 = fmaxf(rmax1, __shfl_xor_sync(0xffffffffu, rmax1, 2));

        const float mn0 = fmaxf(m0, rmax0);
        const float mn1 = fmaxf(m1, rmax1);
        const float corr0 = __expf(m0 - mn0);
        const float corr1 = __expf(m1 - mn1);
        m0 = mn0; m1 = mn1;

        float ls0 = 0.0f, ls1 = 0.0f;
#pragma unroll
        for (int nt = 0; nt < 8; nt++) {
#pragma unroll
            for (int e = 0; e < 2; e++) {
                float p0 = __expf(sc[nt][e]     - mn0);
                float p1 = __expf(sc[nt][e + 2] - mn1);
                float p0t = __uint_as_float(f2tf32(p0));
                float p1t = __uint_as_float(f2tf32(p1));
                sc[nt][e]     = p0t;
                sc[nt][e + 2] = p1t;
                ls0 += p0t;
                ls1 += p1t;
            }
        }
        l0 = l0 * corr0 + ls0;
        l1 = l1 * corr1 + ls1;

        if (__ballot_sync(0xffffffffu, (corr0 != 1.0f) | (corr1 != 1.0f))) {
#pragma unroll
            for (int nt = 0; nt < 8; nt++) {
                o[nt][0] *= corr0; o[nt][1] *= corr0;
                o[nt][2] *= corr1; o[nt][3] *= corr1;
            }
        }

#pragma unroll
        for (int kt = 0; kt < 8; kt++) {
            float p0 = sc[kt][0], p1 = sc[kt][1];
            float p2 = sc[kt][2], p3 = sc[kt][3];
            float x0 = __shfl_sync(0xffffffffu, p0, srcA);
            float x1 = __shfl_sync(0xffffffffu, p1, srcA);
            float y0 = __shfl_sync(0xffffffffu, p0, srcB);
            float y1 = __shfl_sync(0xffffffffu, p1, srcB);
            float x2 = __shfl_sync(0xffffffffu, p2, srcA);
            float x3 = __shfl_sync(0xffffffffu, p3, srcA);
            float y2 = __shfl_sync(0xffffffffu, p2, srcB);
            float y3 = __shfl_sync(0xffffffffu, p3, srcB);
            uint32_t a0 = __float_as_uint(oddl ? x1 : x0);
            uint32_t a2 = __float_as_uint(oddl ? y1 : y0);
            uint32_t a1 = __float_as_uint(oddl ? x3 : x2);
            uint32_t a3 = __float_as_uint(oddl ? y3 : y2);

            const float* vp = Vc + (kt * 8 + lc) * KVP + lr;
#pragma unroll
            for (int nt = 0; nt < 8; nt++) {
                uint32_t b0 = __float_as_uint(vp[nt * 8]);
                uint32_t b1 = __float_as_uint(vp[nt * 8 + 4 * KVP]);
                mma_tf32(o[nt][0], o[nt][1], o[nt][2], o[nt][3],
                         a0, a1, a2, a3, b0, b1);
            }
        }

        cur ^= 1;
    }

    l0 += __shfl_xor_sync(0xffffffffu, l0, 1);
    l0 += __shfl_xor_sync(0xffffffffu, l0, 2);
    l1 += __shfl_xor_sync(0xffffffffu, l1, 1);
    l1 += __shfl_xor_sync(0xffffffffu, l1, 2);
    const float il0 = 1.0f / l0;
    const float il1 = 1.0f / l1;

    float* op0 = g_att + (size_t)(b * Sn + qw + lr) * En + h * Dn + colb;
    float* op1 = op0 + 8 * En;
#pragma unroll
    for (int nt = 0; nt < 8; nt++) {
        float2 r0 = make_float2(
            __uint_as_float(f2tf32(o[nt][0] * il0)),
            __uint_as_float(f2tf32(o[nt][1] * il0)));
        float2 r1 = make_float2(
            __uint_as_float(f2tf32(o[nt][2] * il1)),
            __uint_as_float(f2tf32(o[nt][3] * il1)));
        *reinterpret_cast<float2*>(op0 + nt * 8) = r0;
        *reinterpret_cast<float2*>(op1 + nt * 8) = r1;
    }
}

// ===========================================================================
// Launch
// ===========================================================================
extern "C" void kernel_launch(void* const* d_in, const int* in_sizes, int n_in,
                              void* d_out, int out_size)
{
    const float* x  = (const float*)d_in[0];
    const float* w1 = (const float*)d_in[1];
    const float* b1 = (const float*)d_in[2];
    const float* w2 = (const float*)d_in[3];
    const float* b2 = (const float*)d_in[4];
    const float* t  = (const float*)d_in[5];
    float* out = (float*)d_out;
    (void)in_sizes; (void)n_in; (void)out_size;

    cvt_tf32_kernel<<<(NX4 + NW14 + NW24) / 256, 256>>>(
        (const float4*)x, (const float4*)w1, (const float4*)w2);

    cudaFuncSetAttribute(gemm_qkv_kernel,
                         cudaFuncAttributeMaxDynamicSharedMemorySize, GEMM_SMEM);
    cudaFuncSetAttribute(gemm_out_kernel,
                         cudaFuncAttributeMaxDynamicSharedMemorySize, GEMM_SMEM);
    cudaFuncSetAttribute(attn_fa2_kernel,
                         cudaFuncAttributeMaxDynamicSharedMemorySize, ATTN_SMEM);

    gemm_qkv_kernel<<<dim3(E3 / 128, Mrows / 128), 256, GEMM_SMEM>>>(b1);

    attn_fa2_kernel<<<dim3(Sn / BR, Hn, Bn), ATTN_THREADS, ATTN_SMEM>>>(t);

    gemm_out_kernel<<<dim3(En / 128, Mrows / 128), 256, GEMM_SMEM>>>(b2, out);
}

// round 10
// speedup vs baseline: 13.9138x; 1.0288x over previous
#include <cuda_runtime.h>
#include <math.h>
#include <stdint.h>

// Problem constants
#define Bn  2
#define Sn  4096
#define En  512
#define Hn  8
#define Dn  64
#define E3  1536
#define Mrows (Bn * Sn)   // 8192

// Scratch (static device globals -- no allocation at runtime)
__device__ float g_qkv[(size_t)Mrows * E3];   // [B*S, 3E] (tf32; V region unused)
__device__ float g_vt [(size_t)Bn * Hn * Dn * Sn]; // V transposed [b][h][d][s]
__device__ float g_att[(size_t)Mrows * En];   // [B*S, E]  (tf32-rounded)
__device__ float g_xc [(size_t)Mrows * En];   // x  pre-rounded to tf32
__device__ float g_w1c[(size_t)E3 * En];      // w1 pre-rounded
__device__ float g_w2c[(size_t)En * En];      // w2 pre-rounded

// ===========================================================================
// Helpers
// ===========================================================================
__device__ __forceinline__ uint32_t f2tf32(float x) {
    uint32_t r;
    asm("cvt.rna.tf32.f32 %0, %1;" : "=r"(r) : "f"(x));
    return r;
}
__device__ __forceinline__ uint32_t smem_u32(const void* p) {
    uint32_t a;
    asm("{ .reg .u64 t; cvta.to.shared.u64 t, %1; cvt.u32.u64 %0, t; }"
        : "=r"(a) : "l"(p));
    return a;
}
__device__ __forceinline__ void cp16(uint32_t d, const void* s) {
    asm volatile("cp.async.cg.shared.global [%0], [%1], 16;"
                 :: "r"(d), "l"(s));
}
#define CP_COMMIT() asm volatile("cp.async.commit_group;" ::: "memory")
#define CP_WAIT1()  asm volatile("cp.async.wait_group 1;" ::: "memory")
#define CP_WAIT0()  asm volatile("cp.async.wait_group 0;" ::: "memory")

__device__ __forceinline__ void mma_tf32(
    float& c0, float& c1, float& c2, float& c3,
    uint32_t a0, uint32_t a1, uint32_t a2, uint32_t a3,
    uint32_t b0, uint32_t b1)
{
    asm volatile(
        "mma.sync.aligned.m16n8k8.row.col.f32.tf32.tf32.f32 "
        "{%0,%1,%2,%3}, {%4,%5,%6,%7}, {%8,%9}, {%0,%1,%2,%3};"
        : "+f"(c0), "+f"(c1), "+f"(c2), "+f"(c3)
        : "r"(a0), "r"(a1), "r"(a2), "r"(a3), "r"(b0), "r"(b1));
}

// ldmatrix x4: four 8x8 b16 matrices (= four 8x4 tf32 matrices)
__device__ __forceinline__ void ldsm_x4(uint32_t& r0, uint32_t& r1,
                                        uint32_t& r2, uint32_t& r3,
                                        uint32_t addr)
{
    asm volatile("ldmatrix.sync.aligned.m8n8.x4.shared.b16 {%0,%1,%2,%3}, [%4];"
                 : "=r"(r0), "=r"(r1), "=r"(r2), "=r"(r3) : "r"(addr));
}

// ===========================================================================
// Pre-round x, w1, w2 to tf32 (one flat grid: 5120 blocks x 256)
// ===========================================================================
#define NX4  (Mrows * En / 4)      // 1048576
#define NW14 (E3 * En / 4)         // 196608
#define NW24 (En * En / 4)         // 65536

__global__ void __launch_bounds__(256)
cvt_tf32_kernel(const float4* __restrict__ x, const float4* __restrict__ w1,
                const float4* __restrict__ w2)
{
    int i = blockIdx.x * 256 + threadIdx.x;
    const float4* s;
    float4* d;
    if (i < NX4) {
        s = x + i;                       d = (float4*)g_xc + i;
    } else if (i < NX4 + NW14) {
        s = w1 + (i - NX4);              d = (float4*)g_w1c + (i - NX4);
    } else {
        s = w2 + (i - NX4 - NW14);       d = (float4*)g_w2c + (i - NX4 - NW14);
    }
    float4 v = *s;
    float4 w;
    w.x = __uint_as_float(f2tf32(v.x));
    w.y = __uint_as_float(f2tf32(v.y));
    w.z = __uint_as_float(f2tf32(v.z));
    w.w = __uint_as_float(f2tf32(v.w));
    *d = w;
}

// ===========================================================================
// tf32 GEMM, cp.async 3-stage, BK=32, ldmatrix fragments.
// C[M,N] = A[M,K] @ Bw[N,K]^T + bias[N]; inputs already tf32-rounded.
// 128x128 tile, 256 thr (8 warps 2x4), warp 64x32.
// VT: tiles with nBase >= 1024 are V columns of the qkv projection; they are
// written TRANSPOSED to g_vt[b][h][d][s] via an smem round-trip (coalesced),
// and the g_qkv store is skipped for them.
// ===========================================================================
#define GP 36   // smem pitch in floats (32 + 4)
#define GEMM_SMEM (3 * 2 * 128 * GP * 4)   // 110592 B
#define TP 132  // transpose scratch pitch (floats)

template<bool ROUND, bool VT>
__device__ __forceinline__ void tf32_gemm_ca(
    const float* __restrict__ A, const float* __restrict__ Bw,
    const float* __restrict__ bias, float* __restrict__ C,
    int M, int N, int K)
{
    extern __shared__ float gsm[];
    const int tid  = threadIdx.x;
    const int lane = tid & 31;
    const int wid  = tid >> 5;
    const int wm   = wid >> 2;
    const int wn   = wid & 3;
    const int lr   = lane >> 2;
    const int lc   = lane & 3;
    const int mBase = blockIdx.y * 128;
    const int nBase = blockIdx.x * 128;
    const uint32_t smb = smem_u32(gsm);
    constexpr uint32_t STAGE_B = 2u * 128 * GP * 4;   // 36864

    float acc[4][4][4];
#pragma unroll
    for (int mt = 0; mt < 4; mt++)
#pragma unroll
        for (int nt = 0; nt < 4; nt++)
#pragma unroll
            for (int i = 0; i < 4; i++) acc[mt][nt][i] = 0.0f;

    const float* srcA[4];
    const float* srcW[4];
    uint32_t dA[4], dW[4];
#pragma unroll
    for (int i = 0; i < 4; i++) {
        int f   = tid + i * 256;
        int row = f >> 3;
        int c4  = (f & 7) << 2;
        srcA[i] = A  + (size_t)(mBase + row) * K + c4;
        srcW[i] = Bw + (size_t)(nBase + row) * K + c4;
        dA[i] = (uint32_t)(row * GP + c4) * 4u;
        dW[i] = dA[i] + 128u * GP * 4u;
    }

    const int rowA = (lane & 7) + ((lane >> 3) & 1) * 8;
    const int kofA = (lane >> 4) * 4;
    const int rowB = (lane & 7) + ((lane >> 4) & 1) * 8;
    const int kofB = ((lane >> 3) & 1) * 4;
    uint32_t offA[4], offB[2];
#pragma unroll
    for (int mt = 0; mt < 4; mt++)
        offA[mt] = (uint32_t)(((wm * 64 + mt * 16 + rowA) * GP + kofA) * 4);
#pragma unroll
    for (int p = 0; p < 2; p++)
        offB[p] = (uint32_t)((128 * GP + (wn * 32 + p * 16 + rowB) * GP + kofB) * 4);

    const int nIter = K >> 5;
    auto issue = [&](int it, int s) {
        if (it < nIter) {
            uint32_t sb = smb + (uint32_t)s * STAGE_B;
            int kt = it << 5;
#pragma unroll
            for (int i = 0; i < 4; i++) {
                cp16(sb + dA[i], srcA[i] + kt);
                cp16(sb + dW[i], srcW[i] + kt);
            }
        }
        CP_COMMIT();
    };
    issue(0, 0);
    issue(1, 1);

    int s = 0;
    for (int it = 0; it < nIter; it++) {
        CP_WAIT1();
        __syncthreads();
        int s2 = s + 2; if (s2 >= 3) s2 -= 3;
        issue(it + 2, s2);

        const uint32_t stb = smb + (uint32_t)s * STAGE_B;
#pragma unroll
        for (int k8 = 0; k8 < 32; k8 += 8) {
            uint32_t af[4][4], bf[4][2];
#pragma unroll
            for (int mt = 0; mt < 4; mt++)
                ldsm_x4(af[mt][0], af[mt][1], af[mt][2], af[mt][3],
                        stb + offA[mt] + (uint32_t)(k8 * 4));
#pragma unroll
            for (int p = 0; p < 2; p++)
                ldsm_x4(bf[2 * p][0], bf[2 * p][1],
                        bf[2 * p + 1][0], bf[2 * p + 1][1],
                        stb + offB[p] + (uint32_t)(k8 * 4));
#pragma unroll
            for (int mt = 0; mt < 4; mt++)
#pragma unroll
                for (int nt = 0; nt < 4; nt++)
                    mma_tf32(acc[mt][nt][0], acc[mt][nt][1],
                             acc[mt][nt][2], acc[mt][nt][3],
                             af[mt][0], af[mt][1], af[mt][2], af[mt][3],
                             bf[nt][0], bf[nt][1]);
        }
        if (++s == 3) s = 0;
    }

    if (VT && nBase >= 2 * En) {
        // ---- V tile: bias + round, transpose via smem, write g_vt ----
        CP_WAIT0();
        __syncthreads();                   // stage smem now reusable
        float* T = gsm;                    // [128 cols][TP]
#pragma unroll
        for (int mt = 0; mt < 4; mt++) {
            const int r0 = wm * 64 + mt * 16 + lr;
#pragma unroll
            for (int nt = 0; nt < 4; nt++) {
                const int c = wn * 32 + nt * 8 + 2 * lc;
                const float bx = bias[nBase + c];
                const float by = bias[nBase + c + 1];
                T[c * TP + r0]           = __uint_as_float(f2tf32(acc[mt][nt][0] + bx));
                T[(c + 1) * TP + r0]     = __uint_as_float(f2tf32(acc[mt][nt][1] + by));
                T[c * TP + r0 + 8]       = __uint_as_float(f2tf32(acc[mt][nt][2] + bx));
                T[(c + 1) * TP + r0 + 8] = __uint_as_float(f2tf32(acc[mt][nt][3] + by));
            }
        }
        __syncthreads();
        const int bb = mBase >> 12;
        const int s0 = mBase & (Sn - 1);
#pragma unroll
        for (int i = 0; i < 16; i++) {
            int f  = tid + i * 256;        // 0..4095
            int c  = f >> 5;               // 0..127 local col
            int r4 = (f & 31) << 2;        // 0..124 local row
            int col = nBase - 2 * En + c;  // 0..511 within V
            int h = col >> 6, d = col & 63;
            float4 v = *reinterpret_cast<const float4*>(T + c * TP + r4);
            *reinterpret_cast<float4*>(
                g_vt + (((size_t)bb * Hn + h) * Dn + d) * Sn + s0 + r4) = v;
        }
        return;
    }

    // ---- normal epilogue: bias add; optional tf32 rounding ----
#pragma unroll
    for (int mt = 0; mt < 4; mt++) {
        const int row0 = mBase + wm * 64 + mt * 16 + lr;
#pragma unroll
        for (int nt = 0; nt < 4; nt++) {
            const int col = nBase + wn * 32 + nt * 8 + 2 * lc;
            const float bx = bias[col];
            const float by = bias[col + 1];
            float v0 = acc[mt][nt][0] + bx, v1 = acc[mt][nt][1] + by;
            float v2 = acc[mt][nt][2] + bx, v3 = acc[mt][nt][3] + by;
            if (ROUND) {
                v0 = __uint_as_float(f2tf32(v0));
                v1 = __uint_as_float(f2tf32(v1));
                v2 = __uint_as_float(f2tf32(v2));
                v3 = __uint_as_float(f2tf32(v3));
            }
            *reinterpret_cast<float2*>(C + (size_t)row0 * N + col) =
                make_float2(v0, v1);
            *reinterpret_cast<float2*>(C + (size_t)(row0 + 8) * N + col) =
                make_float2(v2, v3);
        }
    }
}

__global__ void __launch_bounds__(256, 2)
gemm_qkv_kernel(const float* __restrict__ b1)
{
    tf32_gemm_ca<true, true>(g_xc, g_w1c, b1, g_qkv, Mrows, E3, En);
}

__global__ void __launch_bounds__(256, 2)
gemm_out_kernel(const float* __restrict__ b2, float* __restrict__ out)
{
    tf32_gemm_ca<false, false>(g_att, g_w2c, b2, out, Mrows, En, En);
}

// ===========================================================================
// FlashAttention-2, Gaussian-bias windowed, tf32 HMMA, cp.async staging,
// ldmatrix fragments for BOTH K and V (V staged transposed from g_vt).
// Window W = 11 t^2 + 64 (dropped mass < 4e-10).
// Grid (Sn/64, Hn, Bn), 128 threads, 3 CTAs/SM.
// ===========================================================================
#define BR   64
#define BC   64
#define KVP  68
#define NKB  (Sn / BC)
#define ATTN_THREADS 128
#define ATTN_SMEM (4 * BC * KVP * 4)   // 69632 B

__global__ void __launch_bounds__(ATTN_THREADS, 3)
attn_fa2_kernel(const float* __restrict__ t)
{
    extern __shared__ float sm[];
    const uint32_t smb = smem_u32(sm);

    const int tid  = threadIdx.x;
    const int lane = tid & 31;
    const int wid  = tid >> 5;             // 0..3
    const int qt = blockIdx.x, h = blockIdx.y, b = blockIdx.z;
    const int q0 = qt * BR;
    const int qw = q0 + wid * 16;          // this warp's first q row

    const int lr = lane >> 2;
    const int lc = lane & 3;

    const float tt = t[h];
    const float sig = tt * tt;
    const float ninv = -1.0f / (2.0f * sig * sig);

    const float Wf = fminf(11.0f * sig + 64.0f, (float)Sn);
    const int   W  = (int)Wf;
    const int kb_lo = max(0, (q0 - W) >> 6);
    const int kb_hi = min(NKB - 1, (q0 + BR - 1 + W) >> 6);

    // Stage K [key][d] from g_qkv and V^T [d][key] from g_vt, both pitch KVP.
    const float* srcVbase = g_vt + ((size_t)b * Hn + h) * Dn * Sn;
    auto issue_kv = [&](int k0, int buf) {
        const float* srcK = g_qkv + En + (size_t)(b * Sn + k0) * E3 + h * Dn;
        const float* srcV = srcVbase + k0;
        uint32_t sb = smb + (uint32_t)buf * (2u * BC * KVP * 4u);
#pragma unroll
        for (int i = 0; i < 16; i++) {
            int f   = i * ATTN_THREADS + tid;   // 0..2047
            int sel = f >> 10;
            int idx = f & 1023;
            int row = idx >> 4;                 // 0..63 (key for K, d for V)
            int c4  = (idx & 15) << 2;          // 0..60
            const float* src = sel ? (srcV + (size_t)row * Sn + c4)
                                   : (srcK + (size_t)row * E3 + c4);
            uint32_t dst = sb + (uint32_t)((sel * BC + row) * KVP + c4) * 4u;
            cp16(dst, src);
        }
    };

    const int rowB = (lane & 7) + ((lane >> 4) & 1) * 8;
    const int kofB = ((lane >> 3) & 1) * 4;
    uint32_t offK[4], offV[4];
#pragma unroll
    for (int p = 0; p < 4; p++) {
        offK[p] = (uint32_t)(((p * 16 + rowB) * KVP + kofB) * 4);
        offV[p] = offK[p] + (uint32_t)(BC * KVP * 4);
    }

    uint32_t qa[8][4];
    {
        const float* qp  = g_qkv + (size_t)(b * Sn + qw + lr) * E3 + h * Dn;
        const float* qp8 = qp + 8 * E3;
#pragma unroll
        for (int kt = 0; kt < 8; kt++) {
            qa[kt][0] = __float_as_uint(qp [kt * 8 + lc]     * 0.125f);
            qa[kt][1] = __float_as_uint(qp8[kt * 8 + lc]     * 0.125f);
            qa[kt][2] = __float_as_uint(qp [kt * 8 + lc + 4] * 0.125f);
            qa[kt][3] = __float_as_uint(qp8[kt * 8 + lc + 4] * 0.125f);
        }
    }

    float o[8][4];
#pragma unroll
    for (int nt = 0; nt < 8; nt++)
#pragma unroll
        for (int i = 0; i < 4; i++) o[nt][i] = 0.0f;
    float m0 = -INFINITY, m1 = -INFINITY;
    float l0 = 0.0f, l1 = 0.0f;

    issue_kv(kb_lo * BC, 0);
    CP_COMMIT();

    const int srcA = (lane & ~3) | (lc >> 1);
    const int srcB = srcA + 2;
    const bool oddl = lane & 1;
    const int colb = 2 * lc;

    int cur = 0;
    for (int kb = kb_lo; kb <= kb_hi; kb++) {
        const int k0 = kb * BC;

        CP_WAIT0();
        __syncthreads();
        if (kb + 1 <= kb_hi) issue_kv(k0 + BC, cur ^ 1);
        CP_COMMIT();

        const uint32_t Kb = smb + (uint32_t)cur * (2u * BC * KVP * 4u);

        // ---- S = Q @ K^T (ldmatrix B-fragments) ----
        float sc[8][4];
#pragma unroll
        for (int nt = 0; nt < 8; nt++)
#pragma unroll
            for (int i = 0; i < 4; i++) sc[nt][i] = 0.0f;

#pragma unroll
        for (int kt = 0; kt < 8; kt++) {
            uint32_t kf[8][2];
#pragma unroll
            for (int p = 0; p < 4; p++)
                ldsm_x4(kf[2 * p][0], kf[2 * p][1],
                        kf[2 * p + 1][0], kf[2 * p + 1][1],
                        Kb + offK[p] + (uint32_t)(kt * 32));
#pragma unroll
            for (int nt = 0; nt < 8; nt++)
                mma_tf32(sc[nt][0], sc[nt][1], sc[nt][2], sc[nt][3],
                         qa[kt][0], qa[kt][1], qa[kt][2], qa[kt][3],
                         kf[nt][0], kf[nt][1]);
        }

        // ---- Gaussian bias + online softmax ----
        const float d0f = (float)(qw + lr - k0);
        const float d1f = d0f + 8.0f;
        float rmax0 = -INFINITY, rmax1 = -INFINITY;
#pragma unroll
        for (int nt = 0; nt < 8; nt++) {
#pragma unroll
            for (int e = 0; e < 2; e++) {
                float cj = (float)(nt * 8 + colb + e);
                float fd0 = d0f - cj;
                float fd1 = d1f - cj;
                sc[nt][e]     = fmaf(fd0 * fd0, ninv, sc[nt][e]);
                sc[nt][e + 2] = fmaf(fd1 * fd1, ninv, sc[nt][e + 2]);
                rmax0 = fmaxf(rmax0, sc[nt][e]);
                rmax1 = fmaxf(rmax1, sc[nt][e + 2]);
            }
        }
        rmax0 = fmaxf(rmax0, __shfl_xor_sync(0xffffffffu, rmax0, 1));
        rmax0 = fmaxf(rmax0, __shfl_xor_sync(0xffffffffu, rmax0, 2));
        rmax1 = fmaxf(rmax1, __shfl_xor_sync(0xffffffffu, rmax1, 1));
        rmax1 = fmaxf(rmax1, __shfl_xor_sync(0xffffffffu, rmax1, 2));

        const float mn0 = fmaxf(m0, rmax0);
        const float mn1 = fmaxf(m1, rmax1);
        const float corr0 = __expf(m0 - mn0);
        const float corr1 = __expf(m1 - mn1);
        m0 = mn0; m1 = mn1;

        float ls0 = 0.0f, ls1 = 0.0f;
#pragma unroll
        for (int nt = 0; nt < 8; nt++) {
#pragma unroll
            for (int e = 0; e < 2; e++) {
                float p0 = __expf(sc[nt][e]     - mn0);
                float p1 = __expf(sc[nt][e + 2] - mn1);
                float p0t = __uint_as_float(f2tf32(p0));
                float p1t = __uint_as_float(f2tf32(p1));
                sc[nt][e]     = p0t;
                sc[nt][e + 2] = p1t;
                ls0 += p0t;
                ls1 += p1t;
            }
        }
        l0 = l0 * corr0 + ls0;
        l1 = l1 * corr1 + ls1;

        if (__ballot_sync(0xffffffffu, (corr0 != 1.0f) | (corr1 != 1.0f))) {
#pragma unroll
            for (int nt = 0; nt < 8; nt++) {
                o[nt][0] *= corr0; o[nt][1] *= corr0;
                o[nt][2] *= corr1; o[nt][3] *= corr1;
            }
        }

        // ---- O += P @ V (ldmatrix B-fragments from transposed V) ----
#pragma unroll
        for (int kt = 0; kt < 8; kt++) {
            float p0 = sc[kt][0], p1 = sc[kt][1];
            float p2 = sc[kt][2], p3 = sc[kt][3];
            float x0 = __shfl_sync(0xffffffffu, p0, srcA);
            float x1 = __shfl_sync(0xffffffffu, p1, srcA);
            float y0 = __shfl_sync(0xffffffffu, p0, srcB);
            float y1 = __shfl_sync(0xffffffffu, p1, srcB);
            float x2 = __shfl_sync(0xffffffffu, p2, srcA);
            float x3 = __shfl_sync(0xffffffffu, p3, srcA);
            float y2 = __shfl_sync(0xffffffffu, p2, srcB);
            float y3 = __shfl_sync(0xffffffffu, p3, srcB);
            uint32_t a0 = __float_as_uint(oddl ? x1 : x0);
            uint32_t a2 = __float_as_uint(oddl ? y1 : y0);
            uint32_t a1 = __float_as_uint(oddl ? x3 : x2);
            uint32_t a3 = __float_as_uint(oddl ? y3 : y2);

            uint32_t vf[8][2];
#pragma unroll
            for (int p = 0; p < 4; p++)
                ldsm_x4(vf[2 * p][0], vf[2 * p][1],
                        vf[2 * p + 1][0], vf[2 * p + 1][1],
                        Kb + offV[p] + (uint32_t)(kt * 32));
#pragma unroll
            for (int nt = 0; nt < 8; nt++)
                mma_tf32(o[nt][0], o[nt][1], o[nt][2], o[nt][3],
                         a0, a1, a2, a3, vf[nt][0], vf[nt][1]);
        }

        cur ^= 1;
    }

    l0 += __shfl_xor_sync(0xffffffffu, l0, 1);
    l0 += __shfl_xor_sync(0xffffffffu, l0, 2);
    l1 += __shfl_xor_sync(0xffffffffu, l1, 1);
    l1 += __shfl_xor_sync(0xffffffffu, l1, 2);
    const float il0 = 1.0f / l0;
    const float il1 = 1.0f / l1;

    float* op0 = g_att + (size_t)(b * Sn + qw + lr) * En + h * Dn + colb;
    float* op1 = op0 + 8 * En;
#pragma unroll
    for (int nt = 0; nt < 8; nt++) {
        float2 r0 = make_float2(
            __uint_as_float(f2tf32(o[nt][0] * il0)),
            __uint_as_float(f2tf32(o[nt][1] * il0)));
        float2 r1 = make_float2(
            __uint_as_float(f2tf32(o[nt][2] * il1)),
            __uint_as_float(f2tf32(o[nt][3] * il1)));
        *reinterpret_cast<float2*>(op0 + nt * 8) = r0;
        *reinterpret_cast<float2*>(op1 + nt * 8) = r1;
    }
}

// ===========================================================================
// Launch
// ===========================================================================
extern "C" void kernel_launch(void* const* d_in, const int* in_sizes, int n_in,
                              void* d_out, int out_size)
{
    const float* x  = (const float*)d_in[0];
    const float* w1 = (const float*)d_in[1];
    const float* b1 = (const float*)d_in[2];
    const float* w2 = (const float*)d_in[3];
    const float* b2 = (const float*)d_in[4];
    const float* t  = (const float*)d_in[5];
    float* out = (float*)d_out;
    (void)in_sizes; (void)n_in; (void)out_size;

    cvt_tf32_kernel<<<(NX4 + NW14 + NW24) / 256, 256>>>(
        (const float4*)x, (const float4*)w1, (const float4*)w2);

    cudaFuncSetAttribute(gemm_qkv_kernel,
                         cudaFuncAttributeMaxDynamicSharedMemorySize, GEMM_SMEM);
    cudaFuncSetAttribute(gemm_out_kernel,
                         cudaFuncAttributeMaxDynamicSharedMemorySize, GEMM_SMEM);
    cudaFuncSetAttribute(attn_fa2_kernel,
                         cudaFuncAttributeMaxDynamicSharedMemorySize, ATTN_SMEM);

    gemm_qkv_kernel<<<dim3(E3 / 128, Mrows / 128), 256, GEMM_SMEM>>>(b1);

    attn_fa2_kernel<<<dim3(Sn / BR, Hn, Bn), ATTN_THREADS, ATTN_SMEM>>>(t);

    gemm_out_kernel<<<dim3(En / 128, Mrows / 128), 256, GEMM_SMEM>>>(b2, out);
}

// round 11
// speedup vs baseline: 24.6528x; 1.7718x over previous
#include <cuda_runtime.h>
#include <cuda_fp16.h>
#include <math.h>
#include <stdint.h>

// Problem constants
#define Bn  2
#define Sn  4096
#define En  512
#define Hn  8
#define Dn  64
#define E3  1536
#define Mrows (Bn * Sn)   // 8192

// Scratch (static device globals -- no allocation at runtime)
__device__ __half g_qkv[(size_t)Mrows * E3];        // [B*S,3E] fp16 (V unused)
__device__ __half g_vt [(size_t)Bn * Hn * Dn * Sn]; // V transposed [b][h][d][s]
__device__ __half g_att[(size_t)Mrows * En];        // attention out fp16
__device__ __half g_xh [(size_t)Mrows * En];        // x  fp16
__device__ __half g_w1h[(size_t)E3 * En];           // w1 fp16
__device__ __half g_w2h[(size_t)En * En];           // w2 fp16

// ===========================================================================
// Helpers
// ===========================================================================
__device__ __forceinline__ uint32_t smem_u32(const void* p) {
    uint32_t a;
    asm("{ .reg .u64 t; cvta.to.shared.u64 t, %1; cvt.u32.u64 %0, t; }"
        : "=r"(a) : "l"(p));
    return a;
}
__device__ __forceinline__ void cp16(uint32_t d, const void* s) {
    asm volatile("cp.async.cg.shared.global [%0], [%1], 16;"
                 :: "r"(d), "l"(s));
}
#define CP_COMMIT() asm volatile("cp.async.commit_group;" ::: "memory")
#define CP_WAIT1()  asm volatile("cp.async.wait_group 1;" ::: "memory")
#define CP_WAIT0()  asm volatile("cp.async.wait_group 0;" ::: "memory")

__device__ __forceinline__ uint32_t h2u(__half2 h) {
    return *reinterpret_cast<uint32_t*>(&h);
}
__device__ __forceinline__ __half2 u2h(uint32_t u) {
    return *reinterpret_cast<__half2*>(&u);
}

// fp16 mma m16n8k16, fp32 accumulate
__device__ __forceinline__ void mma_f16(
    float& c0, float& c1, float& c2, float& c3,
    uint32_t a0, uint32_t a1, uint32_t a2, uint32_t a3,
    uint32_t b0, uint32_t b1)
{
    asm volatile(
        "mma.sync.aligned.m16n8k16.row.col.f32.f16.f16.f32 "
        "{%0,%1,%2,%3}, {%4,%5,%6,%7}, {%8,%9}, {%0,%1,%2,%3};"
        : "+f"(c0), "+f"(c1), "+f"(c2), "+f"(c3)
        : "r"(a0), "r"(a1), "r"(a2), "r"(a3), "r"(b0), "r"(b1));
}

// ldmatrix x4: four 8x8 b16 matrices
__device__ __forceinline__ void ldsm_x4(uint32_t& r0, uint32_t& r1,
                                        uint32_t& r2, uint32_t& r3,
                                        uint32_t addr)
{
    asm volatile("ldmatrix.sync.aligned.m8n8.x4.shared.b16 {%0,%1,%2,%3}, [%4];"
                 : "=r"(r0), "=r"(r1), "=r"(r2), "=r"(r3) : "r"(addr));
}

// ===========================================================================
// Convert x, w1, w2 to fp16 (8 floats per thread)
// ===========================================================================
#define NXf  (Mrows * En)          // 4194304
#define NW1f (E3 * En)             // 786432
#define NW2f (En * En)             // 262144

__global__ void __launch_bounds__(256)
cvt_h_kernel(const float* __restrict__ x, const float* __restrict__ w1,
             const float* __restrict__ w2)
{
    int i = blockIdx.x * 256 + threadIdx.x;
    int base = i * 8;
    const float* s;
    __half* d;
    if (base < NXf) {
        s = x + base;                 d = g_xh + base;
    } else if (base < NXf + NW1f) {
        s = w1 + (base - NXf);        d = g_w1h + (base - NXf);
    } else {
        s = w2 + (base - NXf - NW1f); d = g_w2h + (base - NXf - NW1f);
    }
    float4 v0 = *reinterpret_cast<const float4*>(s);
    float4 v1 = *reinterpret_cast<const float4*>(s + 4);
    uint4 o;
    o.x = h2u(__floats2half2_rn(v0.x, v0.y));
    o.y = h2u(__floats2half2_rn(v0.z, v0.w));
    o.z = h2u(__floats2half2_rn(v1.x, v1.y));
    o.w = h2u(__floats2half2_rn(v1.z, v1.w));
    *reinterpret_cast<uint4*>(d) = o;
}

// ===========================================================================
// fp16 GEMM, cp.async 3-stage, BK=64 halves, ldmatrix, m16n8k16.
// C[M,N] = A[M,K] @ Bw[N,K]^T + bias[N].
// 128x128 tile, 256 thr (8 warps 2x4), warp 64x32. 8 barriers per K=512.
// VT: qkv V-columns (nBase >= 1024) go TRANSPOSED (fp16) to g_vt.
// ===========================================================================
#define GPh 72   // smem pitch in halves (64 + 8); 144B rows -> conflict-free
#define GEMM_SMEM (3 * 2 * 128 * GPh * 2)   // 110592 B
#define TP 132   // transpose scratch pitch (floats)

template<bool HALF_OUT, bool VT>
__device__ __forceinline__ void h16_gemm(
    const __half* __restrict__ A, const __half* __restrict__ Bw,
    const float* __restrict__ bias, void* __restrict__ Cv,
    int M, int N, int K)
{
    extern __shared__ float gsm[];
    const int tid  = threadIdx.x;
    const int lane = tid & 31;
    const int wid  = tid >> 5;
    const int wm   = wid >> 2;
    const int wn   = wid & 3;
    const int lr   = lane >> 2;
    const int lc   = lane & 3;
    const int mBase = blockIdx.y * 128;
    const int nBase = blockIdx.x * 128;
    const uint32_t smb = smem_u32(gsm);
    constexpr uint32_t STAGE_B = 2u * 128 * GPh * 2;   // 36864

    float acc[4][4][4];
#pragma unroll
    for (int mt = 0; mt < 4; mt++)
#pragma unroll
        for (int nt = 0; nt < 4; nt++)
#pragma unroll
            for (int i = 0; i < 4; i++) acc[mt][nt][i] = 0.0f;

    // Loader: 4 cp16 per (A, W) per thread per stage (128 rows x 64 halves)
    const __half* srcA[4];
    const __half* srcW[4];
    uint32_t dA[4], dW[4];
#pragma unroll
    for (int i = 0; i < 4; i++) {
        int f   = tid + i * 256;           // 0..1023
        int row = f >> 3;                  // 0..127
        int c8  = (f & 7) << 3;            // 0..56 (halves)
        srcA[i] = A  + (size_t)(mBase + row) * K + c8;
        srcW[i] = Bw + (size_t)(nBase + row) * K + c8;
        dA[i] = (uint32_t)(row * GPh + c8) * 2u;
        dW[i] = dA[i] + 128u * GPh * 2u;
    }

    // ldmatrix per-lane offsets (bytes within stage)
    const int lrow16 = lane & 15;
    const int kgrpA  = (lane >> 4) * 8;                       // halves
    const int rowB2  = (lane & 7) + ((lane >> 4) & 1) * 8;
    const int kofB8  = ((lane >> 3) & 1) * 8;                 // halves
    uint32_t offA[4], offB[2];
#pragma unroll
    for (int mt = 0; mt < 4; mt++)
        offA[mt] = (uint32_t)(((wm * 64 + mt * 16 + lrow16) * GPh + kgrpA) * 2);
#pragma unroll
    for (int p = 0; p < 2; p++)
        offB[p] = (uint32_t)((128 * GPh + (wn * 32 + p * 16 + rowB2) * GPh + kofB8) * 2);

    const int nIter = K >> 6;
    auto issue = [&](int it, int s) {
        if (it < nIter) {
            uint32_t sb = smb + (uint32_t)s * STAGE_B;
            int kt = it << 6;
#pragma unroll
            for (int i = 0; i < 4; i++) {
                cp16(sb + dA[i], srcA[i] + kt);
                cp16(sb + dW[i], srcW[i] + kt);
            }
        }
        CP_COMMIT();
    };
    issue(0, 0);
    issue(1, 1);

    int s = 0;
    for (int it = 0; it < nIter; it++) {
        CP_WAIT1();
        __syncthreads();
        int s2 = s + 2; if (s2 >= 3) s2 -= 3;
        issue(it + 2, s2);

        const uint32_t stb = smb + (uint32_t)s * STAGE_B;
#pragma unroll
        for (int k16 = 0; k16 < 4; k16++) {
            const uint32_t kb = (uint32_t)(k16 * 32);   // 16 halves = 32 B
            uint32_t af[4][4], bf[4][2];
#pragma unroll
            for (int mt = 0; mt < 4; mt++)
                ldsm_x4(af[mt][0], af[mt][1], af[mt][2], af[mt][3],
                        stb + offA[mt] + kb);
#pragma unroll
            for (int p = 0; p < 2; p++)
                ldsm_x4(bf[2 * p][0], bf[2 * p][1],
                        bf[2 * p + 1][0], bf[2 * p + 1][1],
                        stb + offB[p] + kb);
#pragma unroll
            for (int mt = 0; mt < 4; mt++)
#pragma unroll
                for (int nt = 0; nt < 4; nt++)
                    mma_f16(acc[mt][nt][0], acc[mt][nt][1],
                            acc[mt][nt][2], acc[mt][nt][3],
                            af[mt][0], af[mt][1], af[mt][2], af[mt][3],
                            bf[nt][0], bf[nt][1]);
        }
        if (++s == 3) s = 0;
    }

    if (VT && nBase >= 2 * En) {
        // ---- V tile: bias, transpose via smem (fp32), write fp16 g_vt ----
        CP_WAIT0();
        __syncthreads();
        float* T = gsm;                    // [128 cols][TP]
#pragma unroll
        for (int mt = 0; mt < 4; mt++) {
            const int r0 = wm * 64 + mt * 16 + lr;
#pragma unroll
            for (int nt = 0; nt < 4; nt++) {
                const int c = wn * 32 + nt * 8 + 2 * lc;
                const float bx = bias[nBase + c];
                const float by = bias[nBase + c + 1];
                T[c * TP + r0]           = acc[mt][nt][0] + bx;
                T[(c + 1) * TP + r0]     = acc[mt][nt][1] + by;
                T[c * TP + r0 + 8]       = acc[mt][nt][2] + bx;
                T[(c + 1) * TP + r0 + 8] = acc[mt][nt][3] + by;
            }
        }
        __syncthreads();
        const int bb = mBase >> 12;
        const int s0 = mBase & (Sn - 1);
#pragma unroll
        for (int i = 0; i < 8; i++) {
            int f  = tid + i * 256;        // 0..2047
            int c  = f >> 4;               // 0..127 local col (h,d)
            int r8 = (f & 15) << 3;        // 0..120 local row (seq)
            int col = nBase - 2 * En + c;
            int h = col >> 6, d = col & 63;
            const float* tp = T + c * TP + r8;
            uint4 o;
            o.x = h2u(__floats2half2_rn(tp[0], tp[1]));
            o.y = h2u(__floats2half2_rn(tp[2], tp[3]));
            o.z = h2u(__floats2half2_rn(tp[4], tp[5]));
            o.w = h2u(__floats2half2_rn(tp[6], tp[7]));
            *reinterpret_cast<uint4*>(
                g_vt + (((size_t)bb * Hn + h) * Dn + d) * Sn + s0 + r8) = o;
        }
        return;
    }

    // ---- normal epilogue ----
#pragma unroll
    for (int mt = 0; mt < 4; mt++) {
        const int row0 = mBase + wm * 64 + mt * 16 + lr;
#pragma unroll
        for (int nt = 0; nt < 4; nt++) {
            const int col = nBase + wn * 32 + nt * 8 + 2 * lc;
            const float bx = bias[col];
            const float by = bias[col + 1];
            float v0 = acc[mt][nt][0] + bx, v1 = acc[mt][nt][1] + by;
            float v2 = acc[mt][nt][2] + bx, v3 = acc[mt][nt][3] + by;
            if (HALF_OUT) {
                __half* C = (__half*)Cv;
                *reinterpret_cast<uint32_t*>(C + (size_t)row0 * N + col) =
                    h2u(__floats2half2_rn(v0, v1));
                *reinterpret_cast<uint32_t*>(C + (size_t)(row0 + 8) * N + col) =
                    h2u(__floats2half2_rn(v2, v3));
            } else {
                float* C = (float*)Cv;
                *reinterpret_cast<float2*>(C + (size_t)row0 * N + col) =
                    make_float2(v0, v1);
                *reinterpret_cast<float2*>(C + (size_t)(row0 + 8) * N + col) =
                    make_float2(v2, v3);
            }
        }
    }
}

__global__ void __launch_bounds__(256, 2)
gemm_qkv_kernel(const float* __restrict__ b1)
{
    h16_gemm<true, true>(g_xh, g_w1h, b1, g_qkv, Mrows, E3, En);
}

__global__ void __launch_bounds__(256, 2)
gemm_out_kernel(const float* __restrict__ b2, float* __restrict__ out)
{
    h16_gemm<false, false>(g_att, g_w2h, b2, out, Mrows, En, En);
}

// ===========================================================================
// FlashAttention-2, Gaussian-bias windowed, fp16 m16n8k16 HMMA.
// P's fp16 A-fragment layout == pairs of S C-fragments -> zero shuffles.
// Window W = 11 t^2 + 64 (dropped mass < 4e-10).
// Grid (Sn/64, Hn, Bn), 128 threads, 4 CTAs/SM.
// ===========================================================================
#define BR   64
#define BC   64
#define KVPh 72                         // smem pitch (halves)
#define NKB  (Sn / BC)
#define ATTN_THREADS 128
#define KV_TILE_B (BC * KVPh * 2)       // 9216 B per operand tile
#define ATTN_SMEM (2 * 2 * KV_TILE_B)   // 36864 B

__global__ void __launch_bounds__(ATTN_THREADS, 4)
attn_fa2_kernel(const float* __restrict__ t)
{
    extern __shared__ float sm[];
    const uint32_t smb = smem_u32(sm);

    const int tid  = threadIdx.x;
    const int lane = tid & 31;
    const int wid  = tid >> 5;             // 0..3
    const int qt = blockIdx.x, h = blockIdx.y, b = blockIdx.z;
    const int q0 = qt * BR;
    const int qw = q0 + wid * 16;

    const int lr = lane >> 2;
    const int lc = lane & 3;

    const float tt = t[h];
    const float sig = tt * tt;
    const float ninv = -1.0f / (2.0f * sig * sig);

    const float Wf = fminf(11.0f * sig + 64.0f, (float)Sn);
    const int   W  = (int)Wf;
    const int kb_lo = max(0, (q0 - W) >> 6);
    const int kb_hi = min(NKB - 1, (q0 + BR - 1 + W) >> 6);

    // Stage K [key][d] from g_qkv and V^T [d][key] from g_vt (both fp16)
    const __half* srcVbase = g_vt + ((size_t)b * Hn + h) * Dn * Sn;
    auto issue_kv = [&](int k0, int buf) {
        const __half* srcK = g_qkv + En + (size_t)(b * Sn + k0) * E3 + h * Dn;
        const __half* srcV = srcVbase + k0;
        uint32_t sb = smb + (uint32_t)buf * (2u * KV_TILE_B);
#pragma unroll
        for (int i = 0; i < 8; i++) {
            int f   = i * ATTN_THREADS + tid;   // 0..1023
            int sel = f >> 9;
            int idx = f & 511;
            int row = idx >> 3;                 // 0..63
            int c8  = (idx & 7) << 3;           // 0..56 halves
            const __half* src = sel ? (srcV + (size_t)row * Sn + c8)
                                    : (srcK + (size_t)row * E3 + c8);
            uint32_t dst = sb + (uint32_t)((sel * BC + row) * KVPh + c8) * 2u;
            cp16(dst, src);
        }
    };

    // ldmatrix per-lane offsets for K / V^T B-fragments
    const int rowB2 = (lane & 7) + ((lane >> 4) & 1) * 8;
    const int kofB8 = ((lane >> 3) & 1) * 8;
    uint32_t offK[4], offV[4];
#pragma unroll
    for (int p = 0; p < 4; p++) {
        offK[p] = (uint32_t)(((p * 16 + rowB2) * KVPh + kofB8) * 2);
        offV[p] = offK[p] + (uint32_t)KV_TILE_B;
    }

    // Q fragments (fp16, scaled by 0.125 -- exact pow2)
    uint32_t qa[4][4];
    {
        const __half2 s125 = __float2half2_rn(0.125f);
        const __half* qp  = g_qkv + (size_t)(b * Sn + qw + lr) * E3 + h * Dn;
        const __half* qp8 = qp + 8 * E3;
#pragma unroll
        for (int kt = 0; kt < 4; kt++) {
            int k0h = kt * 16 + 2 * lc;
            qa[kt][0] = h2u(__hmul2(*(const __half2*)(qp  + k0h),     s125));
            qa[kt][1] = h2u(__hmul2(*(const __half2*)(qp8 + k0h),     s125));
            qa[kt][2] = h2u(__hmul2(*(const __half2*)(qp  + k0h + 8), s125));
            qa[kt][3] = h2u(__hmul2(*(const __half2*)(qp8 + k0h + 8), s125));
        }
    }

    float o[8][4];
#pragma unroll
    for (int nt = 0; nt < 8; nt++)
#pragma unroll
        for (int i = 0; i < 4; i++) o[nt][i] = 0.0f;
    float m0 = -INFINITY, m1 = -INFINITY;
    float l0 = 0.0f, l1 = 0.0f;

    issue_kv(kb_lo * BC, 0);
    CP_COMMIT();

    const int colb = 2 * lc;

    int cur = 0;
    for (int kb = kb_lo; kb <= kb_hi; kb++) {
        const int k0 = kb * BC;

        CP_WAIT0();
        __syncthreads();
        if (kb + 1 <= kb_hi) issue_kv(k0 + BC, cur ^ 1);
        CP_COMMIT();

        const uint32_t Kb = smb + (uint32_t)cur * (2u * KV_TILE_B);

        // ---- S = Q @ K^T ----
        float sc[8][4];
#pragma unroll
        for (int nt = 0; nt < 8; nt++)
#pragma unroll
            for (int i = 0; i < 4; i++) sc[nt][i] = 0.0f;

#pragma unroll
        for (int kt = 0; kt < 4; kt++) {
            uint32_t kf[8][2];
#pragma unroll
            for (int p = 0; p < 4; p++)
                ldsm_x4(kf[2 * p][0], kf[2 * p][1],
                        kf[2 * p + 1][0], kf[2 * p + 1][1],
                        Kb + offK[p] + (uint32_t)(kt * 32));
#pragma unroll
            for (int nt = 0; nt < 8; nt++)
                mma_f16(sc[nt][0], sc[nt][1], sc[nt][2], sc[nt][3],
                        qa[kt][0], qa[kt][1], qa[kt][2], qa[kt][3],
                        kf[nt][0], kf[nt][1]);
        }

        // ---- Gaussian bias + online softmax ----
        const float d0f = (float)(qw + lr - k0);
        const float d1f = d0f + 8.0f;
        float rmax0 = -INFINITY, rmax1 = -INFINITY;
#pragma unroll
        for (int nt = 0; nt < 8; nt++) {
#pragma unroll
            for (int e = 0; e < 2; e++) {
                float cj = (float)(nt * 8 + colb + e);
                float fd0 = d0f - cj;
                float fd1 = d1f - cj;
                sc[nt][e]     = fmaf(fd0 * fd0, ninv, sc[nt][e]);
                sc[nt][e + 2] = fmaf(fd1 * fd1, ninv, sc[nt][e + 2]);
                rmax0 = fmaxf(rmax0, sc[nt][e]);
                rmax1 = fmaxf(rmax1, sc[nt][e + 2]);
            }
        }
        rmax0 = fmaxf(rmax0, __shfl_xor_sync(0xffffffffu, rmax0, 1));
        rmax0 = fmaxf(rmax0, __shfl_xor_sync(0xffffffffu, rmax0, 2));
        rmax1 = fmaxf(rmax1, __shfl_xor_sync(0xffffffffu, rmax1, 1));
        rmax1 = fmaxf(rmax1, __shfl_xor_sync(0xffffffffu, rmax1, 2));

        const float mn0 = fmaxf(m0, rmax0);
        const float mn1 = fmaxf(m1, rmax1);
        const float corr0 = __expf(m0 - mn0);
        const float corr1 = __expf(m1 - mn1);
        m0 = mn0; m1 = mn1;

        // P -> fp16 (rn); l sums the ROUNDED values so O/l cancels exactly
        uint32_t plo[8], phi[8];
        float ls0 = 0.0f, ls1 = 0.0f;
#pragma unroll
        for (int nt = 0; nt < 8; nt++) {
            float p0 = __expf(sc[nt][0] - mn0);
            float p1 = __expf(sc[nt][1] - mn0);
            float p2 = __expf(sc[nt][2] - mn1);
            float p3 = __expf(sc[nt][3] - mn1);
            __half2 hl = __floats2half2_rn(p0, p1);
            __half2 hh = __floats2half2_rn(p2, p3);
            float2 fl = __half22float2(hl);
            float2 fh = __half22float2(hh);
            ls0 += fl.x + fl.y;
            ls1 += fh.x + fh.y;
            plo[nt] = h2u(hl);
            phi[nt] = h2u(hh);
        }
        l0 = l0 * corr0 + ls0;
        l1 = l1 * corr1 + ls1;

        if (__ballot_sync(0xffffffffu, (corr0 != 1.0f) | (corr1 != 1.0f))) {
#pragma unroll
            for (int nt = 0; nt < 8; nt++) {
                o[nt][0] *= corr0; o[nt][1] *= corr0;
                o[nt][2] *= corr1; o[nt][3] *= corr1;
            }
        }

        // ---- O += P @ V : P fragments come straight from S fragments ----
#pragma unroll
        for (int kt2 = 0; kt2 < 4; kt2++) {
            uint32_t a0 = plo[2 * kt2];
            uint32_t a1 = phi[2 * kt2];
            uint32_t a2 = plo[2 * kt2 + 1];
            uint32_t a3 = phi[2 * kt2 + 1];

            uint32_t vf[8][2];
#pragma unroll
            for (int p = 0; p < 4; p++)
                ldsm_x4(vf[2 * p][0], vf[2 * p][1],
                        vf[2 * p + 1][0], vf[2 * p + 1][1],
                        Kb + offV[p] + (uint32_t)(kt2 * 32));
#pragma unroll
            for (int nt = 0; nt < 8; nt++)
                mma_f16(o[nt][0], o[nt][1], o[nt][2], o[nt][3],
                        a0, a1, a2, a3, vf[nt][0], vf[nt][1]);
        }

        cur ^= 1;
    }

    // ---- epilogue: normalize, round to fp16 into g_att ----
    l0 += __shfl_xor_sync(0xffffffffu, l0, 1);
    l0 += __shfl_xor_sync(0xffffffffu, l0, 2);
    l1 += __shfl_xor_sync(0xffffffffu, l1, 1);
    l1 += __shfl_xor_sync(0xffffffffu, l1, 2);
    const float il0 = 1.0f / l0;
    const float il1 = 1.0f / l1;

    __half* op0 = g_att + (size_t)(b * Sn + qw + lr) * En + h * Dn + colb;
    __half* op1 = op0 + 8 * En;
#pragma unroll
    for (int nt = 0; nt < 8; nt++) {
        *reinterpret_cast<uint32_t*>(op0 + nt * 8) =
            h2u(__floats2half2_rn(o[nt][0] * il0, o[nt][1] * il0));
        *reinterpret_cast<uint32_t*>(op1 + nt * 8) =
            h2u(__floats2half2_rn(o[nt][2] * il1, o[nt][3] * il1));
    }
}

// ===========================================================================
// Launch
// ===========================================================================
extern "C" void kernel_launch(void* const* d_in, const int* in_sizes, int n_in,
                              void* d_out, int out_size)
{
    const float* x  = (const float*)d_in[0];
    const float* w1 = (const float*)d_in[1];
    const float* b1 = (const float*)d_in[2];
    const float* w2 = (const float*)d_in[3];
    const float* b2 = (const float*)d_in[4];
    const float* t  = (const float*)d_in[5];
    float* out = (float*)d_out;
    (void)in_sizes; (void)n_in; (void)out_size;

    cvt_h_kernel<<<(NXf + NW1f + NW2f) / (256 * 8), 256>>>(x, w1, w2);

    cudaFuncSetAttribute(gemm_qkv_kernel,
                         cudaFuncAttributeMaxDynamicSharedMemorySize, GEMM_SMEM);
    cudaFuncSetAttribute(gemm_out_kernel,
                         cudaFuncAttributeMaxDynamicSharedMemorySize, GEMM_SMEM);
    cudaFuncSetAttribute(attn_fa2_kernel,
                         cudaFuncAttributeMaxDynamicSharedMemorySize, ATTN_SMEM);

    gemm_qkv_kernel<<<dim3(E3 / 128, Mrows / 128), 256, GEMM_SMEM>>>(b1);

    attn_fa2_kernel<<<dim3(Sn / BR, Hn, Bn), ATTN_THREADS, ATTN_SMEM>>>(t);

    gemm_out_kernel<<<dim3(En / 128, Mrows / 128), 256, GEMM_SMEM>>>(b2, out);
}

// round 12
// speedup vs baseline: 25.4943x; 1.0341x over previous
#include <cuda_runtime.h>
#include <cuda_fp16.h>
#include <math.h>
#include <stdint.h>

// Problem constants
#define Bn  2
#define Sn  4096
#define En  512
#define Hn  8
#define Dn  64
#define E3  1536
#define Mrows (Bn * Sn)   // 8192

// Scratch (static device globals -- no allocation at runtime)
__device__ __half g_qkv[(size_t)Mrows * E3];        // [B*S,3E] fp16 (V unused)
__device__ __half g_vt [(size_t)Bn * Hn * Dn * Sn]; // V transposed [b][h][d][s]
__device__ __half g_att[(size_t)Mrows * En];        // attention out fp16
__device__ __half g_xh [(size_t)Mrows * En];        // x  fp16
__device__ __half g_w1h[(size_t)E3 * En];           // w1 fp16
__device__ __half g_w2h[(size_t)En * En];           // w2 fp16

// ===========================================================================
// Helpers
// ===========================================================================
__device__ __forceinline__ uint32_t smem_u32(const void* p) {
    uint32_t a;
    asm("{ .reg .u64 t; cvta.to.shared.u64 t, %1; cvt.u32.u64 %0, t; }"
        : "=r"(a) : "l"(p));
    return a;
}
__device__ __forceinline__ void cp16(uint32_t d, const void* s) {
    asm volatile("cp.async.cg.shared.global [%0], [%1], 16;"
                 :: "r"(d), "l"(s));
}
#define CP_COMMIT() asm volatile("cp.async.commit_group;" ::: "memory")
#define CP_WAIT0()  asm volatile("cp.async.wait_group 0;" ::: "memory")

__device__ __forceinline__ uint32_t h2u(__half2 h) {
    return *reinterpret_cast<uint32_t*>(&h);
}

// fp16 mma m16n8k16, fp32 accumulate
__device__ __forceinline__ void mma_f16(
    float& c0, float& c1, float& c2, float& c3,
    uint32_t a0, uint32_t a1, uint32_t a2, uint32_t a3,
    uint32_t b0, uint32_t b1)
{
    asm volatile(
        "mma.sync.aligned.m16n8k16.row.col.f32.f16.f16.f32 "
        "{%0,%1,%2,%3}, {%4,%5,%6,%7}, {%8,%9}, {%0,%1,%2,%3};"
        : "+f"(c0), "+f"(c1), "+f"(c2), "+f"(c3)
        : "r"(a0), "r"(a1), "r"(a2), "r"(a3), "r"(b0), "r"(b1));
}

// ldmatrix x4: four 8x8 b16 matrices
__device__ __forceinline__ void ldsm_x4(uint32_t& r0, uint32_t& r1,
                                        uint32_t& r2, uint32_t& r3,
                                        uint32_t addr)
{
    asm volatile("ldmatrix.sync.aligned.m8n8.x4.shared.b16 {%0,%1,%2,%3}, [%4];"
                 : "=r"(r0), "=r"(r1), "=r"(r2), "=r"(r3) : "r"(addr));
}

// ===========================================================================
// Convert x, w1, w2 to fp16 (8 floats per thread)
// ===========================================================================
#define NXf  (Mrows * En)          // 4194304
#define NW1f (E3 * En)             // 786432
#define NW2f (En * En)             // 262144

__global__ void __launch_bounds__(256)
cvt_h_kernel(const float* __restrict__ x, const float* __restrict__ w1,
             const float* __restrict__ w2)
{
    int i = blockIdx.x * 256 + threadIdx.x;
    int base = i * 8;
    const float* s;
    __half* d;
    if (base < NXf) {
        s = x + base;                 d = g_xh + base;
    } else if (base < NXf + NW1f) {
        s = w1 + (base - NXf);        d = g_w1h + (base - NXf);
    } else {
        s = w2 + (base - NXf - NW1f); d = g_w2h + (base - NXf - NW1f);
    }
    float4 v0 = *reinterpret_cast<const float4*>(s);
    float4 v1 = *reinterpret_cast<const float4*>(s + 4);
    uint4 o;
    o.x = h2u(__floats2half2_rn(v0.x, v0.y));
    o.y = h2u(__floats2half2_rn(v0.z, v0.w));
    o.z = h2u(__floats2half2_rn(v1.x, v1.y));
    o.w = h2u(__floats2half2_rn(v1.z, v1.w));
    *reinterpret_cast<uint4*>(d) = o;
}

// ===========================================================================
// fp16 GEMM, cp.async 2-stage, BK=64 halves, ldmatrix, m16n8k16.
// R12: CTA 64x128 (M x N), 128 threads / 4 warps (warp tile 64x32, wm=0),
// 4 CTAs/SM -> 4 independent barrier groups per SM (convoy mitigation).
// C[M,N] = A[M,K] @ Bw[N,K]^T + bias[N].
// VT: qkv V-columns (nBase >= 1024) go TRANSPOSED (fp16) to g_vt.
// ===========================================================================
#define GPh 72   // smem pitch in halves (64 + 8); 144B rows -> conflict-free
#define GROWS 192                             // 64 A rows + 128 W rows
#define GSTAGE_B (GROWS * GPh * 2)            // 27648 B
#define GEMM_SMEM (2 * GSTAGE_B)              // 55296 B
#define TP 68    // transpose scratch pitch (floats, 64 rows + 4)

template<bool HALF_OUT, bool VT>
__device__ __forceinline__ void h16_gemm(
    const __half* __restrict__ A, const __half* __restrict__ Bw,
    const float* __restrict__ bias, void* __restrict__ Cv,
    int M, int N, int K)
{
    extern __shared__ float gsm[];
    const int tid  = threadIdx.x;
    const int lane = tid & 31;
    const int wid  = tid >> 5;         // 0..3
    const int wn   = wid;              // all warps tile N; wm = 0
    const int lr   = lane >> 2;
    const int lc   = lane & 3;
    const int mBase = blockIdx.y * 64;
    const int nBase = blockIdx.x * 128;
    const uint32_t smb = smem_u32(gsm);

    float acc[4][4][4];
#pragma unroll
    for (int mt = 0; mt < 4; mt++)
#pragma unroll
        for (int nt = 0; nt < 4; nt++)
#pragma unroll
            for (int i = 0; i < 4; i++) acc[mt][nt][i] = 0.0f;

    const __half* Abase = A  + (size_t)mBase * K;
    const __half* Wbase = Bw + (size_t)nBase * K;

    // ldmatrix per-lane offsets (bytes within a stage)
    const int lrow16 = lane & 15;
    const int kgrpA  = (lane >> 4) * 8;                       // halves
    const int rowB2  = (lane & 7) + ((lane >> 4) & 1) * 8;
    const int kofB8  = ((lane >> 3) & 1) * 8;                 // halves
    uint32_t offA[4], offB[2];
#pragma unroll
    for (int mt = 0; mt < 4; mt++)
        offA[mt] = (uint32_t)(((mt * 16 + lrow16) * GPh + kgrpA) * 2);
#pragma unroll
    for (int p = 0; p < 2; p++)
        offB[p] = (uint32_t)((64 * GPh + (wn * 32 + p * 16 + rowB2) * GPh + kofB8) * 2);

    const int nIter = K >> 6;
    // Loader: 12 cp16 per thread per stage (192 rows x 64 halves)
    auto issue = [&](int it, int s) {
        if (it < nIter) {
            uint32_t sb = smb + (uint32_t)s * GSTAGE_B;
            int kt = it << 6;
#pragma unroll
            for (int i = 0; i < 12; i++) {
                int f   = tid + i * 128;       // 0..1535
                int row = f >> 3;              // 0..191
                int c8  = (f & 7) << 3;        // 0..56 halves
                const __half* src = (row < 64)
                    ? (Abase + (size_t)row * K + kt + c8)
                    : (Wbase + (size_t)(row - 64) * K + kt + c8);
                cp16(sb + (uint32_t)(row * GPh + c8) * 2u, src);
            }
        }
        CP_COMMIT();
    };
    issue(0, 0);

    for (int it = 0; it < nIter; it++) {
        CP_WAIT0();
        __syncthreads();
        issue(it + 1, (it + 1) & 1);

        const uint32_t stb = smb + (uint32_t)(it & 1) * GSTAGE_B;
#pragma unroll
        for (int k16 = 0; k16 < 4; k16++) {
            const uint32_t kb = (uint32_t)(k16 * 32);   // 16 halves = 32 B
            uint32_t af[4][4], bf[4][2];
#pragma unroll
            for (int mt = 0; mt < 4; mt++)
                ldsm_x4(af[mt][0], af[mt][1], af[mt][2], af[mt][3],
                        stb + offA[mt] + kb);
#pragma unroll
            for (int p = 0; p < 2; p++)
                ldsm_x4(bf[2 * p][0], bf[2 * p][1],
                        bf[2 * p + 1][0], bf[2 * p + 1][1],
                        stb + offB[p] + kb);
#pragma unroll
            for (int mt = 0; mt < 4; mt++)
#pragma unroll
                for (int nt = 0; nt < 4; nt++)
                    mma_f16(acc[mt][nt][0], acc[mt][nt][1],
                            acc[mt][nt][2], acc[mt][nt][3],
                            af[mt][0], af[mt][1], af[mt][2], af[mt][3],
                            bf[nt][0], bf[nt][1]);
        }
    }

    if (VT && nBase >= 2 * En) {
        // ---- V tile (64 x 128): bias, transpose via smem, write g_vt ----
        CP_WAIT0();
        __syncthreads();
        float* T = gsm;                    // [128 cols][TP rows(64+4)]
#pragma unroll
        for (int mt = 0; mt < 4; mt++) {
            const int r0 = mt * 16 + lr;
#pragma unroll
            for (int nt = 0; nt < 4; nt++) {
                const int c = wn * 32 + nt * 8 + 2 * lc;
                const float bx = bias[nBase + c];
                const float by = bias[nBase + c + 1];
                T[c * TP + r0]           = acc[mt][nt][0] + bx;
                T[(c + 1) * TP + r0]     = acc[mt][nt][1] + by;
                T[c * TP + r0 + 8]       = acc[mt][nt][2] + bx;
                T[(c + 1) * TP + r0 + 8] = acc[mt][nt][3] + by;
            }
        }
        __syncthreads();
        const int bb = mBase >> 12;
        const int s0 = mBase & (Sn - 1);
#pragma unroll
        for (int i = 0; i < 8; i++) {
            int f  = tid + i * 128;        // 0..1023
            int c  = f >> 3;               // 0..127 local col (h,d)
            int r8 = (f & 7) << 3;         // 0..56 local row (seq)
            int col = nBase - 2 * En + c;
            int h = col >> 6, d = col & 63;
            const float* tp = T + c * TP + r8;
            uint4 o;
            o.x = h2u(__floats2half2_rn(tp[0], tp[1]));
            o.y = h2u(__floats2half2_rn(tp[2], tp[3]));
            o.z = h2u(__floats2half2_rn(tp[4], tp[5]));
            o.w = h2u(__floats2half2_rn(tp[6], tp[7]));
            *reinterpret_cast<uint4*>(
                g_vt + (((size_t)bb * Hn + h) * Dn + d) * Sn + s0 + r8) = o;
        }
        return;
    }

    // ---- normal epilogue ----
#pragma unroll
    for (int mt = 0; mt < 4; mt++) {
        const int row0 = mBase + mt * 16 + lr;
#pragma unroll
        for (int nt = 0; nt < 4; nt++) {
            const int col = nBase + wn * 32 + nt * 8 + 2 * lc;
            const float bx = bias[col];
            const float by = bias[col + 1];
            float v0 = acc[mt][nt][0] + bx, v1 = acc[mt][nt][1] + by;
            float v2 = acc[mt][nt][2] + bx, v3 = acc[mt][nt][3] + by;
            if (HALF_OUT) {
                __half* C = (__half*)Cv;
                *reinterpret_cast<uint32_t*>(C + (size_t)row0 * N + col) =
                    h2u(__floats2half2_rn(v0, v1));
                *reinterpret_cast<uint32_t*>(C + (size_t)(row0 + 8) * N + col) =
                    h2u(__floats2half2_rn(v2, v3));
            } else {
                float* C = (float*)Cv;
                *reinterpret_cast<float2*>(C + (size_t)row0 * N + col) =
                    make_float2(v0, v1);
                *reinterpret_cast<float2*>(C + (size_t)(row0 + 8) * N + col) =
                    make_float2(v2, v3);
            }
        }
    }
}

__global__ void __launch_bounds__(128, 4)
gemm_qkv_kernel(const float* __restrict__ b1)
{
    h16_gemm<true, true>(g_xh, g_w1h, b1, g_qkv, Mrows, E3, En);
}

__global__ void __launch_bounds__(128, 4)
gemm_out_kernel(const float* __restrict__ b2, float* __restrict__ out)
{
    h16_gemm<false, false>(g_att, g_w2h, b2, out, Mrows, En, En);
}

// ===========================================================================
// FlashAttention-2, Gaussian-bias windowed, fp16 m16n8k16 HMMA.
// P's fp16 A-fragment layout == pairs of S C-fragments -> zero shuffles.
// Window W = 11 t^2 + 64 (dropped mass < 4e-10).
// Grid (Sn/64, Hn, Bn), 128 threads, 4 CTAs/SM.  (unchanged from R11)
// ===========================================================================
#define BR   64
#define BC   64
#define KVPh 72                         // smem pitch (halves)
#define NKB  (Sn / BC)
#define ATTN_THREADS 128
#define KV_TILE_B (BC * KVPh * 2)       // 9216 B per operand tile
#define ATTN_SMEM (2 * 2 * KV_TILE_B)   // 36864 B

__global__ void __launch_bounds__(ATTN_THREADS, 4)
attn_fa2_kernel(const float* __restrict__ t)
{
    extern __shared__ float sm[];
    const uint32_t smb = smem_u32(sm);

    const int tid  = threadIdx.x;
    const int lane = tid & 31;
    const int wid  = tid >> 5;             // 0..3
    const int qt = blockIdx.x, h = blockIdx.y, b = blockIdx.z;
    const int q0 = qt * BR;
    const int qw = q0 + wid * 16;

    const int lr = lane >> 2;
    const int lc = lane & 3;

    const float tt = t[h];
    const float sig = tt * tt;
    const float ninv = -1.0f / (2.0f * sig * sig);

    const float Wf = fminf(11.0f * sig + 64.0f, (float)Sn);
    const int   W  = (int)Wf;
    const int kb_lo = max(0, (q0 - W) >> 6);
    const int kb_hi = min(NKB - 1, (q0 + BR - 1 + W) >> 6);

    const __half* srcVbase = g_vt + ((size_t)b * Hn + h) * Dn * Sn;
    auto issue_kv = [&](int k0, int buf) {
        const __half* srcK = g_qkv + En + (size_t)(b * Sn + k0) * E3 + h * Dn;
        const __half* srcV = srcVbase + k0;
        uint32_t sb = smb + (uint32_t)buf * (2u * KV_TILE_B);
#pragma unroll
        for (int i = 0; i < 8; i++) {
            int f   = i * ATTN_THREADS + tid;   // 0..1023
            int sel = f >> 9;
            int idx = f & 511;
            int row = idx >> 3;                 // 0..63
            int c8  = (idx & 7) << 3;           // 0..56 halves
            const __half* src = sel ? (srcV + (size_t)row * Sn + c8)
                                    : (srcK + (size_t)row * E3 + c8);
            uint32_t dst = sb + (uint32_t)((sel * BC + row) * KVPh + c8) * 2u;
            cp16(dst, src);
        }
    };

    const int rowB2 = (lane & 7) + ((lane >> 4) & 1) * 8;
    const int kofB8 = ((lane >> 3) & 1) * 8;
    uint32_t offK[4], offV[4];
#pragma unroll
    for (int p = 0; p < 4; p++) {
        offK[p] = (uint32_t)(((p * 16 + rowB2) * KVPh + kofB8) * 2);
        offV[p] = offK[p] + (uint32_t)KV_TILE_B;
    }

    uint32_t qa[4][4];
    {
        const __half2 s125 = __float2half2_rn(0.125f);
        const __half* qp  = g_qkv + (size_t)(b * Sn + qw + lr) * E3 + h * Dn;
        const __half* qp8 = qp + 8 * E3;
#pragma unroll
        for (int kt = 0; kt < 4; kt++) {
            int k0h = kt * 16 + 2 * lc;
            qa[kt][0] = h2u(__hmul2(*(const __half2*)(qp  + k0h),     s125));
            qa[kt][1] = h2u(__hmul2(*(const __half2*)(qp8 + k0h),     s125));
            qa[kt][2] = h2u(__hmul2(*(const __half2*)(qp  + k0h + 8), s125));
            qa[kt][3] = h2u(__hmul2(*(const __half2*)(qp8 + k0h + 8), s125));
        }
    }

    float o[8][4];
#pragma unroll
    for (int nt = 0; nt < 8; nt++)
#pragma unroll
        for (int i = 0; i < 4; i++) o[nt][i] = 0.0f;
    float m0 = -INFINITY, m1 = -INFINITY;
    float l0 = 0.0f, l1 = 0.0f;

    issue_kv(kb_lo * BC, 0);
    CP_COMMIT();

    const int colb = 2 * lc;

    int cur = 0;
    for (int kb = kb_lo; kb <= kb_hi; kb++) {
        const int k0 = kb * BC;

        CP_WAIT0();
        __syncthreads();
        if (kb + 1 <= kb_hi) issue_kv(k0 + BC, cur ^ 1);
        CP_COMMIT();

        const uint32_t Kb = smb + (uint32_t)cur * (2u * KV_TILE_B);

        // ---- S = Q @ K^T ----
        float sc[8][4];
#pragma unroll
        for (int nt = 0; nt < 8; nt++)
#pragma unroll
            for (int i = 0; i < 4; i++) sc[nt][i] = 0.0f;

#pragma unroll
        for (int kt = 0; kt < 4; kt++) {
            uint32_t kf[8][2];
#pragma unroll
            for (int p = 0; p < 4; p++)
                ldsm_x4(kf[2 * p][0], kf[2 * p][1],
                        kf[2 * p + 1][0], kf[2 * p + 1][1],
                        Kb + offK[p] + (uint32_t)(kt * 32));
#pragma unroll
            for (int nt = 0; nt < 8; nt++)
                mma_f16(sc[nt][0], sc[nt][1], sc[nt][2], sc[nt][3],
                        qa[kt][0], qa[kt][1], qa[kt][2], qa[kt][3],
                        kf[nt][0], kf[nt][1]);
        }

        // ---- Gaussian bias + online softmax ----
        const float d0f = (float)(qw + lr - k0);
        const float d1f = d0f + 8.0f;
        float rmax0 = -INFINITY, rmax1 = -INFINITY;
#pragma unroll
        for (int nt = 0; nt < 8; nt++) {
#pragma unroll
            for (int e = 0; e < 2; e++) {
                float cj = (float)(nt * 8 + colb + e);
                float fd0 = d0f - cj;
                float fd1 = d1f - cj;
                sc[nt][e]     = fmaf(fd0 * fd0, ninv, sc[nt][e]);
                sc[nt][e + 2] = fmaf(fd1 * fd1, ninv, sc[nt][e + 2]);
                rmax0 = fmaxf(rmax0, sc[nt][e]);
                rmax1 = fmaxf(rmax1, sc[nt][e + 2]);
            }
        }
        rmax0 = fmaxf(rmax0, __shfl_xor_sync(0xffffffffu, rmax0, 1));
        rmax0 = fmaxf(rmax0, __shfl_xor_sync(0xffffffffu, rmax0, 2));
        rmax1 = fmaxf(rmax1, __shfl_xor_sync(0xffffffffu, rmax1, 1));
        rmax1 = fmaxf(rmax1, __shfl_xor_sync(0xffffffffu, rmax1, 2));

        const float mn0 = fmaxf(m0, rmax0);
        const float mn1 = fmaxf(m1, rmax1);
        const float corr0 = __expf(m0 - mn0);
        const float corr1 = __expf(m1 - mn1);
        m0 = mn0; m1 = mn1;

        uint32_t plo[8], phi[8];
        float ls0 = 0.0f, ls1 = 0.0f;
#pragma unroll
        for (int nt = 0; nt < 8; nt++) {
            float p0 = __expf(sc[nt][0] - mn0);
            float p1 = __expf(sc[nt][1] - mn0);
            float p2 = __expf(sc[nt][2] - mn1);
            float p3 = __expf(sc[nt][3] - mn1);
            __half2 hl = __floats2half2_rn(p0, p1);
            __half2 hh = __floats2half2_rn(p2, p3);
            float2 fl = __half22float2(hl);
            float2 fh = __half22float2(hh);
            ls0 += fl.x + fl.y;
            ls1 += fh.x + fh.y;
            plo[nt] = h2u(hl);
            phi[nt] = h2u(hh);
        }
        l0 = l0 * corr0 + ls0;
        l1 = l1 * corr1 + ls1;

        if (__ballot_sync(0xffffffffu, (corr0 != 1.0f) | (corr1 != 1.0f))) {
#pragma unroll
            for (int nt = 0; nt < 8; nt++) {
                o[nt][0] *= corr0; o[nt][1] *= corr0;
                o[nt][2] *= corr1; o[nt][3] *= corr1;
            }
        }

        // ---- O += P @ V ----
#pragma unroll
        for (int kt2 = 0; kt2 < 4; kt2++) {
            uint32_t a0 = plo[2 * kt2];
            uint32_t a1 = phi[2 * kt2];
            uint32_t a2 = plo[2 * kt2 + 1];
            uint32_t a3 = phi[2 * kt2 + 1];

            uint32_t vf[8][2];
#pragma unroll
            for (int p = 0; p < 4; p++)
                ldsm_x4(vf[2 * p][0], vf[2 * p][1],
                        vf[2 * p + 1][0], vf[2 * p + 1][1],
                        Kb + offV[p] + (uint32_t)(kt2 * 32));
#pragma unroll
            for (int nt = 0; nt < 8; nt++)
                mma_f16(o[nt][0], o[nt][1], o[nt][2], o[nt][3],
                        a0, a1, a2, a3, vf[nt][0], vf[nt][1]);
        }

        cur ^= 1;
    }

    l0 += __shfl_xor_sync(0xffffffffu, l0, 1);
    l0 += __shfl_xor_sync(0xffffffffu, l0, 2);
    l1 += __shfl_xor_sync(0xffffffffu, l1, 1);
    l1 += __shfl_xor_sync(0xffffffffu, l1, 2);
    const float il0 = 1.0f / l0;
    const float il1 = 1.0f / l1;

    __half* op0 = g_att + (size_t)(b * Sn + qw + lr) * En + h * Dn + colb;
    __half* op1 = op0 + 8 * En;
#pragma unroll
    for (int nt = 0; nt < 8; nt++) {
        *reinterpret_cast<uint32_t*>(op0 + nt * 8) =
            h2u(__floats2half2_rn(o[nt][0] * il0, o[nt][1] * il0));
        *reinterpret_cast<uint32_t*>(op1 + nt * 8) =
            h2u(__floats2half2_rn(o[nt][2] * il1, o[nt][3] * il1));
    }
}

// ===========================================================================
// Launch
// ===========================================================================
extern "C" void kernel_launch(void* const* d_in, const int* in_sizes, int n_in,
                              void* d_out, int out_size)
{
    const float* x  = (const float*)d_in[0];
    const float* w1 = (const float*)d_in[1];
    const float* b1 = (const float*)d_in[2];
    const float* w2 = (const float*)d_in[3];
    const float* b2 = (const float*)d_in[4];
    const float* t  = (const float*)d_in[5];
    float* out = (float*)d_out;
    (void)in_sizes; (void)n_in; (void)out_size;

    cvt_h_kernel<<<(NXf + NW1f + NW2f) / (256 * 8), 256>>>(x, w1, w2);

    cudaFuncSetAttribute(gemm_qkv_kernel,
                         cudaFuncAttributeMaxDynamicSharedMemorySize, GEMM_SMEM);
    cudaFuncSetAttribute(gemm_out_kernel,
                         cudaFuncAttributeMaxDynamicSharedMemorySize, GEMM_SMEM);
    cudaFuncSetAttribute(attn_fa2_kernel,
                         cudaFuncAttributeMaxDynamicSharedMemorySize, ATTN_SMEM);

    gemm_qkv_kernel<<<dim3(E3 / 128, Mrows / 64), 128, GEMM_SMEM>>>(b1);

    attn_fa2_kernel<<<dim3(Sn / BR, Hn, Bn), ATTN_THREADS, ATTN_SMEM>>>(t);

    gemm_out_kernel<<<dim3(En / 128, Mrows / 64), 128, GEMM_SMEM>>>(b2, out);
}